// round 1
// baseline (speedup 1.0000x reference)
#include <cuda_runtime.h>
#include <math.h>
#include <stdint.h>

// ---------------------------------------------------------------------------
// Problem constants: B=4, T=2048, C=1024, H=16, HS=64
// M = B*T = 8192 rows
// ---------------------------------------------------------------------------
#define MROWS 8192
#define CDIM  1024

// Scratch (allocation-free: __device__ globals)
__device__ float g_ln1 [8192u * 1024];
__device__ float g_qkv [8192u * 3072];
__device__ float g_attn[8192u * 1024];
__device__ float g_x1  [8192u * 1024];
__device__ float g_ln2 [8192u * 1024];
__device__ float g_hbuf[8192u * 4096];

// ---------------------------------------------------------------------------
// LayerNorm: one block per row (C=1024), 256 threads, float4 per thread
// ---------------------------------------------------------------------------
__global__ __launch_bounds__(256) void ln_kernel(
    const float* __restrict__ x,
    const float* __restrict__ g,
    const float* __restrict__ b,
    float* __restrict__ o)
{
    const int row = blockIdx.x;
    const int tid = threadIdx.x;
    const float4 v = reinterpret_cast<const float4*>(x + (size_t)row * CDIM)[tid];

    float s  = v.x + v.y + v.z + v.w;
    float sq = v.x * v.x + v.y * v.y + v.z * v.z + v.w * v.w;

    // warp reduce
    #pragma unroll
    for (int off = 16; off > 0; off >>= 1) {
        s  += __shfl_xor_sync(0xffffffffu, s,  off);
        sq += __shfl_xor_sync(0xffffffffu, sq, off);
    }
    __shared__ float shs[8], shq[8];
    const int wid = tid >> 5;
    if ((tid & 31) == 0) { shs[wid] = s; shq[wid] = sq; }
    __syncthreads();
    float ts = 0.f, tq = 0.f;
    #pragma unroll
    for (int w = 0; w < 8; w++) { ts += shs[w]; tq += shq[w]; }

    const float mean = ts * (1.0f / CDIM);
    const float var  = tq * (1.0f / CDIM) - mean * mean;
    const float rstd = rsqrtf(var + 1e-5f);

    const float4 gv = reinterpret_cast<const float4*>(g)[tid];
    const float4 bv = reinterpret_cast<const float4*>(b)[tid];
    float4 ov;
    ov.x = (v.x - mean) * rstd * gv.x + bv.x;
    ov.y = (v.y - mean) * rstd * gv.y + bv.y;
    ov.z = (v.z - mean) * rstd * gv.z + bv.z;
    ov.w = (v.w - mean) * rstd * gv.w + bv.w;
    reinterpret_cast<float4*>(o + (size_t)row * CDIM)[tid] = ov;
}

// ---------------------------------------------------------------------------
// SGEMM: C[M,N] = A[M,K] @ W[K,N] + bias  (+ optional GELU, + optional resid)
// 128x128x8 tile, 256 threads, 8x8 per thread (split 4+4 to stay conflict-free)
// M,N multiples of 128; K multiple of 8.
// ---------------------------------------------------------------------------
__device__ __forceinline__ float gelu_f(float x) {
    float x3 = x * x * x;
    return 0.5f * x * (1.0f + tanhf(0.7978845608028654f * (x + 0.044715f * x3)));
}

__global__ __launch_bounds__(256, 2) void sgemm_kernel(
    const float* __restrict__ A,
    const float* __restrict__ W,
    const float* __restrict__ bias,
    const float* __restrict__ resid,
    float* __restrict__ C,
    int M, int N, int K, int act)
{
    __shared__ float As[8 * 128];   // [k][m]
    __shared__ float Ws[8 * 128];   // [k][n]

    const int tid = threadIdx.x;
    const int bm = blockIdx.y * 128;
    const int bn = blockIdx.x * 128;

    const int arow = tid >> 1;            // 0..127
    const int acol = (tid & 1) * 4;       // 0 or 4
    const int wrow = tid >> 5;            // 0..7
    const int wcol = (tid & 31) * 4;      // 0..124

    const float* Ap = A + (size_t)(bm + arow) * K + acol;
    const float* Wp = W + (size_t)wrow * N + bn + wcol;

    const int tx = tid & 15;              // 0..15
    const int ty = tid >> 4;              // 0..15

    float acc[8][8];
    #pragma unroll
    for (int i = 0; i < 8; i++)
        #pragma unroll
        for (int j = 0; j < 8; j++) acc[i][j] = 0.f;

    const int nk = K >> 3;
    for (int t = 0; t < nk; t++) {
        const float4 av = *reinterpret_cast<const float4*>(Ap);
        const float4 wv = *reinterpret_cast<const float4*>(Wp);
        __syncthreads();
        As[(acol + 0) * 128 + arow] = av.x;
        As[(acol + 1) * 128 + arow] = av.y;
        As[(acol + 2) * 128 + arow] = av.z;
        As[(acol + 3) * 128 + arow] = av.w;
        *reinterpret_cast<float4*>(&Ws[wrow * 128 + wcol]) = wv;
        __syncthreads();

        #pragma unroll
        for (int kk = 0; kk < 8; kk++) {
            float ra[8], rb[8];
            *reinterpret_cast<float4*>(&ra[0]) = *reinterpret_cast<const float4*>(&As[kk * 128 + ty * 4]);
            *reinterpret_cast<float4*>(&ra[4]) = *reinterpret_cast<const float4*>(&As[kk * 128 + ty * 4 + 64]);
            *reinterpret_cast<float4*>(&rb[0]) = *reinterpret_cast<const float4*>(&Ws[kk * 128 + tx * 4]);
            *reinterpret_cast<float4*>(&rb[4]) = *reinterpret_cast<const float4*>(&Ws[kk * 128 + tx * 4 + 64]);
            #pragma unroll
            for (int i = 0; i < 8; i++)
                #pragma unroll
                for (int j = 0; j < 8; j++)
                    acc[i][j] += ra[i] * rb[j];
        }
        Ap += 8;
        Wp += (size_t)8 * N;
    }

    // Epilogue
    const float4 b0 = *reinterpret_cast<const float4*>(&bias[bn + tx * 4]);
    const float4 b1 = *reinterpret_cast<const float4*>(&bias[bn + tx * 4 + 64]);

    #pragma unroll
    for (int i = 0; i < 8; i++) {
        const int row = bm + ((i >> 2) << 6) + ty * 4 + (i & 3);
        float v[8];
        v[0] = acc[i][0] + b0.x; v[1] = acc[i][1] + b0.y;
        v[2] = acc[i][2] + b0.z; v[3] = acc[i][3] + b0.w;
        v[4] = acc[i][4] + b1.x; v[5] = acc[i][5] + b1.y;
        v[6] = acc[i][6] + b1.z; v[7] = acc[i][7] + b1.w;
        if (act) {
            #pragma unroll
            for (int j = 0; j < 8; j++) v[j] = gelu_f(v[j]);
        }
        const size_t off = (size_t)row * N + bn + tx * 4;
        if (resid) {
            const float4 r0 = *reinterpret_cast<const float4*>(&resid[off]);
            const float4 r1 = *reinterpret_cast<const float4*>(&resid[off + 64]);
            v[0] += r0.x; v[1] += r0.y; v[2] += r0.z; v[3] += r0.w;
            v[4] += r1.x; v[5] += r1.y; v[6] += r1.z; v[7] += r1.w;
        }
        *reinterpret_cast<float4*>(&C[off])      = make_float4(v[0], v[1], v[2], v[3]);
        *reinterpret_cast<float4*>(&C[off + 64]) = make_float4(v[4], v[5], v[6], v[7]);
    }
}

// ---------------------------------------------------------------------------
// Flash attention (fp32), causal. One block per (q-tile of 64, b*h).
// qkv layout: [M, 3C]; q cols [h*64, h*64+64), k at +C, v at +2C.
// 256 threads = 16x16; each thread owns a 4x4 fragment of the 64x64 S tile.
// Shared: QsT[d][i], KP (K^T then P), Vs[k][d]  -> exactly 48 KB.
// ---------------------------------------------------------------------------
__global__ __launch_bounds__(256) void attn_kernel(
    const float* __restrict__ qkv,
    float* __restrict__ out)
{
    __shared__ float QsT[64 * 64];  // [d][i]
    __shared__ float KP [64 * 64];  // K^T [d][j], then P [i][j]
    __shared__ float Vs [64 * 64];  // [k][d]

    const int tid = threadIdx.x;
    const int qt  = blockIdx.x;          // 0..31
    const int bh  = blockIdx.y;          // 0..63
    const int b   = bh >> 4;
    const int h   = bh & 15;
    const int q0  = qt * 64;

    const int tr = tid >> 4;             // 0..15 (row group)
    const int tc = tid & 15;             // 0..15 (col group)

    const size_t base = (size_t)b * 2048 * 3072 + (size_t)h * 64;

    // Load Q transposed: QsT[d][i]
    for (int idx = tid; idx < 1024; idx += 256) {
        const int r  = idx >> 4;          // q row within tile
        const int c4 = (idx & 15) << 2;   // d group
        const float4 qv = *reinterpret_cast<const float4*>(
            qkv + base + (size_t)(q0 + r) * 3072 + c4);
        QsT[(c4 + 0) * 64 + r] = qv.x;
        QsT[(c4 + 1) * 64 + r] = qv.y;
        QsT[(c4 + 2) * 64 + r] = qv.z;
        QsT[(c4 + 3) * 64 + r] = qv.w;
    }

    float m[4], l[4], o[4][4];
    #pragma unroll
    for (int i = 0; i < 4; i++) {
        m[i] = -1e30f; l[i] = 0.f;
        #pragma unroll
        for (int j = 0; j < 4; j++) o[i][j] = 0.f;
    }

    for (int kt = 0; kt <= qt; kt++) {
        const int k0 = kt * 64;
        __syncthreads();  // prev PV done before overwriting KP/Vs; QsT ready (1st iter)

        // Load K^T into KP, V natural into Vs
        for (int idx = tid; idx < 1024; idx += 256) {
            const int r  = idx >> 4;
            const int c4 = (idx & 15) << 2;
            const size_t roff = base + (size_t)(k0 + r) * 3072 + c4;
            const float4 kv = *reinterpret_cast<const float4*>(qkv + roff + 1024);
            KP[(c4 + 0) * 64 + r] = kv.x;
            KP[(c4 + 1) * 64 + r] = kv.y;
            KP[(c4 + 2) * 64 + r] = kv.z;
            KP[(c4 + 3) * 64 + r] = kv.w;
            const float4 vv = *reinterpret_cast<const float4*>(qkv + roff + 2048);
            *reinterpret_cast<float4*>(&Vs[r * 64 + c4]) = vv;
        }
        __syncthreads();

        // S = Q K^T * 0.125 (+ causal mask on diagonal tile)
        float s[4][4];
        #pragma unroll
        for (int i = 0; i < 4; i++)
            #pragma unroll
            for (int j = 0; j < 4; j++) s[i][j] = 0.f;

        #pragma unroll 8
        for (int d = 0; d < 64; d++) {
            const float4 qa = *reinterpret_cast<const float4*>(&QsT[d * 64 + tr * 4]);
            const float4 kb = *reinterpret_cast<const float4*>(&KP [d * 64 + tc * 4]);
            const float qr[4] = {qa.x, qa.y, qa.z, qa.w};
            const float kr[4] = {kb.x, kb.y, kb.z, kb.w};
            #pragma unroll
            for (int i = 0; i < 4; i++)
                #pragma unroll
                for (int j = 0; j < 4; j++)
                    s[i][j] += qr[i] * kr[j];
        }

        #pragma unroll
        for (int i = 0; i < 4; i++)
            #pragma unroll
            for (int j = 0; j < 4; j++) {
                float sv = s[i][j] * 0.125f;
                if (kt == qt && (tc * 4 + j) > (tr * 4 + i)) sv = -1e30f;
                s[i][j] = sv;
            }

        // online softmax row stats (rows live in lanes [tr%2]*16.. within warp)
        float alpha[4];
        #pragma unroll
        for (int i = 0; i < 4; i++) {
            float rm = fmaxf(fmaxf(s[i][0], s[i][1]), fmaxf(s[i][2], s[i][3]));
            #pragma unroll
            for (int off = 8; off > 0; off >>= 1)
                rm = fmaxf(rm, __shfl_xor_sync(0xffffffffu, rm, off, 16));
            const float mn = fmaxf(m[i], rm);
            alpha[i] = __expf(m[i] - mn);
            m[i] = mn;

            float rs = 0.f;
            #pragma unroll
            for (int j = 0; j < 4; j++) {
                s[i][j] = __expf(s[i][j] - mn);
                rs += s[i][j];
            }
            #pragma unroll
            for (int off = 8; off > 0; off >>= 1)
                rs += __shfl_xor_sync(0xffffffffu, rs, off, 16);
            l[i] = l[i] * alpha[i] + rs;
            #pragma unroll
            for (int j = 0; j < 4; j++) o[i][j] *= alpha[i];
        }

        __syncthreads();  // everyone done reading K from KP
        // store P natural: KP[i][j]
        #pragma unroll
        for (int i = 0; i < 4; i++)
            #pragma unroll
            for (int j = 0; j < 4; j++)
                KP[(tr * 4 + i) * 64 + tc * 4 + j] = s[i][j];
        __syncthreads();

        // O += P @ V
        #pragma unroll 8
        for (int k = 0; k < 64; k++) {
            const float4 vv = *reinterpret_cast<const float4*>(&Vs[k * 64 + tc * 4]);
            #pragma unroll
            for (int i = 0; i < 4; i++) {
                const float pi = KP[(tr * 4 + i) * 64 + k];
                o[i][0] += pi * vv.x;
                o[i][1] += pi * vv.y;
                o[i][2] += pi * vv.z;
                o[i][3] += pi * vv.w;
            }
        }
    }

    // finalize + write (B,T,C) layout
    #pragma unroll
    for (int i = 0; i < 4; i++) {
        const float inv = 1.0f / l[i];
        float4 ov = make_float4(o[i][0] * inv, o[i][1] * inv, o[i][2] * inv, o[i][3] * inv);
        *reinterpret_cast<float4*>(
            &out[(size_t)(b * 2048 + q0 + tr * 4 + i) * 1024 + h * 64 + tc * 4]) = ov;
    }
}

// ---------------------------------------------------------------------------
// Launch
// ---------------------------------------------------------------------------
extern "C" void kernel_launch(void* const* d_in, const int* in_sizes, int n_in,
                              void* d_out, int out_size)
{
    const float* x        = (const float*)d_in[0];
    const float* c_attn_w = (const float*)d_in[1];
    const float* c_attn_b = (const float*)d_in[2];
    const float* c_proj_w = (const float*)d_in[3];
    const float* c_proj_b = (const float*)d_in[4];
    const float* fc_w     = (const float*)d_in[5];
    const float* fc_b     = (const float*)d_in[6];
    const float* proj_w   = (const float*)d_in[7];
    const float* proj_b   = (const float*)d_in[8];
    const float* ln1_g    = (const float*)d_in[9];
    const float* ln1_b    = (const float*)d_in[10];
    const float* ln2_g    = (const float*)d_in[11];
    const float* ln2_b    = (const float*)d_in[12];

    float *ln1, *qkv, *attn, *x1, *ln2, *hbuf;
    cudaGetSymbolAddress((void**)&ln1,  g_ln1);
    cudaGetSymbolAddress((void**)&qkv,  g_qkv);
    cudaGetSymbolAddress((void**)&attn, g_attn);
    cudaGetSymbolAddress((void**)&x1,   g_x1);
    cudaGetSymbolAddress((void**)&ln2,  g_ln2);
    cudaGetSymbolAddress((void**)&hbuf, g_hbuf);

    float* outp = (float*)d_out;

    // 1. ln1 = LN(x)
    ln_kernel<<<MROWS, 256>>>(x, ln1_g, ln1_b, ln1);
    // 2. qkv = ln1 @ c_attn_w + b        (8192 x 3072 x 1024)
    sgemm_kernel<<<dim3(3072 / 128, MROWS / 128), 256>>>(
        ln1, c_attn_w, c_attn_b, nullptr, qkv, MROWS, 3072, 1024, 0);
    // 3. attention
    attn_kernel<<<dim3(32, 64), 256>>>(qkv, attn);
    // 4. x1 = attn @ c_proj_w + b + x    (8192 x 1024 x 1024)
    sgemm_kernel<<<dim3(1024 / 128, MROWS / 128), 256>>>(
        attn, c_proj_w, c_proj_b, x, x1, MROWS, 1024, 1024, 0);
    // 5. ln2 = LN(x1)
    ln_kernel<<<MROWS, 256>>>(x1, ln2_g, ln2_b, ln2);
    // 6. h = gelu(ln2 @ fc_w + b)        (8192 x 4096 x 1024)
    sgemm_kernel<<<dim3(4096 / 128, MROWS / 128), 256>>>(
        ln2, fc_w, fc_b, nullptr, hbuf, MROWS, 4096, 1024, 1);
    // 7. out = h @ proj_w + b + x1       (8192 x 1024 x 4096)
    sgemm_kernel<<<dim3(1024 / 128, MROWS / 128), 256>>>(
        hbuf, proj_w, proj_b, x1, outp, MROWS, 1024, 4096, 0);
}

// round 2
// speedup vs baseline: 1.0002x; 1.0002x over previous
#include <cuda_runtime.h>
#include <math.h>
#include <stdint.h>

// ---------------------------------------------------------------------------
// Problem constants: B=4, T=2048, C=1024, H=16, HS=64
// M = B*T = 8192 rows
// ---------------------------------------------------------------------------
#define MROWS 8192
#define CDIM  1024

// Scratch (allocation-free: __device__ globals)
__device__ float g_ln1 [8192u * 1024];
__device__ float g_qkv [8192u * 3072];
__device__ float g_attn[8192u * 1024];
__device__ float g_x1  [8192u * 1024];
__device__ float g_ln2 [8192u * 1024];
__device__ float g_hbuf[8192u * 4096];

// ---------------------------------------------------------------------------
// LayerNorm: one block per row (C=1024), 256 threads, float4 per thread
// ---------------------------------------------------------------------------
__global__ __launch_bounds__(256) void ln_kernel(
    const float* __restrict__ x,
    const float* __restrict__ g,
    const float* __restrict__ b,
    float* __restrict__ o)
{
    const int row = blockIdx.x;
    const int tid = threadIdx.x;
    const float4 v = reinterpret_cast<const float4*>(x + (size_t)row * CDIM)[tid];

    float s  = v.x + v.y + v.z + v.w;
    float sq = v.x * v.x + v.y * v.y + v.z * v.z + v.w * v.w;

    // warp reduce
    #pragma unroll
    for (int off = 16; off > 0; off >>= 1) {
        s  += __shfl_xor_sync(0xffffffffu, s,  off);
        sq += __shfl_xor_sync(0xffffffffu, sq, off);
    }
    __shared__ float shs[8], shq[8];
    const int wid = tid >> 5;
    if ((tid & 31) == 0) { shs[wid] = s; shq[wid] = sq; }
    __syncthreads();
    float ts = 0.f, tq = 0.f;
    #pragma unroll
    for (int w = 0; w < 8; w++) { ts += shs[w]; tq += shq[w]; }

    const float mean = ts * (1.0f / CDIM);
    const float var  = tq * (1.0f / CDIM) - mean * mean;
    const float rstd = rsqrtf(var + 1e-5f);

    const float4 gv = reinterpret_cast<const float4*>(g)[tid];
    const float4 bv = reinterpret_cast<const float4*>(b)[tid];
    float4 ov;
    ov.x = (v.x - mean) * rstd * gv.x + bv.x;
    ov.y = (v.y - mean) * rstd * gv.y + bv.y;
    ov.z = (v.z - mean) * rstd * gv.z + bv.z;
    ov.w = (v.w - mean) * rstd * gv.w + bv.w;
    reinterpret_cast<float4*>(o + (size_t)row * CDIM)[tid] = ov;
}

// ---------------------------------------------------------------------------
// SGEMM: C[M,N] = A[M,K] @ W[K,N] + bias  (+ optional GELU, + optional resid)
// 128x128x8 tile, 256 threads, 8x8 per thread (split 4+4 to stay conflict-free)
// M,N multiples of 128; K multiple of 8.
// ---------------------------------------------------------------------------
__device__ __forceinline__ float gelu_f(float x) {
    float x3 = x * x * x;
    return 0.5f * x * (1.0f + tanhf(0.7978845608028654f * (x + 0.044715f * x3)));
}

__global__ __launch_bounds__(256, 2) void sgemm_kernel(
    const float* __restrict__ A,
    const float* __restrict__ W,
    const float* __restrict__ bias,
    const float* __restrict__ resid,
    float* __restrict__ C,
    int M, int N, int K, int act)
{
    __shared__ float As[8 * 128];   // [k][m]
    __shared__ float Ws[8 * 128];   // [k][n]

    const int tid = threadIdx.x;
    const int bm = blockIdx.y * 128;
    const int bn = blockIdx.x * 128;

    const int arow = tid >> 1;            // 0..127
    const int acol = (tid & 1) * 4;       // 0 or 4
    const int wrow = tid >> 5;            // 0..7
    const int wcol = (tid & 31) * 4;      // 0..124

    const float* Ap = A + (size_t)(bm + arow) * K + acol;
    const float* Wp = W + (size_t)wrow * N + bn + wcol;

    const int tx = tid & 15;              // 0..15
    const int ty = tid >> 4;              // 0..15

    float acc[8][8];
    #pragma unroll
    for (int i = 0; i < 8; i++)
        #pragma unroll
        for (int j = 0; j < 8; j++) acc[i][j] = 0.f;

    const int nk = K >> 3;
    for (int t = 0; t < nk; t++) {
        const float4 av = *reinterpret_cast<const float4*>(Ap);
        const float4 wv = *reinterpret_cast<const float4*>(Wp);
        __syncthreads();
        As[(acol + 0) * 128 + arow] = av.x;
        As[(acol + 1) * 128 + arow] = av.y;
        As[(acol + 2) * 128 + arow] = av.z;
        As[(acol + 3) * 128 + arow] = av.w;
        *reinterpret_cast<float4*>(&Ws[wrow * 128 + wcol]) = wv;
        __syncthreads();

        #pragma unroll
        for (int kk = 0; kk < 8; kk++) {
            float ra[8], rb[8];
            *reinterpret_cast<float4*>(&ra[0]) = *reinterpret_cast<const float4*>(&As[kk * 128 + ty * 4]);
            *reinterpret_cast<float4*>(&ra[4]) = *reinterpret_cast<const float4*>(&As[kk * 128 + ty * 4 + 64]);
            *reinterpret_cast<float4*>(&rb[0]) = *reinterpret_cast<const float4*>(&Ws[kk * 128 + tx * 4]);
            *reinterpret_cast<float4*>(&rb[4]) = *reinterpret_cast<const float4*>(&Ws[kk * 128 + tx * 4 + 64]);
            #pragma unroll
            for (int i = 0; i < 8; i++)
                #pragma unroll
                for (int j = 0; j < 8; j++)
                    acc[i][j] += ra[i] * rb[j];
        }
        Ap += 8;
        Wp += (size_t)8 * N;
    }

    // Epilogue
    const float4 b0 = *reinterpret_cast<const float4*>(&bias[bn + tx * 4]);
    const float4 b1 = *reinterpret_cast<const float4*>(&bias[bn + tx * 4 + 64]);

    #pragma unroll
    for (int i = 0; i < 8; i++) {
        const int row = bm + ((i >> 2) << 6) + ty * 4 + (i & 3);
        float v[8];
        v[0] = acc[i][0] + b0.x; v[1] = acc[i][1] + b0.y;
        v[2] = acc[i][2] + b0.z; v[3] = acc[i][3] + b0.w;
        v[4] = acc[i][4] + b1.x; v[5] = acc[i][5] + b1.y;
        v[6] = acc[i][6] + b1.z; v[7] = acc[i][7] + b1.w;
        if (act) {
            #pragma unroll
            for (int j = 0; j < 8; j++) v[j] = gelu_f(v[j]);
        }
        const size_t off = (size_t)row * N + bn + tx * 4;
        if (resid) {
            const float4 r0 = *reinterpret_cast<const float4*>(&resid[off]);
            const float4 r1 = *reinterpret_cast<const float4*>(&resid[off + 64]);
            v[0] += r0.x; v[1] += r0.y; v[2] += r0.z; v[3] += r0.w;
            v[4] += r1.x; v[5] += r1.y; v[6] += r1.z; v[7] += r1.w;
        }
        *reinterpret_cast<float4*>(&C[off])      = make_float4(v[0], v[1], v[2], v[3]);
        *reinterpret_cast<float4*>(&C[off + 64]) = make_float4(v[4], v[5], v[6], v[7]);
    }
}

// ---------------------------------------------------------------------------
// Flash attention (fp32), causal. One block per (q-tile of 64, b*h).
// qkv layout: [M, 3C]; q cols [h*64, h*64+64), k at +C, v at +2C.
// 256 threads = 16x16; each thread owns a 4x4 fragment of the 64x64 S tile.
// Shared: QsT[d][i], KP (K^T then P), Vs[k][d]  -> exactly 48 KB.
// ---------------------------------------------------------------------------
__global__ __launch_bounds__(256) void attn_kernel(
    const float* __restrict__ qkv,
    float* __restrict__ out)
{
    __shared__ float QsT[64 * 64];  // [d][i]
    __shared__ float KP [64 * 64];  // K^T [d][j], then P [i][j]
    __shared__ float Vs [64 * 64];  // [k][d]

    const int tid = threadIdx.x;
    const int qt  = blockIdx.x;          // 0..31
    const int bh  = blockIdx.y;          // 0..63
    const int b   = bh >> 4;
    const int h   = bh & 15;
    const int q0  = qt * 64;

    const int tr = tid >> 4;             // 0..15 (row group)
    const int tc = tid & 15;             // 0..15 (col group)

    const size_t base = (size_t)b * 2048 * 3072 + (size_t)h * 64;

    // Load Q transposed: QsT[d][i]
    for (int idx = tid; idx < 1024; idx += 256) {
        const int r  = idx >> 4;          // q row within tile
        const int c4 = (idx & 15) << 2;   // d group
        const float4 qv = *reinterpret_cast<const float4*>(
            qkv + base + (size_t)(q0 + r) * 3072 + c4);
        QsT[(c4 + 0) * 64 + r] = qv.x;
        QsT[(c4 + 1) * 64 + r] = qv.y;
        QsT[(c4 + 2) * 64 + r] = qv.z;
        QsT[(c4 + 3) * 64 + r] = qv.w;
    }

    float m[4], l[4], o[4][4];
    #pragma unroll
    for (int i = 0; i < 4; i++) {
        m[i] = -1e30f; l[i] = 0.f;
        #pragma unroll
        for (int j = 0; j < 4; j++) o[i][j] = 0.f;
    }

    for (int kt = 0; kt <= qt; kt++) {
        const int k0 = kt * 64;
        __syncthreads();  // prev PV done before overwriting KP/Vs; QsT ready (1st iter)

        // Load K^T into KP, V natural into Vs
        for (int idx = tid; idx < 1024; idx += 256) {
            const int r  = idx >> 4;
            const int c4 = (idx & 15) << 2;
            const size_t roff = base + (size_t)(k0 + r) * 3072 + c4;
            const float4 kv = *reinterpret_cast<const float4*>(qkv + roff + 1024);
            KP[(c4 + 0) * 64 + r] = kv.x;
            KP[(c4 + 1) * 64 + r] = kv.y;
            KP[(c4 + 2) * 64 + r] = kv.z;
            KP[(c4 + 3) * 64 + r] = kv.w;
            const float4 vv = *reinterpret_cast<const float4*>(qkv + roff + 2048);
            *reinterpret_cast<float4*>(&Vs[r * 64 + c4]) = vv;
        }
        __syncthreads();

        // S = Q K^T * 0.125 (+ causal mask on diagonal tile)
        float s[4][4];
        #pragma unroll
        for (int i = 0; i < 4; i++)
            #pragma unroll
            for (int j = 0; j < 4; j++) s[i][j] = 0.f;

        #pragma unroll 8
        for (int d = 0; d < 64; d++) {
            const float4 qa = *reinterpret_cast<const float4*>(&QsT[d * 64 + tr * 4]);
            const float4 kb = *reinterpret_cast<const float4*>(&KP [d * 64 + tc * 4]);
            const float qr[4] = {qa.x, qa.y, qa.z, qa.w};
            const float kr[4] = {kb.x, kb.y, kb.z, kb.w};
            #pragma unroll
            for (int i = 0; i < 4; i++)
                #pragma unroll
                for (int j = 0; j < 4; j++)
                    s[i][j] += qr[i] * kr[j];
        }

        #pragma unroll
        for (int i = 0; i < 4; i++)
            #pragma unroll
            for (int j = 0; j < 4; j++) {
                float sv = s[i][j] * 0.125f;
                if (kt == qt && (tc * 4 + j) > (tr * 4 + i)) sv = -1e30f;
                s[i][j] = sv;
            }

        // online softmax row stats (rows live in lanes [tr%2]*16.. within warp)
        float alpha[4];
        #pragma unroll
        for (int i = 0; i < 4; i++) {
            float rm = fmaxf(fmaxf(s[i][0], s[i][1]), fmaxf(s[i][2], s[i][3]));
            #pragma unroll
            for (int off = 8; off > 0; off >>= 1)
                rm = fmaxf(rm, __shfl_xor_sync(0xffffffffu, rm, off, 16));
            const float mn = fmaxf(m[i], rm);
            alpha[i] = __expf(m[i] - mn);
            m[i] = mn;

            float rs = 0.f;
            #pragma unroll
            for (int j = 0; j < 4; j++) {
                s[i][j] = __expf(s[i][j] - mn);
                rs += s[i][j];
            }
            #pragma unroll
            for (int off = 8; off > 0; off >>= 1)
                rs += __shfl_xor_sync(0xffffffffu, rs, off, 16);
            l[i] = l[i] * alpha[i] + rs;
            #pragma unroll
            for (int j = 0; j < 4; j++) o[i][j] *= alpha[i];
        }

        __syncthreads();  // everyone done reading K from KP
        // store P natural: KP[i][j]
        #pragma unroll
        for (int i = 0; i < 4; i++)
            #pragma unroll
            for (int j = 0; j < 4; j++)
                KP[(tr * 4 + i) * 64 + tc * 4 + j] = s[i][j];
        __syncthreads();

        // O += P @ V
        #pragma unroll 8
        for (int k = 0; k < 64; k++) {
            const float4 vv = *reinterpret_cast<const float4*>(&Vs[k * 64 + tc * 4]);
            #pragma unroll
            for (int i = 0; i < 4; i++) {
                const float pi = KP[(tr * 4 + i) * 64 + k];
                o[i][0] += pi * vv.x;
                o[i][1] += pi * vv.y;
                o[i][2] += pi * vv.z;
                o[i][3] += pi * vv.w;
            }
        }
    }

    // finalize + write (B,T,C) layout
    #pragma unroll
    for (int i = 0; i < 4; i++) {
        const float inv = 1.0f / l[i];
        float4 ov = make_float4(o[i][0] * inv, o[i][1] * inv, o[i][2] * inv, o[i][3] * inv);
        *reinterpret_cast<float4*>(
            &out[(size_t)(b * 2048 + q0 + tr * 4 + i) * 1024 + h * 64 + tc * 4]) = ov;
    }
}

// ---------------------------------------------------------------------------
// Launch
// ---------------------------------------------------------------------------
extern "C" void kernel_launch(void* const* d_in, const int* in_sizes, int n_in,
                              void* d_out, int out_size)
{
    const float* x        = (const float*)d_in[0];
    const float* c_attn_w = (const float*)d_in[1];
    const float* c_attn_b = (const float*)d_in[2];
    const float* c_proj_w = (const float*)d_in[3];
    const float* c_proj_b = (const float*)d_in[4];
    const float* fc_w     = (const float*)d_in[5];
    const float* fc_b     = (const float*)d_in[6];
    const float* proj_w   = (const float*)d_in[7];
    const float* proj_b   = (const float*)d_in[8];
    const float* ln1_g    = (const float*)d_in[9];
    const float* ln1_b    = (const float*)d_in[10];
    const float* ln2_g    = (const float*)d_in[11];
    const float* ln2_b    = (const float*)d_in[12];

    float *ln1, *qkv, *attn, *x1, *ln2, *hbuf;
    cudaGetSymbolAddress((void**)&ln1,  g_ln1);
    cudaGetSymbolAddress((void**)&qkv,  g_qkv);
    cudaGetSymbolAddress((void**)&attn, g_attn);
    cudaGetSymbolAddress((void**)&x1,   g_x1);
    cudaGetSymbolAddress((void**)&ln2,  g_ln2);
    cudaGetSymbolAddress((void**)&hbuf, g_hbuf);

    float* outp = (float*)d_out;

    // 1. ln1 = LN(x)
    ln_kernel<<<MROWS, 256>>>(x, ln1_g, ln1_b, ln1);
    // 2. qkv = ln1 @ c_attn_w + b        (8192 x 3072 x 1024)
    sgemm_kernel<<<dim3(3072 / 128, MROWS / 128), 256>>>(
        ln1, c_attn_w, c_attn_b, nullptr, qkv, MROWS, 3072, 1024, 0);
    // 3. attention
    attn_kernel<<<dim3(32, 64), 256>>>(qkv, attn);
    // 4. x1 = attn @ c_proj_w + b + x    (8192 x 1024 x 1024)
    sgemm_kernel<<<dim3(1024 / 128, MROWS / 128), 256>>>(
        attn, c_proj_w, c_proj_b, x, x1, MROWS, 1024, 1024, 0);
    // 5. ln2 = LN(x1)
    ln_kernel<<<MROWS, 256>>>(x1, ln2_g, ln2_b, ln2);
    // 6. h = gelu(ln2 @ fc_w + b)        (8192 x 4096 x 1024)
    sgemm_kernel<<<dim3(4096 / 128, MROWS / 128), 256>>>(
        ln2, fc_w, fc_b, nullptr, hbuf, MROWS, 4096, 1024, 1);
    // 7. out = h @ proj_w + b + x1       (8192 x 1024 x 4096)
    sgemm_kernel<<<dim3(1024 / 128, MROWS / 128), 256>>>(
        hbuf, proj_w, proj_b, x1, outp, MROWS, 1024, 4096, 0);
}

// round 4
// speedup vs baseline: 1.8305x; 1.8302x over previous
#include <cuda_runtime.h>
#include <math.h>
#include <stdint.h>

// ---------------------------------------------------------------------------
// B=4, T=2048, C=1024, H=16, HS=64. M = 8192.
// GEMMs: mma.sync.m16n8k8 tf32 (baseline PTX ISA — tcgen05 is unavailable:
// harness ptxas targets sm_103 without the 'a' feature set).
// ---------------------------------------------------------------------------
#define MROWS 8192
#define CDIM  1024

__device__ float g_ln1 [8192u * 1024];
__device__ float g_qkv [8192u * 3072];
__device__ float g_attn[8192u * 1024];
__device__ float g_x1  [8192u * 1024];
__device__ float g_ln2 [8192u * 1024];
__device__ float g_hbuf[8192u * 4096];
__device__ float g_w1r [1024u * 3072];
__device__ float g_w2r [1024u * 1024];
__device__ float g_w3r [1024u * 4096];
__device__ float g_w4r [4096u * 1024];

// ---------------- helpers ----------------
__device__ __forceinline__ float tf32r(float x) {
    uint32_t u;
    asm("cvt.rna.tf32.f32 %0, %1;" : "=r"(u) : "f"(x));
    return __uint_as_float(u);
}
__device__ __forceinline__ uint32_t smem_u32(const void* p) {
    uint32_t a;
    asm("{ .reg .u64 t; cvta.to.shared.u64 t, %1; cvt.u32.u64 %0, t; }"
        : "=r"(a) : "l"(p));
    return a;
}
#define CP_ASYNC16(dst, src) \
    asm volatile("cp.async.cg.shared.global [%0], [%1], 16;" :: "r"(dst), "l"(src))
#define CP_COMMIT() asm volatile("cp.async.commit_group;" ::: "memory")
#define CP_WAIT0()  asm volatile("cp.async.wait_group 0;"  ::: "memory")

__device__ __forceinline__ void mma_tf32(float c[4], const uint32_t a[4],
                                         uint32_t b0, uint32_t b1) {
    asm volatile(
        "mma.sync.aligned.m16n8k8.row.col.f32.tf32.tf32.f32 "
        "{%0,%1,%2,%3}, {%4,%5,%6,%7}, {%8,%9}, {%0,%1,%2,%3};"
        : "+f"(c[0]), "+f"(c[1]), "+f"(c[2]), "+f"(c[3])
        : "r"(a[0]), "r"(a[1]), "r"(a[2]), "r"(a[3]), "r"(b0), "r"(b1));
}

__device__ __forceinline__ float gelu_f(float x) {
    float x3 = x * x * x;
    return 0.5f * x * (1.0f + tanhf(0.7978845608028654f * (x + 0.044715f * x3)));
}

// ---------------------------------------------------------------------------
// Weight rounding: out = rna_tf32(in), same layout
// ---------------------------------------------------------------------------
__global__ __launch_bounds__(256) void wround_kernel(
    const float* __restrict__ in, float* __restrict__ out, int n4)
{
    const int i = blockIdx.x * 256 + threadIdx.x;
    if (i >= n4) return;
    const float4 v = reinterpret_cast<const float4*>(in)[i];
    reinterpret_cast<float4*>(out)[i] =
        make_float4(tf32r(v.x), tf32r(v.y), tf32r(v.z), tf32r(v.w));
}

// ---------------------------------------------------------------------------
// LayerNorm (row = 1024), normal output
// ---------------------------------------------------------------------------
__global__ __launch_bounds__(256) void ln_kernel(
    const float* __restrict__ x, const float* __restrict__ g,
    const float* __restrict__ b, float* __restrict__ o)
{
    const int row = blockIdx.x;
    const int tid = threadIdx.x;
    const float4 v = reinterpret_cast<const float4*>(x + (size_t)row * CDIM)[tid];

    float s  = v.x + v.y + v.z + v.w;
    float sq = v.x * v.x + v.y * v.y + v.z * v.z + v.w * v.w;
    #pragma unroll
    for (int off = 16; off > 0; off >>= 1) {
        s  += __shfl_xor_sync(0xffffffffu, s,  off);
        sq += __shfl_xor_sync(0xffffffffu, sq, off);
    }
    __shared__ float shs[8], shq[8];
    const int wid = tid >> 5;
    if ((tid & 31) == 0) { shs[wid] = s; shq[wid] = sq; }
    __syncthreads();
    float ts = 0.f, tq = 0.f;
    #pragma unroll
    for (int w = 0; w < 8; w++) { ts += shs[w]; tq += shq[w]; }

    const float mean = ts * (1.0f / CDIM);
    const float var  = tq * (1.0f / CDIM) - mean * mean;
    const float rstd = rsqrtf(var + 1e-5f);

    const float4 gv = reinterpret_cast<const float4*>(g)[tid];
    const float4 bv = reinterpret_cast<const float4*>(b)[tid];
    float4 ov;
    ov.x = (v.x - mean) * rstd * gv.x + bv.x;
    ov.y = (v.y - mean) * rstd * gv.y + bv.y;
    ov.z = (v.z - mean) * rstd * gv.z + bv.z;
    ov.w = (v.w - mean) * rstd * gv.w + bv.w;
    reinterpret_cast<float4*>(o + (size_t)row * CDIM)[tid] = ov;
}

// ---------------------------------------------------------------------------
// tf32 mma.sync GEMM: C[M,N] = A[M,K] @ W[K,N] + bias (+gelu) (+resid)
// 128x128x32 CTA tile, 8 warps (4 m x 2 n), warp tile 32x64.
// Smem: As[2][32][136] ([k][m], tf32-rounded at STS), Bs[2][32][136] ([k][n],
// cp.async direct from pre-rounded W). Conflict-free fragment loads.
// ---------------------------------------------------------------------------
#define SSTR 136
#define GEMM_SMEM (4 * 32 * SSTR * 4)   // 69632 bytes

__global__ __launch_bounds__(256, 2) void mma_gemm(
    const float* __restrict__ A, const float* __restrict__ W,
    const float* __restrict__ bias, const float* __restrict__ resid,
    float* __restrict__ C, int M, int N, int K, int act)
{
    extern __shared__ float sm[];
    float* As = sm;                     // 2 bufs
    float* Bs = sm + 2 * 32 * SSTR;     // 2 bufs
    const uint32_t bs_u = smem_u32(Bs);

    const int tid  = threadIdx.x;
    const int wid  = tid >> 5;
    const int lane = tid & 31;
    const int wm = (wid & 3) * 32;
    const int wn = (wid >> 2) * 64;
    const int bm = blockIdx.y << 7;
    const int bn = blockIdx.x << 7;
    const int lr = lane >> 2;           // 0..7
    const int lc = lane & 3;            // 0..3

    float acc[2][8][4];
    #pragma unroll
    for (int mt = 0; mt < 2; mt++)
        #pragma unroll
        for (int nt = 0; nt < 8; nt++)
            #pragma unroll
            for (int j = 0; j < 4; j++) acc[mt][nt][j] = 0.f;

    // A: flat = i*256+tid -> m = flat>>3 (0..127), k4 = flat&7
    // B: flat -> k = flat>>5 (0..31), n4 = flat&31
    int am[4], ak4[4];
    const float* ag[4];
    const float* bg[4];
    uint32_t bd0[4];
    #pragma unroll
    for (int i = 0; i < 4; i++) {
        const int flat = i * 256 + tid;
        am[i]  = flat >> 3;
        ak4[i] = flat & 7;
        ag[i]  = A + (size_t)(bm + am[i]) * K + ak4[i] * 4;
        const int k  = flat >> 5;
        const int n4 = flat & 31;
        bg[i]  = W + (size_t)k * N + bn + n4 * 4;
        bd0[i] = bs_u + (uint32_t)(k * SSTR + n4 * 4) * 4;
    }

    const int nk = K >> 5;

    // prologue: A tile 0 -> regs, B tile 0 -> cp.async buf0
    float4 av[4];
    #pragma unroll
    for (int i = 0; i < 4; i++) av[i] = *reinterpret_cast<const float4*>(ag[i]);
    #pragma unroll
    for (int i = 0; i < 4; i++) CP_ASYNC16(bd0[i], bg[i]);
    CP_COMMIT();

    for (int t = 0; t < nk; t++) {
        const int buf = t & 1;
        float* Ab = As + buf * 32 * SSTR;

        // store A regs (tf32-rounded, transposed [k][m])
        #pragma unroll
        for (int i = 0; i < 4; i++) {
            float* p = Ab + (ak4[i] * 4) * SSTR + am[i];
            p[0 * SSTR] = tf32r(av[i].x);
            p[1 * SSTR] = tf32r(av[i].y);
            p[2 * SSTR] = tf32r(av[i].z);
            p[3 * SSTR] = tf32r(av[i].w);
        }
        CP_WAIT0();
        __syncthreads();

        // prefetch next tile
        if (t + 1 < nk) {
            const uint32_t nb = (uint32_t)(((t + 1) & 1) * 32 * SSTR * 4);
            #pragma unroll
            for (int i = 0; i < 4; i++) {
                ag[i] += 32;
                av[i] = *reinterpret_cast<const float4*>(ag[i]);
            }
            #pragma unroll
            for (int i = 0; i < 4; i++) {
                bg[i] += (size_t)32 * N;
                CP_ASYNC16(bd0[i] + nb, bg[i]);
            }
            CP_COMMIT();
        }

        // compute
        const float* Abuf = As + buf * 32 * SSTR;
        const float* Bbuf = Bs + buf * 32 * SSTR;
        #pragma unroll
        for (int kk = 0; kk < 32; kk += 8) {
            uint32_t a[2][4];
            #pragma unroll
            for (int mt = 0; mt < 2; mt++) {
                const float* ap = Abuf + (kk + lc) * SSTR + wm + mt * 16 + lr;
                a[mt][0] = __float_as_uint(ap[0]);
                a[mt][1] = __float_as_uint(ap[8]);
                a[mt][2] = __float_as_uint(ap[4 * SSTR]);
                a[mt][3] = __float_as_uint(ap[4 * SSTR + 8]);
            }
            #pragma unroll
            for (int nt = 0; nt < 8; nt++) {
                const float* bp = Bbuf + (kk + lc) * SSTR + wn + nt * 8 + lr;
                const uint32_t b0 = __float_as_uint(bp[0]);
                const uint32_t b1 = __float_as_uint(bp[4 * SSTR]);
                mma_tf32(acc[0][nt], a[0], b0, b1);
                mma_tf32(acc[1][nt], a[1], b0, b1);
            }
        }
        __syncthreads();
    }

    // epilogue: c0:(lr, 2lc) c1:(lr, 2lc+1) c2:(lr+8, 2lc) c3:(lr+8, 2lc+1)
    #pragma unroll
    for (int mt = 0; mt < 2; mt++) {
        const int r0 = bm + wm + mt * 16 + lr;
        const int r1 = r0 + 8;
        #pragma unroll
        for (int nt = 0; nt < 8; nt++) {
            const int col = bn + wn + nt * 8 + lc * 2;
            const float bb0 = __ldg(&bias[col]);
            const float bb1 = __ldg(&bias[col + 1]);
            float v0 = acc[mt][nt][0] + bb0;
            float v1 = acc[mt][nt][1] + bb1;
            float v2 = acc[mt][nt][2] + bb0;
            float v3 = acc[mt][nt][3] + bb1;
            if (act) {
                v0 = gelu_f(v0); v1 = gelu_f(v1);
                v2 = gelu_f(v2); v3 = gelu_f(v3);
            }
            const size_t o0 = (size_t)r0 * N + col;
            const size_t o1 = (size_t)r1 * N + col;
            if (resid) {
                const float2 q0 = *reinterpret_cast<const float2*>(&resid[o0]);
                const float2 q1 = *reinterpret_cast<const float2*>(&resid[o1]);
                v0 += q0.x; v1 += q0.y; v2 += q1.x; v3 += q1.y;
            }
            *reinterpret_cast<float2*>(&C[o0]) = make_float2(v0, v1);
            *reinterpret_cast<float2*>(&C[o1]) = make_float2(v2, v3);
        }
    }
}

// ---------------------------------------------------------------------------
// Flash attention (fp32), causal — unchanged from the passing R1 kernel.
// ---------------------------------------------------------------------------
__global__ __launch_bounds__(256) void attn_kernel(
    const float* __restrict__ qkv,
    float* __restrict__ out)
{
    __shared__ float QsT[64 * 64];
    __shared__ float KP [64 * 64];
    __shared__ float Vs [64 * 64];

    const int tid = threadIdx.x;
    const int qt  = blockIdx.x;
    const int bh  = blockIdx.y;
    const int b   = bh >> 4;
    const int h   = bh & 15;
    const int q0  = qt * 64;

    const int tr = tid >> 4;
    const int tc = tid & 15;

    const size_t base = (size_t)b * 2048 * 3072 + (size_t)h * 64;

    for (int idx = tid; idx < 1024; idx += 256) {
        const int r  = idx >> 4;
        const int c4 = (idx & 15) << 2;
        const float4 qv = *reinterpret_cast<const float4*>(
            qkv + base + (size_t)(q0 + r) * 3072 + c4);
        QsT[(c4 + 0) * 64 + r] = qv.x;
        QsT[(c4 + 1) * 64 + r] = qv.y;
        QsT[(c4 + 2) * 64 + r] = qv.z;
        QsT[(c4 + 3) * 64 + r] = qv.w;
    }

    float m[4], l[4], o[4][4];
    #pragma unroll
    for (int i = 0; i < 4; i++) {
        m[i] = -1e30f; l[i] = 0.f;
        #pragma unroll
        for (int j = 0; j < 4; j++) o[i][j] = 0.f;
    }

    for (int kt = 0; kt <= qt; kt++) {
        const int k0 = kt * 64;
        __syncthreads();

        for (int idx = tid; idx < 1024; idx += 256) {
            const int r  = idx >> 4;
            const int c4 = (idx & 15) << 2;
            const size_t roff = base + (size_t)(k0 + r) * 3072 + c4;
            const float4 kv = *reinterpret_cast<const float4*>(qkv + roff + 1024);
            KP[(c4 + 0) * 64 + r] = kv.x;
            KP[(c4 + 1) * 64 + r] = kv.y;
            KP[(c4 + 2) * 64 + r] = kv.z;
            KP[(c4 + 3) * 64 + r] = kv.w;
            const float4 vv = *reinterpret_cast<const float4*>(qkv + roff + 2048);
            *reinterpret_cast<float4*>(&Vs[r * 64 + c4]) = vv;
        }
        __syncthreads();

        float s[4][4];
        #pragma unroll
        for (int i = 0; i < 4; i++)
            #pragma unroll
            for (int j = 0; j < 4; j++) s[i][j] = 0.f;

        #pragma unroll 8
        for (int d = 0; d < 64; d++) {
            const float4 qa = *reinterpret_cast<const float4*>(&QsT[d * 64 + tr * 4]);
            const float4 kb = *reinterpret_cast<const float4*>(&KP [d * 64 + tc * 4]);
            const float qr[4] = {qa.x, qa.y, qa.z, qa.w};
            const float kr[4] = {kb.x, kb.y, kb.z, kb.w};
            #pragma unroll
            for (int i = 0; i < 4; i++)
                #pragma unroll
                for (int j = 0; j < 4; j++)
                    s[i][j] += qr[i] * kr[j];
        }

        #pragma unroll
        for (int i = 0; i < 4; i++)
            #pragma unroll
            for (int j = 0; j < 4; j++) {
                float sv = s[i][j] * 0.125f;
                if (kt == qt && (tc * 4 + j) > (tr * 4 + i)) sv = -1e30f;
                s[i][j] = sv;
            }

        float alpha[4];
        #pragma unroll
        for (int i = 0; i < 4; i++) {
            float rm = fmaxf(fmaxf(s[i][0], s[i][1]), fmaxf(s[i][2], s[i][3]));
            #pragma unroll
            for (int off = 8; off > 0; off >>= 1)
                rm = fmaxf(rm, __shfl_xor_sync(0xffffffffu, rm, off, 16));
            const float mn = fmaxf(m[i], rm);
            alpha[i] = __expf(m[i] - mn);
            m[i] = mn;

            float rs = 0.f;
            #pragma unroll
            for (int j = 0; j < 4; j++) {
                s[i][j] = __expf(s[i][j] - mn);
                rs += s[i][j];
            }
            #pragma unroll
            for (int off = 8; off > 0; off >>= 1)
                rs += __shfl_xor_sync(0xffffffffu, rs, off, 16);
            l[i] = l[i] * alpha[i] + rs;
            #pragma unroll
            for (int j = 0; j < 4; j++) o[i][j] *= alpha[i];
        }

        __syncthreads();
        #pragma unroll
        for (int i = 0; i < 4; i++)
            #pragma unroll
            for (int j = 0; j < 4; j++)
                KP[(tr * 4 + i) * 64 + tc * 4 + j] = s[i][j];
        __syncthreads();

        #pragma unroll 8
        for (int k = 0; k < 64; k++) {
            const float4 vv = *reinterpret_cast<const float4*>(&Vs[k * 64 + tc * 4]);
            #pragma unroll
            for (int i = 0; i < 4; i++) {
                const float pi = KP[(tr * 4 + i) * 64 + k];
                o[i][0] += pi * vv.x;
                o[i][1] += pi * vv.y;
                o[i][2] += pi * vv.z;
                o[i][3] += pi * vv.w;
            }
        }
    }

    #pragma unroll
    for (int i = 0; i < 4; i++) {
        const float inv = 1.0f / l[i];
        float4 ov = make_float4(o[i][0] * inv, o[i][1] * inv, o[i][2] * inv, o[i][3] * inv);
        *reinterpret_cast<float4*>(
            &out[(size_t)(b * 2048 + q0 + tr * 4 + i) * 1024 + h * 64 + tc * 4]) = ov;
    }
}

// ---------------------------------------------------------------------------
// Launch
// ---------------------------------------------------------------------------
extern "C" void kernel_launch(void* const* d_in, const int* in_sizes, int n_in,
                              void* d_out, int out_size)
{
    const float* x        = (const float*)d_in[0];
    const float* c_attn_w = (const float*)d_in[1];
    const float* c_attn_b = (const float*)d_in[2];
    const float* c_proj_w = (const float*)d_in[3];
    const float* c_proj_b = (const float*)d_in[4];
    const float* fc_w     = (const float*)d_in[5];
    const float* fc_b     = (const float*)d_in[6];
    const float* proj_w   = (const float*)d_in[7];
    const float* proj_b   = (const float*)d_in[8];
    const float* ln1_g    = (const float*)d_in[9];
    const float* ln1_b    = (const float*)d_in[10];
    const float* ln2_g    = (const float*)d_in[11];
    const float* ln2_b    = (const float*)d_in[12];

    float *ln1, *qkv, *attn, *x1, *ln2, *hbuf, *w1r, *w2r, *w3r, *w4r;
    cudaGetSymbolAddress((void**)&ln1,  g_ln1);
    cudaGetSymbolAddress((void**)&qkv,  g_qkv);
    cudaGetSymbolAddress((void**)&attn, g_attn);
    cudaGetSymbolAddress((void**)&x1,   g_x1);
    cudaGetSymbolAddress((void**)&ln2,  g_ln2);
    cudaGetSymbolAddress((void**)&hbuf, g_hbuf);
    cudaGetSymbolAddress((void**)&w1r,  g_w1r);
    cudaGetSymbolAddress((void**)&w2r,  g_w2r);
    cudaGetSymbolAddress((void**)&w3r,  g_w3r);
    cudaGetSymbolAddress((void**)&w4r,  g_w4r);

    cudaFuncSetAttribute(mma_gemm, cudaFuncAttributeMaxDynamicSharedMemorySize, GEMM_SMEM);

    float* outp = (float*)d_out;

    // round weights to tf32 (rna)
    wround_kernel<<<(1024 * 3072 / 4 + 255) / 256, 256>>>(c_attn_w, w1r, 1024 * 3072 / 4);
    wround_kernel<<<(1024 * 1024 / 4 + 255) / 256, 256>>>(c_proj_w, w2r, 1024 * 1024 / 4);
    wround_kernel<<<(1024 * 4096 / 4 + 255) / 256, 256>>>(fc_w,     w3r, 1024 * 4096 / 4);
    wround_kernel<<<(4096 * 1024 / 4 + 255) / 256, 256>>>(proj_w,   w4r, 4096 * 1024 / 4);

    // 1. ln1 = LN(x)
    ln_kernel<<<MROWS, 256>>>(x, ln1_g, ln1_b, ln1);
    // 2. qkv = ln1 @ c_attn_w + b   (8192 x 3072 x 1024)
    mma_gemm<<<dim3(24, 64), 256, GEMM_SMEM>>>(
        ln1, w1r, c_attn_b, nullptr, qkv, MROWS, 3072, 1024, 0);
    // 3. attention
    attn_kernel<<<dim3(32, 64), 256>>>(qkv, attn);
    // 4. x1 = attn @ c_proj_w + b + x   (8192 x 1024 x 1024)
    mma_gemm<<<dim3(8, 64), 256, GEMM_SMEM>>>(
        attn, w2r, c_proj_b, x, x1, MROWS, 1024, 1024, 0);
    // 5. ln2 = LN(x1)
    ln_kernel<<<MROWS, 256>>>(x1, ln2_g, ln2_b, ln2);
    // 6. h = gelu(ln2 @ fc_w + b)   (8192 x 4096 x 1024)
    mma_gemm<<<dim3(32, 64), 256, GEMM_SMEM>>>(
        ln2, w3r, fc_b, nullptr, hbuf, MROWS, 4096, 1024, 1);
    // 7. out = h @ proj_w + b + x1  (8192 x 1024 x 4096)
    mma_gemm<<<dim3(8, 64), 256, GEMM_SMEM>>>(
        hbuf, w4r, proj_b, x1, outp, MROWS, 1024, 4096, 0);
}

// round 5
// speedup vs baseline: 2.3752x; 1.2976x over previous
#include <cuda_runtime.h>
#include <math.h>
#include <stdint.h>

// ---------------------------------------------------------------------------
// B=4, T=2048, C=1024, H=16, HS=64. M = 8192.
// GEMMs: mma.sync.m16n8k8 tf32 with FRAGMENT-PACKED operands:
//   A packed so each thread's a0..a3 fragment is one 16B granule (LDS.128)
//   W packed so each thread's b0,b1 fragment is one 8B granule (LDS.64)
// Producers (LN / attention / GELU epilogue / weight prep) write these layouts
// directly, pre-rounded to tf32 (cvt.rna).
// ---------------------------------------------------------------------------
#define MROWS 8192
#define CDIM  1024

__device__ float g_ln1 [8192u * 1024];   // packed A
__device__ float g_qkv [8192u * 3072];   // natural
__device__ float g_attn[8192u * 1024];   // packed A
__device__ float g_x1  [8192u * 1024];   // natural
__device__ float g_ln2 [8192u * 1024];   // packed A
__device__ float g_hbuf[8192u * 4096];   // packed A
__device__ float g_w1p [1024u * 3072];   // packed B
__device__ float g_w2p [1024u * 1024];
__device__ float g_w3p [1024u * 4096];
__device__ float g_w4p [4096u * 1024];

// ---------------- helpers ----------------
__device__ __forceinline__ float tf32r(float x) {
    uint32_t u;
    asm("cvt.rna.tf32.f32 %0, %1;" : "=r"(u) : "f"(x));
    return __uint_as_float(u);
}
__device__ __forceinline__ uint32_t smem_u32(const void* p) {
    uint32_t a;
    asm("{ .reg .u64 t; cvta.to.shared.u64 t, %1; cvt.u32.u64 %0, t; }"
        : "=r"(a) : "l"(p));
    return a;
}
#define CP_ASYNC16(dst, src) \
    asm volatile("cp.async.cg.shared.global [%0], [%1], 16;" :: "r"(dst), "l"(src))
#define CP_COMMIT() asm volatile("cp.async.commit_group;" ::: "memory")
#define CP_WAIT2()  asm volatile("cp.async.wait_group 2;"  ::: "memory")

__device__ __forceinline__ void mma_tf32(float c[4], uint32_t a0, uint32_t a1,
                                         uint32_t a2, uint32_t a3,
                                         uint32_t b0, uint32_t b1) {
    asm volatile(
        "mma.sync.aligned.m16n8k8.row.col.f32.tf32.tf32.f32 "
        "{%0,%1,%2,%3}, {%4,%5,%6,%7}, {%8,%9}, {%0,%1,%2,%3};"
        : "+f"(c[0]), "+f"(c[1]), "+f"(c[2]), "+f"(c[3])
        : "r"(a0), "r"(a1), "r"(a2), "r"(a3), "r"(b0), "r"(b1));
}

__device__ __forceinline__ float gelu_f(float x) {
    float x3 = x * x * x;
    return 0.5f * x * (1.0f + tanhf(0.7978845608028654f * (x + 0.044715f * x3)));
}

// Packed-A address (float index) for element (m,k) of an [M,K] A operand.
// Tile (m/128, k/32) = 4096 floats. Granule (16B) = one thread's a0..a3.
__device__ __forceinline__ size_t paddrA(int m, int k, int K) {
    const int mb = m >> 7, rm = m & 127;
    const int wm = rm >> 5, mt = (rm >> 4) & 1, lr = rm & 7, ah = (rm >> 3) & 1;
    const int kt = k >> 5, kk = (k >> 3) & 3, lc = k & 3, kh = (k >> 2) & 1;
    const int lane = lr * 4 + lc;
    const int reg  = ah + 2 * kh;
    return ((size_t)mb * (K >> 5) + kt) * 4096 +
           ((((kk * 4 + wm) * 2 + mt) * 32 + lane) * 4 + reg);
}
// Packed-B address (float index) for element (n,k) of W[K,N] viewed as [N,K].
// Tile (n/128, k/32) = 4096 floats. Granule (8B) = one thread's b0,b1.
__device__ __forceinline__ size_t paddrB(int n, int k, int K) {
    const int nb = n >> 7, rn = n & 127;
    const int wn = (rn >> 6) & 1, nt = (rn >> 3) & 7, n8 = rn & 7;
    const int kt = k >> 5, kk = (k >> 3) & 3, kh = (k >> 2) & 1;
    const int lane = n8 * 4 + (k & 3);
    return ((size_t)nb * (K >> 5) + kt) * 4096 +
           ((((kk * 2 + wn) * 8 + nt) * 32 + lane) * 2 + kh);
}

// ---------------------------------------------------------------------------
// Weight prep: W[K,N] -> packed B layout, tf32-rounded
// ---------------------------------------------------------------------------
__global__ __launch_bounds__(256) void wprep_kernel(
    const float* __restrict__ W, float* __restrict__ out, int K, int N)
{
    const int idx = blockIdx.x * 256 + threadIdx.x;
    if (idx >= (K >> 2) * N) return;
    const int n = idx % N;
    const int k = (idx / N) << 2;
    #pragma unroll
    for (int i = 0; i < 4; i++)
        out[paddrB(n, k + i, K)] = tf32r(__ldg(&W[(size_t)(k + i) * N + n]));
}

// ---------------------------------------------------------------------------
// LayerNorm -> packed A, tf32-rounded
// ---------------------------------------------------------------------------
__global__ __launch_bounds__(256) void ln_kernel(
    const float* __restrict__ x, const float* __restrict__ g,
    const float* __restrict__ b, float* __restrict__ o)
{
    const int row = blockIdx.x;
    const int tid = threadIdx.x;
    const float4 v = reinterpret_cast<const float4*>(x + (size_t)row * CDIM)[tid];

    float s  = v.x + v.y + v.z + v.w;
    float sq = v.x * v.x + v.y * v.y + v.z * v.z + v.w * v.w;
    #pragma unroll
    for (int off = 16; off > 0; off >>= 1) {
        s  += __shfl_xor_sync(0xffffffffu, s,  off);
        sq += __shfl_xor_sync(0xffffffffu, sq, off);
    }
    __shared__ float shs[8], shq[8];
    const int wid = tid >> 5;
    if ((tid & 31) == 0) { shs[wid] = s; shq[wid] = sq; }
    __syncthreads();
    float ts = 0.f, tq = 0.f;
    #pragma unroll
    for (int w = 0; w < 8; w++) { ts += shs[w]; tq += shq[w]; }

    const float mean = ts * (1.0f / CDIM);
    const float var  = tq * (1.0f / CDIM) - mean * mean;
    const float rstd = rsqrtf(var + 1e-5f);

    const float4 gv = reinterpret_cast<const float4*>(g)[tid];
    const float4 bv = reinterpret_cast<const float4*>(b)[tid];
    const int k = tid << 2;
    o[paddrA(row, k + 0, CDIM)] = tf32r((v.x - mean) * rstd * gv.x + bv.x);
    o[paddrA(row, k + 1, CDIM)] = tf32r((v.y - mean) * rstd * gv.y + bv.y);
    o[paddrA(row, k + 2, CDIM)] = tf32r((v.z - mean) * rstd * gv.z + bv.z);
    o[paddrA(row, k + 3, CDIM)] = tf32r((v.w - mean) * rstd * gv.w + bv.w);
}

// ---------------------------------------------------------------------------
// tf32 mma.sync GEMM, fragment-packed operands.
// CTA 128x128x32, 8 warps (4m x 2n), warp tile 32x64.
// 3-stage cp.async pipeline; stage = A 16KB + B 16KB contiguous tiles.
// ---------------------------------------------------------------------------
#define GSTG 3
#define STG_FLOATS 8192                  // 32KB per stage
#define GEMM_SMEM (GSTG * STG_FLOATS * 4)

__global__ __launch_bounds__(256, 2) void mma_gemm(
    const float* __restrict__ Apk, const float* __restrict__ Bpk,
    const float* __restrict__ bias, const float* __restrict__ resid,
    float* __restrict__ C, int M, int N, int K, int act, int pack_out)
{
    extern __shared__ float sm[];
    const uint32_t sb = smem_u32(sm);

    const int tid  = threadIdx.x;
    const int wid  = tid >> 5;
    const int lane = tid & 31;
    const int wm = wid & 3;
    const int wn = wid >> 2;
    const int bm = blockIdx.y << 7;
    const int bn = blockIdx.x << 7;
    const int lr = lane >> 2;
    const int lc = lane & 3;

    const int nk = K >> 5;
    const char* abase = (const char*)Apk + (size_t)blockIdx.y * nk * 16384;
    const char* bbase = (const char*)Bpk + (size_t)blockIdx.x * nk * 16384;

    float acc[2][8][4];
    #pragma unroll
    for (int mt = 0; mt < 2; mt++)
        #pragma unroll
        for (int nt = 0; nt < 8; nt++)
            #pragma unroll
            for (int j = 0; j < 4; j++) acc[mt][nt][j] = 0.f;

    // stage issue: 8 cp.async of 16B per thread (A 16KB + B 16KB)
    #define ISSUE(t) do { \
        if ((t) < nk) { \
            const char* _a = abase + (size_t)(t) * 16384; \
            const char* _b = bbase + (size_t)(t) * 16384; \
            const uint32_t _d = sb + ((t) % GSTG) * (STG_FLOATS * 4) + tid * 16; \
            CP_ASYNC16(_d,         _a + tid * 16); \
            CP_ASYNC16(_d + 4096,  _a + 4096  + tid * 16); \
            CP_ASYNC16(_d + 8192,  _a + 8192  + tid * 16); \
            CP_ASYNC16(_d + 12288, _a + 12288 + tid * 16); \
            CP_ASYNC16(_d + 16384, _b + tid * 16); \
            CP_ASYNC16(_d + 20480, _b + 4096  + tid * 16); \
            CP_ASYNC16(_d + 24576, _b + 8192  + tid * 16); \
            CP_ASYNC16(_d + 28672, _b + 12288 + tid * 16); \
        } \
        CP_COMMIT(); \
    } while (0)

    ISSUE(0);
    ISSUE(1);

    for (int t = 0; t < nk; t++) {
        ISSUE(t + 2);
        CP_WAIT2();
        __syncthreads();

        const float* Ab = sm + (t % GSTG) * STG_FLOATS;
        const float* Bb = Ab + 4096;
        #pragma unroll
        for (int kk = 0; kk < 4; kk++) {
            const uint4 a0 = *reinterpret_cast<const uint4*>(
                Ab + (kk * 8 + wm * 2 + 0) * 128 + lane * 4);
            const uint4 a1 = *reinterpret_cast<const uint4*>(
                Ab + (kk * 8 + wm * 2 + 1) * 128 + lane * 4);
            const float* bq = Bb + (kk * 2 + wn) * 512 + lane * 2;
            #pragma unroll
            for (int nt = 0; nt < 8; nt++) {
                const uint2 bv = *reinterpret_cast<const uint2*>(bq + nt * 64);
                mma_tf32(acc[0][nt], a0.x, a0.y, a0.z, a0.w, bv.x, bv.y);
                mma_tf32(acc[1][nt], a1.x, a1.y, a1.z, a1.w, bv.x, bv.y);
            }
        }
        __syncthreads();
    }

    // epilogue: c0:(lr,2lc) c1:(lr,2lc+1) c2:(lr+8,2lc) c3:(lr+8,2lc+1)
    #pragma unroll
    for (int mt = 0; mt < 2; mt++) {
        const int r0 = bm + wm * 32 + mt * 16 + lr;
        const int r1 = r0 + 8;
        #pragma unroll
        for (int nt = 0; nt < 8; nt++) {
            const int col = bn + wn * 64 + nt * 8 + lc * 2;
            const float bb0 = __ldg(&bias[col]);
            const float bb1 = __ldg(&bias[col + 1]);
            float v0 = acc[mt][nt][0] + bb0;
            float v1 = acc[mt][nt][1] + bb1;
            float v2 = acc[mt][nt][2] + bb0;
            float v3 = acc[mt][nt][3] + bb1;
            if (act) {
                v0 = gelu_f(v0); v1 = gelu_f(v1);
                v2 = gelu_f(v2); v3 = gelu_f(v3);
            }
            if (pack_out) {
                C[paddrA(r0, col,     N)] = tf32r(v0);
                C[paddrA(r0, col + 1, N)] = tf32r(v1);
                C[paddrA(r1, col,     N)] = tf32r(v2);
                C[paddrA(r1, col + 1, N)] = tf32r(v3);
            } else {
                const size_t o0 = (size_t)r0 * N + col;
                const size_t o1 = (size_t)r1 * N + col;
                if (resid) {
                    const float2 q0 = *reinterpret_cast<const float2*>(&resid[o0]);
                    const float2 q1 = *reinterpret_cast<const float2*>(&resid[o1]);
                    v0 += q0.x; v1 += q0.y; v2 += q1.x; v3 += q1.y;
                }
                *reinterpret_cast<float2*>(&C[o0]) = make_float2(v0, v1);
                *reinterpret_cast<float2*>(&C[o1]) = make_float2(v2, v3);
            }
        }
    }
}

// ---------------------------------------------------------------------------
// Flash attention (fp32), causal. Output -> packed A, tf32-rounded.
// ---------------------------------------------------------------------------
__global__ __launch_bounds__(256) void attn_kernel(
    const float* __restrict__ qkv,
    float* __restrict__ out)
{
    __shared__ float QsT[64 * 64];
    __shared__ float KP [64 * 64];
    __shared__ float Vs [64 * 64];

    const int tid = threadIdx.x;
    const int qt  = blockIdx.x;
    const int bh  = blockIdx.y;
    const int b   = bh >> 4;
    const int h   = bh & 15;
    const int q0  = qt * 64;

    const int tr = tid >> 4;
    const int tc = tid & 15;

    const size_t base = (size_t)b * 2048 * 3072 + (size_t)h * 64;

    for (int idx = tid; idx < 1024; idx += 256) {
        const int r  = idx >> 4;
        const int c4 = (idx & 15) << 2;
        const float4 qv = *reinterpret_cast<const float4*>(
            qkv + base + (size_t)(q0 + r) * 3072 + c4);
        QsT[(c4 + 0) * 64 + r] = qv.x;
        QsT[(c4 + 1) * 64 + r] = qv.y;
        QsT[(c4 + 2) * 64 + r] = qv.z;
        QsT[(c4 + 3) * 64 + r] = qv.w;
    }

    float m[4], l[4], o[4][4];
    #pragma unroll
    for (int i = 0; i < 4; i++) {
        m[i] = -1e30f; l[i] = 0.f;
        #pragma unroll
        for (int j = 0; j < 4; j++) o[i][j] = 0.f;
    }

    for (int kt = 0; kt <= qt; kt++) {
        const int k0 = kt * 64;
        __syncthreads();

        for (int idx = tid; idx < 1024; idx += 256) {
            const int r  = idx >> 4;
            const int c4 = (idx & 15) << 2;
            const size_t roff = base + (size_t)(k0 + r) * 3072 + c4;
            const float4 kv = *reinterpret_cast<const float4*>(qkv + roff + 1024);
            KP[(c4 + 0) * 64 + r] = kv.x;
            KP[(c4 + 1) * 64 + r] = kv.y;
            KP[(c4 + 2) * 64 + r] = kv.z;
            KP[(c4 + 3) * 64 + r] = kv.w;
            const float4 vv = *reinterpret_cast<const float4*>(qkv + roff + 2048);
            *reinterpret_cast<float4*>(&Vs[r * 64 + c4]) = vv;
        }
        __syncthreads();

        float s[4][4];
        #pragma unroll
        for (int i = 0; i < 4; i++)
            #pragma unroll
            for (int j = 0; j < 4; j++) s[i][j] = 0.f;

        #pragma unroll 8
        for (int d = 0; d < 64; d++) {
            const float4 qa = *reinterpret_cast<const float4*>(&QsT[d * 64 + tr * 4]);
            const float4 kb = *reinterpret_cast<const float4*>(&KP [d * 64 + tc * 4]);
            const float qr[4] = {qa.x, qa.y, qa.z, qa.w};
            const float kr[4] = {kb.x, kb.y, kb.z, kb.w};
            #pragma unroll
            for (int i = 0; i < 4; i++)
                #pragma unroll
                for (int j = 0; j < 4; j++)
                    s[i][j] += qr[i] * kr[j];
        }

        #pragma unroll
        for (int i = 0; i < 4; i++)
            #pragma unroll
            for (int j = 0; j < 4; j++) {
                float sv = s[i][j] * 0.125f;
                if (kt == qt && (tc * 4 + j) > (tr * 4 + i)) sv = -1e30f;
                s[i][j] = sv;
            }

        float alpha[4];
        #pragma unroll
        for (int i = 0; i < 4; i++) {
            float rm = fmaxf(fmaxf(s[i][0], s[i][1]), fmaxf(s[i][2], s[i][3]));
            #pragma unroll
            for (int off = 8; off > 0; off >>= 1)
                rm = fmaxf(rm, __shfl_xor_sync(0xffffffffu, rm, off, 16));
            const float mn = fmaxf(m[i], rm);
            alpha[i] = __expf(m[i] - mn);
            m[i] = mn;

            float rs = 0.f;
            #pragma unroll
            for (int j = 0; j < 4; j++) {
                s[i][j] = __expf(s[i][j] - mn);
                rs += s[i][j];
            }
            #pragma unroll
            for (int off = 8; off > 0; off >>= 1)
                rs += __shfl_xor_sync(0xffffffffu, rs, off, 16);
            l[i] = l[i] * alpha[i] + rs;
            #pragma unroll
            for (int j = 0; j < 4; j++) o[i][j] *= alpha[i];
        }

        __syncthreads();
        #pragma unroll
        for (int i = 0; i < 4; i++)
            #pragma unroll
            for (int j = 0; j < 4; j++)
                KP[(tr * 4 + i) * 64 + tc * 4 + j] = s[i][j];
        __syncthreads();

        #pragma unroll 8
        for (int k = 0; k < 64; k++) {
            const float4 vv = *reinterpret_cast<const float4*>(&Vs[k * 64 + tc * 4]);
            #pragma unroll
            for (int i = 0; i < 4; i++) {
                const float pi = KP[(tr * 4 + i) * 64 + k];
                o[i][0] += pi * vv.x;
                o[i][1] += pi * vv.y;
                o[i][2] += pi * vv.z;
                o[i][3] += pi * vv.w;
            }
        }
    }

    const int kcol = h * 64 + tc * 4;
    #pragma unroll
    for (int i = 0; i < 4; i++) {
        const float inv = 1.0f / l[i];
        const int grow = b * 2048 + q0 + tr * 4 + i;
        out[paddrA(grow, kcol + 0, CDIM)] = tf32r(o[i][0] * inv);
        out[paddrA(grow, kcol + 1, CDIM)] = tf32r(o[i][1] * inv);
        out[paddrA(grow, kcol + 2, CDIM)] = tf32r(o[i][2] * inv);
        out[paddrA(grow, kcol + 3, CDIM)] = tf32r(o[i][3] * inv);
    }
}

// ---------------------------------------------------------------------------
// Launch
// ---------------------------------------------------------------------------
extern "C" void kernel_launch(void* const* d_in, const int* in_sizes, int n_in,
                              void* d_out, int out_size)
{
    const float* x        = (const float*)d_in[0];
    const float* c_attn_w = (const float*)d_in[1];
    const float* c_attn_b = (const float*)d_in[2];
    const float* c_proj_w = (const float*)d_in[3];
    const float* c_proj_b = (const float*)d_in[4];
    const float* fc_w     = (const float*)d_in[5];
    const float* fc_b     = (const float*)d_in[6];
    const float* proj_w   = (const float*)d_in[7];
    const float* proj_b   = (const float*)d_in[8];
    const float* ln1_g    = (const float*)d_in[9];
    const float* ln1_b    = (const float*)d_in[10];
    const float* ln2_g    = (const float*)d_in[11];
    const float* ln2_b    = (const float*)d_in[12];

    float *ln1, *qkv, *attn, *x1, *ln2, *hbuf, *w1p, *w2p, *w3p, *w4p;
    cudaGetSymbolAddress((void**)&ln1,  g_ln1);
    cudaGetSymbolAddress((void**)&qkv,  g_qkv);
    cudaGetSymbolAddress((void**)&attn, g_attn);
    cudaGetSymbolAddress((void**)&x1,   g_x1);
    cudaGetSymbolAddress((void**)&ln2,  g_ln2);
    cudaGetSymbolAddress((void**)&hbuf, g_hbuf);
    cudaGetSymbolAddress((void**)&w1p,  g_w1p);
    cudaGetSymbolAddress((void**)&w2p,  g_w2p);
    cudaGetSymbolAddress((void**)&w3p,  g_w3p);
    cudaGetSymbolAddress((void**)&w4p,  g_w4p);

    cudaFuncSetAttribute(mma_gemm, cudaFuncAttributeMaxDynamicSharedMemorySize, GEMM_SMEM);

    float* outp = (float*)d_out;

    wprep_kernel<<<3072, 256>>>(c_attn_w, w1p, 1024, 3072);
    wprep_kernel<<<1024, 256>>>(c_proj_w, w2p, 1024, 1024);
    wprep_kernel<<<4096, 256>>>(fc_w,     w3p, 1024, 4096);
    wprep_kernel<<<4096, 256>>>(proj_w,   w4p, 4096, 1024);

    // 1. ln1 = LN(x) (packed A)
    ln_kernel<<<MROWS, 256>>>(x, ln1_g, ln1_b, ln1);
    // 2. qkv = ln1 @ c_attn_w + b   (8192 x 3072 x 1024)
    mma_gemm<<<dim3(24, 64), 256, GEMM_SMEM>>>(
        ln1, w1p, c_attn_b, nullptr, qkv, MROWS, 3072, 1024, 0, 0);
    // 3. attention (packed A out)
    attn_kernel<<<dim3(32, 64), 256>>>(qkv, attn);
    // 4. x1 = attn @ c_proj_w + b + x   (8192 x 1024 x 1024)
    mma_gemm<<<dim3(8, 64), 256, GEMM_SMEM>>>(
        attn, w2p, c_proj_b, x, x1, MROWS, 1024, 1024, 0, 0);
    // 5. ln2 = LN(x1) (packed A)
    ln_kernel<<<MROWS, 256>>>(x1, ln2_g, ln2_b, ln2);
    // 6. h = gelu(ln2 @ fc_w + b)   (8192 x 4096 x 1024), packed out
    mma_gemm<<<dim3(32, 64), 256, GEMM_SMEM>>>(
        ln2, w3p, fc_b, nullptr, hbuf, MROWS, 4096, 1024, 1, 1);
    // 7. out = h @ proj_w + b + x1  (8192 x 1024 x 4096)
    mma_gemm<<<dim3(8, 64), 256, GEMM_SMEM>>>(
        hbuf, w4p, proj_b, x1, outp, MROWS, 1024, 4096, 0, 0);
}

// round 6
// speedup vs baseline: 3.9205x; 1.6506x over previous
#include <cuda_runtime.h>
#include <math.h>
#include <stdint.h>

// ---------------------------------------------------------------------------
// B=4, T=2048, C=1024, H=16, HS=64. M = 8192.
// GEMMs + attention on mma.sync.m16n8k8 tf32.
// ---------------------------------------------------------------------------
#define MROWS 8192
#define CDIM  1024

__device__ float g_ln1 [8192u * 1024];   // packed A
__device__ float g_qkv [8192u * 3072];   // natural, tf32-rounded
__device__ float g_attn[8192u * 1024];   // packed A
__device__ float g_x1  [8192u * 1024];   // natural
__device__ float g_ln2 [8192u * 1024];   // packed A
__device__ float g_hbuf[8192u * 4096];   // packed A
__device__ float g_w1p [1024u * 3072];   // packed B
__device__ float g_w2p [1024u * 1024];
__device__ float g_w3p [1024u * 4096];
__device__ float g_w4p [4096u * 1024];

// ---------------- helpers ----------------
__device__ __forceinline__ float tf32r(float x) {
    uint32_t u;
    asm("cvt.rna.tf32.f32 %0, %1;" : "=r"(u) : "f"(x));
    return __uint_as_float(u);
}
__device__ __forceinline__ uint32_t smem_u32(const void* p) {
    uint32_t a;
    asm("{ .reg .u64 t; cvta.to.shared.u64 t, %1; cvt.u32.u64 %0, t; }"
        : "=r"(a) : "l"(p));
    return a;
}
#define CP_ASYNC16(dst, src) \
    asm volatile("cp.async.cg.shared.global [%0], [%1], 16;" :: "r"(dst), "l"(src))
#define CP_COMMIT() asm volatile("cp.async.commit_group;" ::: "memory")
#define CP_WAIT0()  asm volatile("cp.async.wait_group 0;"  ::: "memory")
#define CP_WAIT1()  asm volatile("cp.async.wait_group 1;"  ::: "memory")
#define CP_WAIT2()  asm volatile("cp.async.wait_group 2;"  ::: "memory")

__device__ __forceinline__ void mma_tf32(float c[4], uint32_t a0, uint32_t a1,
                                         uint32_t a2, uint32_t a3,
                                         uint32_t b0, uint32_t b1) {
    asm volatile(
        "mma.sync.aligned.m16n8k8.row.col.f32.tf32.tf32.f32 "
        "{%0,%1,%2,%3}, {%4,%5,%6,%7}, {%8,%9}, {%0,%1,%2,%3};"
        : "+f"(c[0]), "+f"(c[1]), "+f"(c[2]), "+f"(c[3])
        : "r"(a0), "r"(a1), "r"(a2), "r"(a3), "r"(b0), "r"(b1));
}

__device__ __forceinline__ float gelu_f(float x) {
    float x3 = x * x * x;
    return 0.5f * x * (1.0f + tanhf(0.7978845608028654f * (x + 0.044715f * x3)));
}

// Packed-A address (float index) for element (m,k) of an [M,K] A operand.
__device__ __forceinline__ size_t paddrA(int m, int k, int K) {
    const int mb = m >> 7, rm = m & 127;
    const int wm = rm >> 5, mt = (rm >> 4) & 1, lr = rm & 7, ah = (rm >> 3) & 1;
    const int kt = k >> 5, kk = (k >> 3) & 3, lc = k & 3, kh = (k >> 2) & 1;
    const int lane = lr * 4 + lc;
    const int reg  = ah + 2 * kh;
    return ((size_t)mb * (K >> 5) + kt) * 4096 +
           ((((kk * 4 + wm) * 2 + mt) * 32 + lane) * 4 + reg);
}
// Packed-B address (float index) for element (n,k) of W[K,N] viewed as [N,K].
__device__ __forceinline__ size_t paddrB(int n, int k, int K) {
    const int nb = n >> 7, rn = n & 127;
    const int wn = (rn >> 6) & 1, nt = (rn >> 3) & 7, n8 = rn & 7;
    const int kt = k >> 5, kk = (k >> 3) & 3, kh = (k >> 2) & 1;
    const int lane = n8 * 4 + (k & 3);
    return ((size_t)nb * (K >> 5) + kt) * 4096 +
           ((((kk * 2 + wn) * 8 + nt) * 32 + lane) * 2 + kh);
}

// ---------------------------------------------------------------------------
// Weight prep: W[K,N] -> packed B layout, tf32-rounded
// ---------------------------------------------------------------------------
__global__ __launch_bounds__(256) void wprep_kernel(
    const float* __restrict__ W, float* __restrict__ out, int K, int N)
{
    const int idx = blockIdx.x * 256 + threadIdx.x;
    if (idx >= (K >> 2) * N) return;
    const int n = idx % N;
    const int k = (idx / N) << 2;
    #pragma unroll
    for (int i = 0; i < 4; i++)
        out[paddrB(n, k + i, K)] = tf32r(__ldg(&W[(size_t)(k + i) * N + n]));
}

// ---------------------------------------------------------------------------
// LayerNorm -> packed A, tf32-rounded
// ---------------------------------------------------------------------------
__global__ __launch_bounds__(256) void ln_kernel(
    const float* __restrict__ x, const float* __restrict__ g,
    const float* __restrict__ b, float* __restrict__ o)
{
    const int row = blockIdx.x;
    const int tid = threadIdx.x;
    const float4 v = reinterpret_cast<const float4*>(x + (size_t)row * CDIM)[tid];

    float s  = v.x + v.y + v.z + v.w;
    float sq = v.x * v.x + v.y * v.y + v.z * v.z + v.w * v.w;
    #pragma unroll
    for (int off = 16; off > 0; off >>= 1) {
        s  += __shfl_xor_sync(0xffffffffu, s,  off);
        sq += __shfl_xor_sync(0xffffffffu, sq, off);
    }
    __shared__ float shs[8], shq[8];
    const int wid = tid >> 5;
    if ((tid & 31) == 0) { shs[wid] = s; shq[wid] = sq; }
    __syncthreads();
    float ts = 0.f, tq = 0.f;
    #pragma unroll
    for (int w = 0; w < 8; w++) { ts += shs[w]; tq += shq[w]; }

    const float mean = ts * (1.0f / CDIM);
    const float var  = tq * (1.0f / CDIM) - mean * mean;
    const float rstd = rsqrtf(var + 1e-5f);

    const float4 gv = reinterpret_cast<const float4*>(g)[tid];
    const float4 bv = reinterpret_cast<const float4*>(b)[tid];
    const int k = tid << 2;
    o[paddrA(row, k + 0, CDIM)] = tf32r((v.x - mean) * rstd * gv.x + bv.x);
    o[paddrA(row, k + 1, CDIM)] = tf32r((v.y - mean) * rstd * gv.y + bv.y);
    o[paddrA(row, k + 2, CDIM)] = tf32r((v.z - mean) * rstd * gv.z + bv.z);
    o[paddrA(row, k + 3, CDIM)] = tf32r((v.w - mean) * rstd * gv.w + bv.w);
}

// ---------------------------------------------------------------------------
// tf32 mma.sync GEMM, fragment-packed operands.
// ---------------------------------------------------------------------------
#define GSTG 3
#define STG_FLOATS 8192
#define GEMM_SMEM (GSTG * STG_FLOATS * 4)

__global__ __launch_bounds__(256, 2) void mma_gemm(
    const float* __restrict__ Apk, const float* __restrict__ Bpk,
    const float* __restrict__ bias, const float* __restrict__ resid,
    float* __restrict__ C, int M, int N, int K, int act, int pack_out,
    int round_out)
{
    extern __shared__ float sm[];
    const uint32_t sb = smem_u32(sm);

    const int tid  = threadIdx.x;
    const int wid  = tid >> 5;
    const int lane = tid & 31;
    const int wm = wid & 3;
    const int wn = wid >> 2;
    const int bm = blockIdx.y << 7;
    const int bn = blockIdx.x << 7;
    const int lr = lane >> 2;
    const int lc = lane & 3;

    const int nk = K >> 5;
    const char* abase = (const char*)Apk + (size_t)blockIdx.y * nk * 16384;
    const char* bbase = (const char*)Bpk + (size_t)blockIdx.x * nk * 16384;

    float acc[2][8][4];
    #pragma unroll
    for (int mt = 0; mt < 2; mt++)
        #pragma unroll
        for (int nt = 0; nt < 8; nt++)
            #pragma unroll
            for (int j = 0; j < 4; j++) acc[mt][nt][j] = 0.f;

    #define ISSUE(t) do { \
        if ((t) < nk) { \
            const char* _a = abase + (size_t)(t) * 16384; \
            const char* _b = bbase + (size_t)(t) * 16384; \
            const uint32_t _d = sb + ((t) % GSTG) * (STG_FLOATS * 4) + tid * 16; \
            CP_ASYNC16(_d,         _a + tid * 16); \
            CP_ASYNC16(_d + 4096,  _a + 4096  + tid * 16); \
            CP_ASYNC16(_d + 8192,  _a + 8192  + tid * 16); \
            CP_ASYNC16(_d + 12288, _a + 12288 + tid * 16); \
            CP_ASYNC16(_d + 16384, _b + tid * 16); \
            CP_ASYNC16(_d + 20480, _b + 4096  + tid * 16); \
            CP_ASYNC16(_d + 24576, _b + 8192  + tid * 16); \
            CP_ASYNC16(_d + 28672, _b + 12288 + tid * 16); \
        } \
        CP_COMMIT(); \
    } while (0)

    ISSUE(0);
    ISSUE(1);

    for (int t = 0; t < nk; t++) {
        ISSUE(t + 2);
        CP_WAIT2();
        __syncthreads();

        const float* Ab = sm + (t % GSTG) * STG_FLOATS;
        const float* Bb = Ab + 4096;
        #pragma unroll
        for (int kk = 0; kk < 4; kk++) {
            const uint4 a0 = *reinterpret_cast<const uint4*>(
                Ab + (kk * 8 + wm * 2 + 0) * 128 + lane * 4);
            const uint4 a1 = *reinterpret_cast<const uint4*>(
                Ab + (kk * 8 + wm * 2 + 1) * 128 + lane * 4);
            const float* bq = Bb + (kk * 2 + wn) * 512 + lane * 2;
            #pragma unroll
            for (int nt = 0; nt < 8; nt++) {
                const uint2 bv = *reinterpret_cast<const uint2*>(bq + nt * 64);
                mma_tf32(acc[0][nt], a0.x, a0.y, a0.z, a0.w, bv.x, bv.y);
                mma_tf32(acc[1][nt], a1.x, a1.y, a1.z, a1.w, bv.x, bv.y);
            }
        }
        __syncthreads();
    }

    #pragma unroll
    for (int mt = 0; mt < 2; mt++) {
        const int r0 = bm + wm * 32 + mt * 16 + lr;
        const int r1 = r0 + 8;
        #pragma unroll
        for (int nt = 0; nt < 8; nt++) {
            const int col = bn + wn * 64 + nt * 8 + lc * 2;
            const float bb0 = __ldg(&bias[col]);
            const float bb1 = __ldg(&bias[col + 1]);
            float v0 = acc[mt][nt][0] + bb0;
            float v1 = acc[mt][nt][1] + bb1;
            float v2 = acc[mt][nt][2] + bb0;
            float v3 = acc[mt][nt][3] + bb1;
            if (act) {
                v0 = gelu_f(v0); v1 = gelu_f(v1);
                v2 = gelu_f(v2); v3 = gelu_f(v3);
            }
            if (pack_out) {
                C[paddrA(r0, col,     N)] = tf32r(v0);
                C[paddrA(r0, col + 1, N)] = tf32r(v1);
                C[paddrA(r1, col,     N)] = tf32r(v2);
                C[paddrA(r1, col + 1, N)] = tf32r(v3);
            } else {
                const size_t o0 = (size_t)r0 * N + col;
                const size_t o1 = (size_t)r1 * N + col;
                if (resid) {
                    const float2 q0 = *reinterpret_cast<const float2*>(&resid[o0]);
                    const float2 q1 = *reinterpret_cast<const float2*>(&resid[o1]);
                    v0 += q0.x; v1 += q0.y; v2 += q1.x; v3 += q1.y;
                }
                if (round_out) {
                    v0 = tf32r(v0); v1 = tf32r(v1); v2 = tf32r(v2); v3 = tf32r(v3);
                }
                *reinterpret_cast<float2*>(&C[o0]) = make_float2(v0, v1);
                *reinterpret_cast<float2*>(&C[o1]) = make_float2(v2, v3);
            }
        }
    }
}

// ---------------------------------------------------------------------------
// Flash attention on mma.sync tf32, causal.
// Block = (q-tile 64, b*h), 128 threads (4 warps, 16 q rows each).
// S = Q K^T (Q frags in regs, K natural [key][d] stride 68).
// PV done transposed: O^T = V^T P^T (V natural [key][d] stride 72, cp.async),
// P^T via per-warp smem round-trip in packed-B form.
// ---------------------------------------------------------------------------
#define AST_K 68
#define AST_V 72
#define ATT_QOFF 0                       // 64*68 = 4352 floats (also P region)
#define ATT_KOFF(b) (4352 + (b) * 4352)
#define ATT_VOFF(b) (13056 + (b) * 4608)
#define ATT_SMEM (22272 * 4)             // 89088 bytes

__global__ __launch_bounds__(128, 2) void attn_mma(
    const float* __restrict__ qkv, float* __restrict__ out)
{
    extern __shared__ float sm[];
    const uint32_t sb = smem_u32(sm);
    const int tid = threadIdx.x;
    const int w = tid >> 5, lane = tid & 31;
    const int lr = lane >> 2, lc = lane & 3;
    const int qt = blockIdx.x, bh = blockIdx.y;
    const int b = bh >> 4, h = bh & 15;
    const int q0 = qt * 64;
    const float* basep = qkv + (size_t)b * 2048 * 3072 + (size_t)h * 64;

    // Q tile -> smem (group 0)
    #pragma unroll
    for (int i = 0; i < 8; i++) {
        const int idx = tid + i * 128, row = idx >> 4, ch = idx & 15;
        CP_ASYNC16(sb + (uint32_t)(ATT_QOFF + row * AST_K + ch * 4) * 4,
                   basep + (size_t)(q0 + row) * 3072 + ch * 4);
    }
    CP_COMMIT();

    #define ISSUE_KV(kt_, bb) do { \
        const float* _k = basep + (size_t)((kt_) * 64) * 3072 + 1024; \
        _Pragma("unroll") \
        for (int _i = 0; _i < 8; _i++) { \
            const int _idx = tid + _i * 128, _r = _idx >> 4, _c = _idx & 15; \
            CP_ASYNC16(sb + (uint32_t)(ATT_KOFF(bb) + _r * AST_K + _c * 4) * 4, \
                       _k + (size_t)_r * 3072 + _c * 4); \
            CP_ASYNC16(sb + (uint32_t)(ATT_VOFF(bb) + _r * AST_V + _c * 4) * 4, \
                       _k + 1024 + (size_t)_r * 3072 + _c * 4); \
        } \
        CP_COMMIT(); \
    } while (0)

    ISSUE_KV(0, 0);      // group 1

    CP_WAIT1();          // Q ready
    __syncthreads();

    // Q fragments (scale folded; values already tf32 from qkv epilogue)
    float qa[8][4];
    {
        const float* Qs = sm + ATT_QOFF;
        const int r0 = w * 16 + lr;
        #pragma unroll
        for (int kk = 0; kk < 8; kk++) {
            qa[kk][0] = 0.125f * Qs[r0 * AST_K + kk * 8 + lc];
            qa[kk][1] = 0.125f * Qs[(r0 + 8) * AST_K + kk * 8 + lc];
            qa[kk][2] = 0.125f * Qs[r0 * AST_K + kk * 8 + lc + 4];
            qa[kk][3] = 0.125f * Qs[(r0 + 8) * AST_K + kk * 8 + lc + 4];
        }
    }
    __syncthreads();     // Qs region becomes P region

    float* Pw = sm + ATT_QOFF + w * 1024;   // per-warp P^T region (1024 floats)

    float m0 = -1e30f, m1 = -1e30f, l0 = 0.f, l1 = 0.f;
    float o[4][2][4];
    #pragma unroll
    for (int mt = 0; mt < 4; mt++)
        #pragma unroll
        for (int nt = 0; nt < 2; nt++)
            #pragma unroll
            for (int j = 0; j < 4; j++) o[mt][nt][j] = 0.f;

    for (int kt = 0; kt <= qt; kt++) {
        const int buf = kt & 1;
        if (kt < qt) { ISSUE_KV(kt + 1, buf ^ 1); CP_WAIT1(); }
        else         { CP_WAIT0(); }
        __syncthreads();

        const float* Ks = sm + ATT_KOFF(buf);
        const float* Vs = sm + ATT_VOFF(buf);

        // ---- S = Q K^T ----
        float s[8][4];
        #pragma unroll
        for (int nt = 0; nt < 8; nt++)
            #pragma unroll
            for (int j = 0; j < 4; j++) s[nt][j] = 0.f;

        #pragma unroll
        for (int kk = 0; kk < 8; kk++) {
            const uint32_t a0 = __float_as_uint(qa[kk][0]);
            const uint32_t a1 = __float_as_uint(qa[kk][1]);
            const uint32_t a2 = __float_as_uint(qa[kk][2]);
            const uint32_t a3 = __float_as_uint(qa[kk][3]);
            #pragma unroll
            for (int nt = 0; nt < 8; nt++) {
                const uint32_t b0 = __float_as_uint(Ks[(nt * 8 + lr) * AST_K + kk * 8 + lc]);
                const uint32_t b1 = __float_as_uint(Ks[(nt * 8 + lr) * AST_K + kk * 8 + lc + 4]);
                mma_tf32(s[nt], a0, a1, a2, a3, b0, b1);
            }
        }

        // ---- causal mask on diagonal tile ----
        if (kt == qt) {
            const int r0l = w * 16 + lr;
            #pragma unroll
            for (int nt = 0; nt < 8; nt++) {
                const int c = nt * 8 + 2 * lc;
                if (c     > r0l)     s[nt][0] = -1e30f;
                if (c + 1 > r0l)     s[nt][1] = -1e30f;
                if (c     > r0l + 8) s[nt][2] = -1e30f;
                if (c + 1 > r0l + 8) s[nt][3] = -1e30f;
            }
        }

        // ---- online softmax (rows lr and lr+8) ----
        float mx0 = -1e30f, mx1 = -1e30f;
        #pragma unroll
        for (int nt = 0; nt < 8; nt++) {
            mx0 = fmaxf(mx0, fmaxf(s[nt][0], s[nt][1]));
            mx1 = fmaxf(mx1, fmaxf(s[nt][2], s[nt][3]));
        }
        mx0 = fmaxf(mx0, __shfl_xor_sync(0xffffffffu, mx0, 1));
        mx0 = fmaxf(mx0, __shfl_xor_sync(0xffffffffu, mx0, 2));
        mx1 = fmaxf(mx1, __shfl_xor_sync(0xffffffffu, mx1, 1));
        mx1 = fmaxf(mx1, __shfl_xor_sync(0xffffffffu, mx1, 2));

        const float mn0 = fmaxf(m0, mx0), mn1 = fmaxf(m1, mx1);
        const float al0 = __expf(m0 - mn0), al1 = __expf(m1 - mn1);
        m0 = mn0; m1 = mn1;

        float sum0 = 0.f, sum1 = 0.f;
        #pragma unroll
        for (int nt = 0; nt < 8; nt++) {
            s[nt][0] = __expf(s[nt][0] - mn0); sum0 += s[nt][0];
            s[nt][1] = __expf(s[nt][1] - mn0); sum0 += s[nt][1];
            s[nt][2] = __expf(s[nt][2] - mn1); sum1 += s[nt][2];
            s[nt][3] = __expf(s[nt][3] - mn1); sum1 += s[nt][3];
        }
        sum0 += __shfl_xor_sync(0xffffffffu, sum0, 1);
        sum0 += __shfl_xor_sync(0xffffffffu, sum0, 2);
        sum1 += __shfl_xor_sync(0xffffffffu, sum1, 1);
        sum1 += __shfl_xor_sync(0xffffffffu, sum1, 2);
        l0 = l0 * al0 + sum0;
        l1 = l1 * al1 + sum1;

        // ---- rescale O^T (cols are q-rows: fetch alpha per column) ----
        const float zA0  = __shfl_sync(0xffffffffu, al0, 8 * lc);      // qrow 2lc
        const float zA0b = __shfl_sync(0xffffffffu, al0, 8 * lc + 4);  // qrow 2lc+1
        const float zA1  = __shfl_sync(0xffffffffu, al1, 8 * lc);      // qrow 8+2lc
        const float zA1b = __shfl_sync(0xffffffffu, al1, 8 * lc + 4);
        #pragma unroll
        for (int mt = 0; mt < 4; mt++) {
            o[mt][0][0] *= zA0;  o[mt][0][1] *= zA0b;
            o[mt][0][2] *= zA0;  o[mt][0][3] *= zA0b;
            o[mt][1][0] *= zA1;  o[mt][1][1] *= zA1b;
            o[mt][1][2] *= zA1;  o[mt][1][3] *= zA1b;
        }

        // ---- store P^T (packed B) ----
        __syncwarp();
        {
            const int c0c = 2 * lc, c1c = 2 * lc + 1;
            const int ln0 = lr * 4 + (c0c & 3), rg0 = (c0c & 4) >> 2;
            const int ln1 = lr * 4 + (c1c & 3), rg1 = (c1c & 4) >> 2;
            #pragma unroll
            for (int nt = 0; nt < 8; nt++) {
                Pw[(nt * 2 + 0) * 64 + ln0 * 2 + rg0] = tf32r(s[nt][0]);
                Pw[(nt * 2 + 0) * 64 + ln1 * 2 + rg1] = tf32r(s[nt][1]);
                Pw[(nt * 2 + 1) * 64 + ln0 * 2 + rg0] = tf32r(s[nt][2]);
                Pw[(nt * 2 + 1) * 64 + ln1 * 2 + rg1] = tf32r(s[nt][3]);
            }
        }
        __syncwarp();

        // ---- O^T += V^T P^T ----
        #pragma unroll
        for (int kk2 = 0; kk2 < 8; kk2++) {
            const uint2 bp0 = *reinterpret_cast<const uint2*>(Pw + (kk2 * 2 + 0) * 64 + lane * 2);
            const uint2 bp1 = *reinterpret_cast<const uint2*>(Pw + (kk2 * 2 + 1) * 64 + lane * 2);
            #pragma unroll
            for (int mt = 0; mt < 4; mt++) {
                const uint32_t a0 = __float_as_uint(Vs[(kk2 * 8 + lc) * AST_V + mt * 16 + lr]);
                const uint32_t a1 = __float_as_uint(Vs[(kk2 * 8 + lc) * AST_V + mt * 16 + lr + 8]);
                const uint32_t a2 = __float_as_uint(Vs[(kk2 * 8 + lc + 4) * AST_V + mt * 16 + lr]);
                const uint32_t a3 = __float_as_uint(Vs[(kk2 * 8 + lc + 4) * AST_V + mt * 16 + lr + 8]);
                mma_tf32(o[mt][0], a0, a1, a2, a3, bp0.x, bp0.y);
                mma_tf32(o[mt][1], a0, a1, a2, a3, bp1.x, bp1.y);
            }
        }
    }

    // ---- finalize: O^T cols are q-rows; fetch 1/l per column, write packed A ----
    const float i0 = 1.0f / l0, i1 = 1.0f / l1;
    const float zI0  = __shfl_sync(0xffffffffu, i0, 8 * lc);
    const float zI0b = __shfl_sync(0xffffffffu, i0, 8 * lc + 4);
    const float zI1  = __shfl_sync(0xffffffffu, i1, 8 * lc);
    const float zI1b = __shfl_sync(0xffffffffu, i1, 8 * lc + 4);

    #pragma unroll
    for (int mt = 0; mt < 4; mt++) {
        const int d0 = h * 64 + mt * 16 + lr;
        const int d1 = d0 + 8;
        #pragma unroll
        for (int ntile = 0; ntile < 2; ntile++) {
            const int qr = b * 2048 + q0 + w * 16 + ntile * 8 + 2 * lc;
            const float sc0 = ntile ? zI1 : zI0;
            const float sc1 = ntile ? zI1b : zI0b;
            out[paddrA(qr,     d0, CDIM)] = tf32r(o[mt][ntile][0] * sc0);
            out[paddrA(qr + 1, d0, CDIM)] = tf32r(o[mt][ntile][1] * sc1);
            out[paddrA(qr,     d1, CDIM)] = tf32r(o[mt][ntile][2] * sc0);
            out[paddrA(qr + 1, d1, CDIM)] = tf32r(o[mt][ntile][3] * sc1);
        }
    }
}

// ---------------------------------------------------------------------------
// Launch
// ---------------------------------------------------------------------------
extern "C" void kernel_launch(void* const* d_in, const int* in_sizes, int n_in,
                              void* d_out, int out_size)
{
    const float* x        = (const float*)d_in[0];
    const float* c_attn_w = (const float*)d_in[1];
    const float* c_attn_b = (const float*)d_in[2];
    const float* c_proj_w = (const float*)d_in[3];
    const float* c_proj_b = (const float*)d_in[4];
    const float* fc_w     = (const float*)d_in[5];
    const float* fc_b     = (const float*)d_in[6];
    const float* proj_w   = (const float*)d_in[7];
    const float* proj_b   = (const float*)d_in[8];
    const float* ln1_g    = (const float*)d_in[9];
    const float* ln1_b    = (const float*)d_in[10];
    const float* ln2_g    = (const float*)d_in[11];
    const float* ln2_b    = (const float*)d_in[12];

    float *ln1, *qkv, *attn, *x1, *ln2, *hbuf, *w1p, *w2p, *w3p, *w4p;
    cudaGetSymbolAddress((void**)&ln1,  g_ln1);
    cudaGetSymbolAddress((void**)&qkv,  g_qkv);
    cudaGetSymbolAddress((void**)&attn, g_attn);
    cudaGetSymbolAddress((void**)&x1,   g_x1);
    cudaGetSymbolAddress((void**)&ln2,  g_ln2);
    cudaGetSymbolAddress((void**)&hbuf, g_hbuf);
    cudaGetSymbolAddress((void**)&w1p,  g_w1p);
    cudaGetSymbolAddress((void**)&w2p,  g_w2p);
    cudaGetSymbolAddress((void**)&w3p,  g_w3p);
    cudaGetSymbolAddress((void**)&w4p,  g_w4p);

    cudaFuncSetAttribute(mma_gemm, cudaFuncAttributeMaxDynamicSharedMemorySize, GEMM_SMEM);
    cudaFuncSetAttribute(attn_mma, cudaFuncAttributeMaxDynamicSharedMemorySize, ATT_SMEM);

    float* outp = (float*)d_out;

    wprep_kernel<<<3072, 256>>>(c_attn_w, w1p, 1024, 3072);
    wprep_kernel<<<1024, 256>>>(c_proj_w, w2p, 1024, 1024);
    wprep_kernel<<<4096, 256>>>(fc_w,     w3p, 1024, 4096);
    wprep_kernel<<<4096, 256>>>(proj_w,   w4p, 4096, 1024);

    // 1. ln1 = LN(x) (packed A)
    ln_kernel<<<MROWS, 256>>>(x, ln1_g, ln1_b, ln1);
    // 2. qkv = ln1 @ c_attn_w + b  (natural, tf32-rounded for attention)
    mma_gemm<<<dim3(24, 64), 256, GEMM_SMEM>>>(
        ln1, w1p, c_attn_b, nullptr, qkv, MROWS, 3072, 1024, 0, 0, 1);
    // 3. attention (mma.sync) -> packed A
    attn_mma<<<dim3(32, 64), 128, ATT_SMEM>>>(qkv, attn);
    // 4. x1 = attn @ c_proj_w + b + x
    mma_gemm<<<dim3(8, 64), 256, GEMM_SMEM>>>(
        attn, w2p, c_proj_b, x, x1, MROWS, 1024, 1024, 0, 0, 0);
    // 5. ln2 = LN(x1) (packed A)
    ln_kernel<<<MROWS, 256>>>(x1, ln2_g, ln2_b, ln2);
    // 6. h = gelu(ln2 @ fc_w + b) (packed out)
    mma_gemm<<<dim3(32, 64), 256, GEMM_SMEM>>>(
        ln2, w3p, fc_b, nullptr, hbuf, MROWS, 4096, 1024, 1, 1, 0);
    // 7. out = h @ proj_w + b + x1
    mma_gemm<<<dim3(8, 64), 256, GEMM_SMEM>>>(
        hbuf, w4p, proj_b, x1, outp, MROWS, 1024, 4096, 0, 0, 0);
}

// round 7
// speedup vs baseline: 4.0469x; 1.0322x over previous
#include <cuda_runtime.h>
#include <math.h>
#include <stdint.h>

// ---------------------------------------------------------------------------
// B=4, T=2048, C=1024, H=16, HS=64. M = 8192.
// GEMMs + attention on mma.sync.m16n8k8 tf32.
// GEMM: 128x128 CTA tile, 128 threads (4 warps, 2x2), warp tile 64x64.
// ---------------------------------------------------------------------------
#define MROWS 8192
#define CDIM  1024

__device__ float g_ln1 [8192u * 1024];   // packed A
__device__ float g_qkv [8192u * 3072];   // natural, tf32-rounded
__device__ float g_attn[8192u * 1024];   // packed A
__device__ float g_x1  [8192u * 1024];   // natural
__device__ float g_ln2 [8192u * 1024];   // packed A
__device__ float g_hbuf[8192u * 4096];   // packed A
__device__ float g_w1p [1024u * 3072];   // packed B
__device__ float g_w2p [1024u * 1024];
__device__ float g_w3p [1024u * 4096];
__device__ float g_w4p [4096u * 1024];

// ---------------- helpers ----------------
__device__ __forceinline__ float tf32r(float x) {
    uint32_t u;
    asm("cvt.rna.tf32.f32 %0, %1;" : "=r"(u) : "f"(x));
    return __uint_as_float(u);
}
__device__ __forceinline__ uint32_t smem_u32(const void* p) {
    uint32_t a;
    asm("{ .reg .u64 t; cvta.to.shared.u64 t, %1; cvt.u32.u64 %0, t; }"
        : "=r"(a) : "l"(p));
    return a;
}
#define CP_ASYNC16(dst, src) \
    asm volatile("cp.async.cg.shared.global [%0], [%1], 16;" :: "r"(dst), "l"(src))
#define CP_COMMIT() asm volatile("cp.async.commit_group;" ::: "memory")
#define CP_WAIT0()  asm volatile("cp.async.wait_group 0;"  ::: "memory")
#define CP_WAIT1()  asm volatile("cp.async.wait_group 1;"  ::: "memory")
#define CP_WAIT2()  asm volatile("cp.async.wait_group 2;"  ::: "memory")

__device__ __forceinline__ void mma_tf32(float c[4], uint32_t a0, uint32_t a1,
                                         uint32_t a2, uint32_t a3,
                                         uint32_t b0, uint32_t b1) {
    asm volatile(
        "mma.sync.aligned.m16n8k8.row.col.f32.tf32.tf32.f32 "
        "{%0,%1,%2,%3}, {%4,%5,%6,%7}, {%8,%9}, {%0,%1,%2,%3};"
        : "+f"(c[0]), "+f"(c[1]), "+f"(c[2]), "+f"(c[3])
        : "r"(a0), "r"(a1), "r"(a2), "r"(a3), "r"(b0), "r"(b1));
}

__device__ __forceinline__ float gelu_f(float x) {
    float x3 = x * x * x;
    return 0.5f * x * (1.0f + tanhf(0.7978845608028654f * (x + 0.044715f * x3)));
}

// Packed-A address (float index) for element (m,k) of an [M,K] A operand.
__device__ __forceinline__ size_t paddrA(int m, int k, int K) {
    const int mb = m >> 7, rm = m & 127;
    const int wm = rm >> 5, mt = (rm >> 4) & 1, lr = rm & 7, ah = (rm >> 3) & 1;
    const int kt = k >> 5, kk = (k >> 3) & 3, lc = k & 3, kh = (k >> 2) & 1;
    const int lane = lr * 4 + lc;
    const int reg  = ah + 2 * kh;
    return ((size_t)mb * (K >> 5) + kt) * 4096 +
           ((((kk * 4 + wm) * 2 + mt) * 32 + lane) * 4 + reg);
}
// Packed-B address (float index) for element (n,k) of W[K,N] viewed as [N,K].
__device__ __forceinline__ size_t paddrB(int n, int k, int K) {
    const int nb = n >> 7, rn = n & 127;
    const int wn = (rn >> 6) & 1, nt = (rn >> 3) & 7, n8 = rn & 7;
    const int kt = k >> 5, kk = (k >> 3) & 3, kh = (k >> 2) & 1;
    const int lane = n8 * 4 + (k & 3);
    return ((size_t)nb * (K >> 5) + kt) * 4096 +
           ((((kk * 2 + wn) * 8 + nt) * 32 + lane) * 2 + kh);
}

// ---------------------------------------------------------------------------
// Weight prep: W[K,N] -> packed B layout, tf32-rounded
// ---------------------------------------------------------------------------
__global__ __launch_bounds__(256) void wprep_kernel(
    const float* __restrict__ W, float* __restrict__ out, int K, int N)
{
    const int idx = blockIdx.x * 256 + threadIdx.x;
    if (idx >= (K >> 2) * N) return;
    const int n = idx % N;
    const int k = (idx / N) << 2;
    #pragma unroll
    for (int i = 0; i < 4; i++)
        out[paddrB(n, k + i, K)] = tf32r(__ldg(&W[(size_t)(k + i) * N + n]));
}

// ---------------------------------------------------------------------------
// LayerNorm -> packed A, tf32-rounded
// ---------------------------------------------------------------------------
__global__ __launch_bounds__(256) void ln_kernel(
    const float* __restrict__ x, const float* __restrict__ g,
    const float* __restrict__ b, float* __restrict__ o)
{
    const int row = blockIdx.x;
    const int tid = threadIdx.x;
    const float4 v = reinterpret_cast<const float4*>(x + (size_t)row * CDIM)[tid];

    float s  = v.x + v.y + v.z + v.w;
    float sq = v.x * v.x + v.y * v.y + v.z * v.z + v.w * v.w;
    #pragma unroll
    for (int off = 16; off > 0; off >>= 1) {
        s  += __shfl_xor_sync(0xffffffffu, s,  off);
        sq += __shfl_xor_sync(0xffffffffu, sq, off);
    }
    __shared__ float shs[8], shq[8];
    const int wid = tid >> 5;
    if ((tid & 31) == 0) { shs[wid] = s; shq[wid] = sq; }
    __syncthreads();
    float ts = 0.f, tq = 0.f;
    #pragma unroll
    for (int w = 0; w < 8; w++) { ts += shs[w]; tq += shq[w]; }

    const float mean = ts * (1.0f / CDIM);
    const float var  = tq * (1.0f / CDIM) - mean * mean;
    const float rstd = rsqrtf(var + 1e-5f);

    const float4 gv = reinterpret_cast<const float4*>(g)[tid];
    const float4 bv = reinterpret_cast<const float4*>(b)[tid];
    const int k = tid << 2;
    o[paddrA(row, k + 0, CDIM)] = tf32r((v.x - mean) * rstd * gv.x + bv.x);
    o[paddrA(row, k + 1, CDIM)] = tf32r((v.y - mean) * rstd * gv.y + bv.y);
    o[paddrA(row, k + 2, CDIM)] = tf32r((v.z - mean) * rstd * gv.z + bv.z);
    o[paddrA(row, k + 3, CDIM)] = tf32r((v.w - mean) * rstd * gv.w + bv.w);
}

// ---------------------------------------------------------------------------
// tf32 mma.sync GEMM, fragment-packed operands.
// 128 threads, 4 warps (2m x 2n), warp tile 64x64, 3-stage cp.async.
// ---------------------------------------------------------------------------
#define GSTG 3
#define STG_FLOATS 8192
#define GEMM_SMEM (GSTG * STG_FLOATS * 4)

__global__ __launch_bounds__(128, 2) void mma_gemm(
    const float* __restrict__ Apk, const float* __restrict__ Bpk,
    const float* __restrict__ bias, const float* __restrict__ resid,
    float* __restrict__ C, int M, int N, int K, int act, int pack_out,
    int round_out)
{
    extern __shared__ float sm[];
    const uint32_t sb = smem_u32(sm);

    const int tid  = threadIdx.x;
    const int wid  = tid >> 5;
    const int lane = tid & 31;
    const int wm = wid & 1;              // m half (64 rows)
    const int wn = wid >> 1;             // n half (64 cols)
    const int bm = blockIdx.y << 7;
    const int bn = blockIdx.x << 7;
    const int lr = lane >> 2;
    const int lc = lane & 3;

    const int nk = K >> 5;
    const char* abase = (const char*)Apk + (size_t)blockIdx.y * nk * 16384;
    const char* bbase = (const char*)Bpk + (size_t)blockIdx.x * nk * 16384;

    float acc[4][8][4];
    #pragma unroll
    for (int at = 0; at < 4; at++)
        #pragma unroll
        for (int nt = 0; nt < 8; nt++)
            #pragma unroll
            for (int j = 0; j < 4; j++) acc[at][nt][j] = 0.f;

    // stage issue: 16 cp.async of 16B per thread (A 16KB + B 16KB)
    #define ISSUE(t) do { \
        if ((t) < nk) { \
            const char* _a = abase + (size_t)(t) * 16384 + tid * 16; \
            const char* _b = bbase + (size_t)(t) * 16384 + tid * 16; \
            const uint32_t _d = sb + ((t) % GSTG) * (STG_FLOATS * 4) + tid * 16; \
            _Pragma("unroll") \
            for (int _i = 0; _i < 8; _i++) { \
                CP_ASYNC16(_d + _i * 2048,         _a + _i * 2048); \
                CP_ASYNC16(_d + 16384 + _i * 2048, _b + _i * 2048); \
            } \
        } \
        CP_COMMIT(); \
    } while (0)

    ISSUE(0);
    ISSUE(1);

    for (int t = 0; t < nk; t++) {
        ISSUE(t + 2);
        CP_WAIT2();
        __syncthreads();

        const float* Ab = sm + (t % GSTG) * STG_FLOATS;
        const float* Bb = Ab + 4096;
        #pragma unroll
        for (int kk = 0; kk < 4; kk++) {
            uint4 a[4];
            #pragma unroll
            for (int at = 0; at < 4; at++)
                a[at] = *reinterpret_cast<const uint4*>(
                    Ab + ((kk * 4 + wm * 2 + (at >> 1)) * 2 + (at & 1)) * 128 + lane * 4);
            const float* bq = Bb + (kk * 2 + wn) * 512 + lane * 2;
            #pragma unroll
            for (int nt = 0; nt < 8; nt++) {
                const uint2 bv = *reinterpret_cast<const uint2*>(bq + nt * 64);
                #pragma unroll
                for (int at = 0; at < 4; at++)
                    mma_tf32(acc[at][nt], a[at].x, a[at].y, a[at].z, a[at].w,
                             bv.x, bv.y);
            }
        }
        __syncthreads();
    }

    // epilogue: rows = bm + wm*64 + (at>>1)*32 + (at&1)*16 + {lr, lr+8}
    #pragma unroll
    for (int at = 0; at < 4; at++) {
        const int r0 = bm + wm * 64 + (at >> 1) * 32 + (at & 1) * 16 + lr;
        const int r1 = r0 + 8;
        #pragma unroll
        for (int nt = 0; nt < 8; nt++) {
            const int col = bn + wn * 64 + nt * 8 + lc * 2;
            const float bb0 = __ldg(&bias[col]);
            const float bb1 = __ldg(&bias[col + 1]);
            float v0 = acc[at][nt][0] + bb0;
            float v1 = acc[at][nt][1] + bb1;
            float v2 = acc[at][nt][2] + bb0;
            float v3 = acc[at][nt][3] + bb1;
            if (act) {
                v0 = gelu_f(v0); v1 = gelu_f(v1);
                v2 = gelu_f(v2); v3 = gelu_f(v3);
            }
            if (pack_out) {
                C[paddrA(r0, col,     N)] = tf32r(v0);
                C[paddrA(r0, col + 1, N)] = tf32r(v1);
                C[paddrA(r1, col,     N)] = tf32r(v2);
                C[paddrA(r1, col + 1, N)] = tf32r(v3);
            } else {
                const size_t o0 = (size_t)r0 * N + col;
                const size_t o1 = (size_t)r1 * N + col;
                if (resid) {
                    const float2 q0 = *reinterpret_cast<const float2*>(&resid[o0]);
                    const float2 q1 = *reinterpret_cast<const float2*>(&resid[o1]);
                    v0 += q0.x; v1 += q0.y; v2 += q1.x; v3 += q1.y;
                }
                if (round_out) {
                    v0 = tf32r(v0); v1 = tf32r(v1); v2 = tf32r(v2); v3 = tf32r(v3);
                }
                *reinterpret_cast<float2*>(&C[o0]) = make_float2(v0, v1);
                *reinterpret_cast<float2*>(&C[o1]) = make_float2(v2, v3);
            }
        }
    }
}

// ---------------------------------------------------------------------------
// Flash attention on mma.sync tf32, causal (unchanged from R6).
// ---------------------------------------------------------------------------
#define AST_K 68
#define AST_V 72
#define ATT_QOFF 0
#define ATT_KOFF(b) (4352 + (b) * 4352)
#define ATT_VOFF(b) (13056 + (b) * 4608)
#define ATT_SMEM (22272 * 4)

__global__ __launch_bounds__(128, 2) void attn_mma(
    const float* __restrict__ qkv, float* __restrict__ out)
{
    extern __shared__ float sm[];
    const uint32_t sb = smem_u32(sm);
    const int tid = threadIdx.x;
    const int w = tid >> 5, lane = tid & 31;
    const int lr = lane >> 2, lc = lane & 3;
    const int qt = blockIdx.x, bh = blockIdx.y;
    const int b = bh >> 4, h = bh & 15;
    const int q0 = qt * 64;
    const float* basep = qkv + (size_t)b * 2048 * 3072 + (size_t)h * 64;

    #pragma unroll
    for (int i = 0; i < 8; i++) {
        const int idx = tid + i * 128, row = idx >> 4, ch = idx & 15;
        CP_ASYNC16(sb + (uint32_t)(ATT_QOFF + row * AST_K + ch * 4) * 4,
                   basep + (size_t)(q0 + row) * 3072 + ch * 4);
    }
    CP_COMMIT();

    #define ISSUE_KV(kt_, bb) do { \
        const float* _k = basep + (size_t)((kt_) * 64) * 3072 + 1024; \
        _Pragma("unroll") \
        for (int _i = 0; _i < 8; _i++) { \
            const int _idx = tid + _i * 128, _r = _idx >> 4, _c = _idx & 15; \
            CP_ASYNC16(sb + (uint32_t)(ATT_KOFF(bb) + _r * AST_K + _c * 4) * 4, \
                       _k + (size_t)_r * 3072 + _c * 4); \
            CP_ASYNC16(sb + (uint32_t)(ATT_VOFF(bb) + _r * AST_V + _c * 4) * 4, \
                       _k + 1024 + (size_t)_r * 3072 + _c * 4); \
        } \
        CP_COMMIT(); \
    } while (0)

    ISSUE_KV(0, 0);

    CP_WAIT1();
    __syncthreads();

    float qa[8][4];
    {
        const float* Qs = sm + ATT_QOFF;
        const int r0 = w * 16 + lr;
        #pragma unroll
        for (int kk = 0; kk < 8; kk++) {
            qa[kk][0] = 0.125f * Qs[r0 * AST_K + kk * 8 + lc];
            qa[kk][1] = 0.125f * Qs[(r0 + 8) * AST_K + kk * 8 + lc];
            qa[kk][2] = 0.125f * Qs[r0 * AST_K + kk * 8 + lc + 4];
            qa[kk][3] = 0.125f * Qs[(r0 + 8) * AST_K + kk * 8 + lc + 4];
        }
    }
    __syncthreads();

    float* Pw = sm + ATT_QOFF + w * 1024;

    float m0 = -1e30f, m1 = -1e30f, l0 = 0.f, l1 = 0.f;
    float o[4][2][4];
    #pragma unroll
    for (int mt = 0; mt < 4; mt++)
        #pragma unroll
        for (int nt = 0; nt < 2; nt++)
            #pragma unroll
            for (int j = 0; j < 4; j++) o[mt][nt][j] = 0.f;

    for (int kt = 0; kt <= qt; kt++) {
        const int buf = kt & 1;
        if (kt < qt) { ISSUE_KV(kt + 1, buf ^ 1); CP_WAIT1(); }
        else         { CP_WAIT0(); }
        __syncthreads();

        const float* Ks = sm + ATT_KOFF(buf);
        const float* Vs = sm + ATT_VOFF(buf);

        float s[8][4];
        #pragma unroll
        for (int nt = 0; nt < 8; nt++)
            #pragma unroll
            for (int j = 0; j < 4; j++) s[nt][j] = 0.f;

        #pragma unroll
        for (int kk = 0; kk < 8; kk++) {
            const uint32_t a0 = __float_as_uint(qa[kk][0]);
            const uint32_t a1 = __float_as_uint(qa[kk][1]);
            const uint32_t a2 = __float_as_uint(qa[kk][2]);
            const uint32_t a3 = __float_as_uint(qa[kk][3]);
            #pragma unroll
            for (int nt = 0; nt < 8; nt++) {
                const uint32_t b0 = __float_as_uint(Ks[(nt * 8 + lr) * AST_K + kk * 8 + lc]);
                const uint32_t b1 = __float_as_uint(Ks[(nt * 8 + lr) * AST_K + kk * 8 + lc + 4]);
                mma_tf32(s[nt], a0, a1, a2, a3, b0, b1);
            }
        }

        if (kt == qt) {
            const int r0l = w * 16 + lr;
            #pragma unroll
            for (int nt = 0; nt < 8; nt++) {
                const int c = nt * 8 + 2 * lc;
                if (c     > r0l)     s[nt][0] = -1e30f;
                if (c + 1 > r0l)     s[nt][1] = -1e30f;
                if (c     > r0l + 8) s[nt][2] = -1e30f;
                if (c + 1 > r0l + 8) s[nt][3] = -1e30f;
            }
        }

        float mx0 = -1e30f, mx1 = -1e30f;
        #pragma unroll
        for (int nt = 0; nt < 8; nt++) {
            mx0 = fmaxf(mx0, fmaxf(s[nt][0], s[nt][1]));
            mx1 = fmaxf(mx1, fmaxf(s[nt][2], s[nt][3]));
        }
        mx0 = fmaxf(mx0, __shfl_xor_sync(0xffffffffu, mx0, 1));
        mx0 = fmaxf(mx0, __shfl_xor_sync(0xffffffffu, mx0, 2));
        mx1 = fmaxf(mx1, __shfl_xor_sync(0xffffffffu, mx1, 1));
        mx1 = fmaxf(mx1, __shfl_xor_sync(0xffffffffu, mx1, 2));

        const float mn0 = fmaxf(m0, mx0), mn1 = fmaxf(m1, mx1);
        const float al0 = __expf(m0 - mn0), al1 = __expf(m1 - mn1);
        m0 = mn0; m1 = mn1;

        float sum0 = 0.f, sum1 = 0.f;
        #pragma unroll
        for (int nt = 0; nt < 8; nt++) {
            s[nt][0] = __expf(s[nt][0] - mn0); sum0 += s[nt][0];
            s[nt][1] = __expf(s[nt][1] - mn0); sum0 += s[nt][1];
            s[nt][2] = __expf(s[nt][2] - mn1); sum1 += s[nt][2];
            s[nt][3] = __expf(s[nt][3] - mn1); sum1 += s[nt][3];
        }
        sum0 += __shfl_xor_sync(0xffffffffu, sum0, 1);
        sum0 += __shfl_xor_sync(0xffffffffu, sum0, 2);
        sum1 += __shfl_xor_sync(0xffffffffu, sum1, 1);
        sum1 += __shfl_xor_sync(0xffffffffu, sum1, 2);
        l0 = l0 * al0 + sum0;
        l1 = l1 * al1 + sum1;

        const float zA0  = __shfl_sync(0xffffffffu, al0, 8 * lc);
        const float zA0b = __shfl_sync(0xffffffffu, al0, 8 * lc + 4);
        const float zA1  = __shfl_sync(0xffffffffu, al1, 8 * lc);
        const float zA1b = __shfl_sync(0xffffffffu, al1, 8 * lc + 4);
        #pragma unroll
        for (int mt = 0; mt < 4; mt++) {
            o[mt][0][0] *= zA0;  o[mt][0][1] *= zA0b;
            o[mt][0][2] *= zA0;  o[mt][0][3] *= zA0b;
            o[mt][1][0] *= zA1;  o[mt][1][1] *= zA1b;
            o[mt][1][2] *= zA1;  o[mt][1][3] *= zA1b;
        }

        __syncwarp();
        {
            const int c0c = 2 * lc, c1c = 2 * lc + 1;
            const int ln0 = lr * 4 + (c0c & 3), rg0 = (c0c & 4) >> 2;
            const int ln1 = lr * 4 + (c1c & 3), rg1 = (c1c & 4) >> 2;
            #pragma unroll
            for (int nt = 0; nt < 8; nt++) {
                Pw[(nt * 2 + 0) * 64 + ln0 * 2 + rg0] = tf32r(s[nt][0]);
                Pw[(nt * 2 + 0) * 64 + ln1 * 2 + rg1] = tf32r(s[nt][1]);
                Pw[(nt * 2 + 1) * 64 + ln0 * 2 + rg0] = tf32r(s[nt][2]);
                Pw[(nt * 2 + 1) * 64 + ln1 * 2 + rg1] = tf32r(s[nt][3]);
            }
        }
        __syncwarp();

        #pragma unroll
        for (int kk2 = 0; kk2 < 8; kk2++) {
            const uint2 bp0 = *reinterpret_cast<const uint2*>(Pw + (kk2 * 2 + 0) * 64 + lane * 2);
            const uint2 bp1 = *reinterpret_cast<const uint2*>(Pw + (kk2 * 2 + 1) * 64 + lane * 2);
            #pragma unroll
            for (int mt = 0; mt < 4; mt++) {
                const uint32_t a0 = __float_as_uint(Vs[(kk2 * 8 + lc) * AST_V + mt * 16 + lr]);
                const uint32_t a1 = __float_as_uint(Vs[(kk2 * 8 + lc) * AST_V + mt * 16 + lr + 8]);
                const uint32_t a2 = __float_as_uint(Vs[(kk2 * 8 + lc + 4) * AST_V + mt * 16 + lr]);
                const uint32_t a3 = __float_as_uint(Vs[(kk2 * 8 + lc + 4) * AST_V + mt * 16 + lr + 8]);
                mma_tf32(o[mt][0], a0, a1, a2, a3, bp0.x, bp0.y);
                mma_tf32(o[mt][1], a0, a1, a2, a3, bp1.x, bp1.y);
            }
        }
    }

    const float i0 = 1.0f / l0, i1 = 1.0f / l1;
    const float zI0  = __shfl_sync(0xffffffffu, i0, 8 * lc);
    const float zI0b = __shfl_sync(0xffffffffu, i0, 8 * lc + 4);
    const float zI1  = __shfl_sync(0xffffffffu, i1, 8 * lc);
    const float zI1b = __shfl_sync(0xffffffffu, i1, 8 * lc + 4);

    #pragma unroll
    for (int mt = 0; mt < 4; mt++) {
        const int d0 = h * 64 + mt * 16 + lr;
        const int d1 = d0 + 8;
        #pragma unroll
        for (int ntile = 0; ntile < 2; ntile++) {
            const int qr = b * 2048 + q0 + w * 16 + ntile * 8 + 2 * lc;
            const float sc0 = ntile ? zI1 : zI0;
            const float sc1 = ntile ? zI1b : zI0b;
            out[paddrA(qr,     d0, CDIM)] = tf32r(o[mt][ntile][0] * sc0);
            out[paddrA(qr + 1, d0, CDIM)] = tf32r(o[mt][ntile][1] * sc1);
            out[paddrA(qr,     d1, CDIM)] = tf32r(o[mt][ntile][2] * sc0);
            out[paddrA(qr + 1, d1, CDIM)] = tf32r(o[mt][ntile][3] * sc1);
        }
    }
}

// ---------------------------------------------------------------------------
// Launch
// ---------------------------------------------------------------------------
extern "C" void kernel_launch(void* const* d_in, const int* in_sizes, int n_in,
                              void* d_out, int out_size)
{
    const float* x        = (const float*)d_in[0];
    const float* c_attn_w = (const float*)d_in[1];
    const float* c_attn_b = (const float*)d_in[2];
    const float* c_proj_w = (const float*)d_in[3];
    const float* c_proj_b = (const float*)d_in[4];
    const float* fc_w     = (const float*)d_in[5];
    const float* fc_b     = (const float*)d_in[6];
    const float* proj_w   = (const float*)d_in[7];
    const float* proj_b   = (const float*)d_in[8];
    const float* ln1_g    = (const float*)d_in[9];
    const float* ln1_b    = (const float*)d_in[10];
    const float* ln2_g    = (const float*)d_in[11];
    const float* ln2_b    = (const float*)d_in[12];

    float *ln1, *qkv, *attn, *x1, *ln2, *hbuf, *w1p, *w2p, *w3p, *w4p;
    cudaGetSymbolAddress((void**)&ln1,  g_ln1);
    cudaGetSymbolAddress((void**)&qkv,  g_qkv);
    cudaGetSymbolAddress((void**)&attn, g_attn);
    cudaGetSymbolAddress((void**)&x1,   g_x1);
    cudaGetSymbolAddress((void**)&ln2,  g_ln2);
    cudaGetSymbolAddress((void**)&hbuf, g_hbuf);
    cudaGetSymbolAddress((void**)&w1p,  g_w1p);
    cudaGetSymbolAddress((void**)&w2p,  g_w2p);
    cudaGetSymbolAddress((void**)&w3p,  g_w3p);
    cudaGetSymbolAddress((void**)&w4p,  g_w4p);

    cudaFuncSetAttribute(mma_gemm, cudaFuncAttributeMaxDynamicSharedMemorySize, GEMM_SMEM);
    cudaFuncSetAttribute(attn_mma, cudaFuncAttributeMaxDynamicSharedMemorySize, ATT_SMEM);

    float* outp = (float*)d_out;

    wprep_kernel<<<3072, 256>>>(c_attn_w, w1p, 1024, 3072);
    wprep_kernel<<<1024, 256>>>(c_proj_w, w2p, 1024, 1024);
    wprep_kernel<<<4096, 256>>>(fc_w,     w3p, 1024, 4096);
    wprep_kernel<<<4096, 256>>>(proj_w,   w4p, 4096, 1024);

    // 1. ln1 = LN(x) (packed A)
    ln_kernel<<<MROWS, 256>>>(x, ln1_g, ln1_b, ln1);
    // 2. qkv = ln1 @ c_attn_w + b  (natural, tf32-rounded for attention)
    mma_gemm<<<dim3(24, 64), 128, GEMM_SMEM>>>(
        ln1, w1p, c_attn_b, nullptr, qkv, MROWS, 3072, 1024, 0, 0, 1);
    // 3. attention (mma.sync) -> packed A
    attn_mma<<<dim3(32, 64), 128, ATT_SMEM>>>(qkv, attn);
    // 4. x1 = attn @ c_proj_w + b + x
    mma_gemm<<<dim3(8, 64), 128, GEMM_SMEM>>>(
        attn, w2p, c_proj_b, x, x1, MROWS, 1024, 1024, 0, 0, 0);
    // 5. ln2 = LN(x1) (packed A)
    ln_kernel<<<MROWS, 256>>>(x1, ln2_g, ln2_b, ln2);
    // 6. h = gelu(ln2 @ fc_w + b) (packed out)
    mma_gemm<<<dim3(32, 64), 128, GEMM_SMEM>>>(
        ln2, w3p, fc_b, nullptr, hbuf, MROWS, 4096, 1024, 1, 1, 0);
    // 7. out = h @ proj_w + b + x1
    mma_gemm<<<dim3(8, 64), 128, GEMM_SMEM>>>(
        hbuf, w4p, proj_b, x1, outp, MROWS, 1024, 4096, 0, 0, 0);
}

// round 9
// speedup vs baseline: 4.1621x; 1.0285x over previous
#include <cuda_runtime.h>
#include <math.h>
#include <stdint.h>

// ---------------------------------------------------------------------------
// B=4, T=2048, C=1024, H=16, HS=64. M = 8192.
// GEMMs + attention on mma.sync.m16n8k8 tf32, fragment-packed operands.
// All packed-layout producers emit full 16B granules.
// R9: fixed cross-warp race in attention double-buffering (missing trailing
// __syncthreads before re-issuing cp.async into the buffer read last iter).
// ---------------------------------------------------------------------------
#define MROWS 8192
#define CDIM  1024

__device__ float g_ln1 [8192u * 1024];   // packed A
__device__ float g_qkv [8192u * 3072];   // natural, tf32-rounded
__device__ float g_attn[8192u * 1024];   // packed A
__device__ float g_x1  [8192u * 1024];   // natural
__device__ float g_ln2 [8192u * 1024];   // packed A
__device__ float g_hbuf[8192u * 4096];   // packed A
__device__ float g_w1p [1024u * 3072];   // packed B
__device__ float g_w2p [1024u * 1024];
__device__ float g_w3p [1024u * 4096];
__device__ float g_w4p [4096u * 1024];

// ---------------- helpers ----------------
__device__ __forceinline__ float tf32r(float x) {
    uint32_t u;
    asm("cvt.rna.tf32.f32 %0, %1;" : "=r"(u) : "f"(x));
    return __uint_as_float(u);
}
__device__ __forceinline__ uint32_t smem_u32(const void* p) {
    uint32_t a;
    asm("{ .reg .u64 t; cvta.to.shared.u64 t, %1; cvt.u32.u64 %0, t; }"
        : "=r"(a) : "l"(p));
    return a;
}
#define CP_ASYNC16(dst, src) \
    asm volatile("cp.async.cg.shared.global [%0], [%1], 16;" :: "r"(dst), "l"(src))
#define CP_COMMIT() asm volatile("cp.async.commit_group;" ::: "memory")
#define CP_WAIT0()  asm volatile("cp.async.wait_group 0;"  ::: "memory")
#define CP_WAIT1()  asm volatile("cp.async.wait_group 1;"  ::: "memory")
#define CP_WAIT2()  asm volatile("cp.async.wait_group 2;"  ::: "memory")

__device__ __forceinline__ void mma_tf32(float c[4], uint32_t a0, uint32_t a1,
                                         uint32_t a2, uint32_t a3,
                                         uint32_t b0, uint32_t b1) {
    asm volatile(
        "mma.sync.aligned.m16n8k8.row.col.f32.tf32.tf32.f32 "
        "{%0,%1,%2,%3}, {%4,%5,%6,%7}, {%8,%9}, {%0,%1,%2,%3};"
        : "+f"(c[0]), "+f"(c[1]), "+f"(c[2]), "+f"(c[3])
        : "r"(a0), "r"(a1), "r"(a2), "r"(a3), "r"(b0), "r"(b1));
}

__device__ __forceinline__ float gelu_f(float x) {
    float x3 = x * x * x;
    return 0.5f * x * (1.0f + tanhf(0.7978845608028654f * (x + 0.044715f * x3)));
}

// Packed-A address (float index) for element (m,k) of an [M,K] A operand.
__device__ __forceinline__ size_t paddrA(int m, int k, int K) {
    const int mb = m >> 7, rm = m & 127;
    const int wm = rm >> 5, mt = (rm >> 4) & 1, lr = rm & 7, ah = (rm >> 3) & 1;
    const int kt = k >> 5, kk = (k >> 3) & 3, lc = k & 3, kh = (k >> 2) & 1;
    const int lane = lr * 4 + lc;
    const int reg  = ah + 2 * kh;
    return ((size_t)mb * (K >> 5) + kt) * 4096 +
           ((((kk * 4 + wm) * 2 + mt) * 32 + lane) * 4 + reg);
}
// Packed-B address (float index) for element (n,k) of W[K,N] viewed as [N,K].
__device__ __forceinline__ size_t paddrB(int n, int k, int K) {
    const int nb = n >> 7, rn = n & 127;
    const int wn = (rn >> 6) & 1, nt = (rn >> 3) & 7, n8 = rn & 7;
    const int kt = k >> 5, kk = (k >> 3) & 3, kh = (k >> 2) & 1;
    const int lane = n8 * 4 + (k & 3);
    return ((size_t)nb * (K >> 5) + kt) * 4096 +
           ((((kk * 2 + wn) * 8 + nt) * 32 + lane) * 2 + kh);
}

// ---------------------------------------------------------------------------
// Weight prep, all 4 weights in one launch. Thread handles (n, kb..kb+7)
// -> one contiguous 32B store.
// ---------------------------------------------------------------------------
__global__ __launch_bounds__(256) void wprep4_kernel(
    const float* __restrict__ w1, const float* __restrict__ w2,
    const float* __restrict__ w3, const float* __restrict__ w4,
    float* __restrict__ o1, float* __restrict__ o2,
    float* __restrict__ o3, float* __restrict__ o4)
{
    const int bid = blockIdx.x;
    const float* W; float* O; int K, N, base;
    if (bid < 1536)      { W = w1; O = o1; K = 1024; N = 3072; base = 0; }
    else if (bid < 2048) { W = w2; O = o2; K = 1024; N = 1024; base = 1536; }
    else if (bid < 4096) { W = w3; O = o3; K = 1024; N = 4096; base = 2048; }
    else                 { W = w4; O = o4; K = 4096; N = 1024; base = 4096; }

    const int idx = (bid - base) * 256 + threadIdx.x;
    const int n  = idx % N;
    const int kb = (idx / N) * 8;

    float v[8];
    #pragma unroll
    for (int i = 0; i < 8; i++)
        v[i] = tf32r(__ldg(&W[(size_t)(kb + i) * N + n]));

    float4* p = reinterpret_cast<float4*>(&O[paddrB(n, kb, K)]);
    p[0] = make_float4(v[0], v[4], v[1], v[5]);
    p[1] = make_float4(v[2], v[6], v[3], v[7]);
}

// ---------------------------------------------------------------------------
// LayerNorm, row-pair (m, m+8) per block -> full float4 granule stores.
// ---------------------------------------------------------------------------
__global__ __launch_bounds__(256) void ln_kernel(
    const float* __restrict__ x, const float* __restrict__ g,
    const float* __restrict__ b, float* __restrict__ o)
{
    const int p  = blockIdx.x;
    const int m0 = (p >> 3) * 16 + (p & 7);
    const int m1 = m0 + 8;
    const int tid = threadIdx.x;
    const int k0 = ((tid >> 2) << 3) + (tid & 3);
    const int k1 = k0 + 512;

    const float* x0 = x + (size_t)m0 * CDIM;
    const float* x1 = x + (size_t)m1 * CDIM;
    const float a00 = x0[k0], a01 = x0[k0 + 4], a02 = x0[k1], a03 = x0[k1 + 4];
    const float a10 = x1[k0], a11 = x1[k0 + 4], a12 = x1[k1], a13 = x1[k1 + 4];

    float s0 = a00 + a01 + a02 + a03;
    float q0 = a00 * a00 + a01 * a01 + a02 * a02 + a03 * a03;
    float s1 = a10 + a11 + a12 + a13;
    float q1 = a10 * a10 + a11 * a11 + a12 * a12 + a13 * a13;

    #pragma unroll
    for (int off = 16; off > 0; off >>= 1) {
        s0 += __shfl_xor_sync(0xffffffffu, s0, off);
        q0 += __shfl_xor_sync(0xffffffffu, q0, off);
        s1 += __shfl_xor_sync(0xffffffffu, s1, off);
        q1 += __shfl_xor_sync(0xffffffffu, q1, off);
    }
    __shared__ float red[4][8];
    const int wid = tid >> 5;
    if ((tid & 31) == 0) {
        red[0][wid] = s0; red[1][wid] = q0; red[2][wid] = s1; red[3][wid] = q1;
    }
    __syncthreads();
    float ts0 = 0.f, tq0 = 0.f, ts1 = 0.f, tq1 = 0.f;
    #pragma unroll
    for (int w = 0; w < 8; w++) {
        ts0 += red[0][w]; tq0 += red[1][w]; ts1 += red[2][w]; tq1 += red[3][w];
    }

    const float mu0 = ts0 * (1.0f / CDIM);
    const float mu1 = ts1 * (1.0f / CDIM);
    const float r0 = rsqrtf(tq0 * (1.0f / CDIM) - mu0 * mu0 + 1e-5f);
    const float r1 = rsqrtf(tq1 * (1.0f / CDIM) - mu1 * mu1 + 1e-5f);

    #pragma unroll
    for (int gi = 0; gi < 2; gi++) {
        const int k = gi ? k1 : k0;
        const float ga = __ldg(&g[k]), gb = __ldg(&g[k + 4]);
        const float ba = __ldg(&b[k]), bb = __ldg(&b[k + 4]);
        const float xa0 = gi ? a02 : a00, xa1 = gi ? a03 : a01;
        const float xb0 = gi ? a12 : a10, xb1 = gi ? a13 : a11;
        *reinterpret_cast<float4*>(&o[paddrA(m0, k, CDIM)]) = make_float4(
            tf32r((xa0 - mu0) * r0 * ga + ba),
            tf32r((xb0 - mu1) * r1 * ga + ba),
            tf32r((xa1 - mu0) * r0 * gb + bb),
            tf32r((xb1 - mu1) * r1 * gb + bb));
    }
}

// ---------------------------------------------------------------------------
// tf32 mma.sync GEMM, fragment-packed operands.
// 128 threads, 4 warps (2m x 2n), warp tile 64x64, 3-stage cp.async.
// ---------------------------------------------------------------------------
#define GSTG 3
#define STG_FLOATS 8192
#define GEMM_SMEM (GSTG * STG_FLOATS * 4)

__global__ __launch_bounds__(128, 2) void mma_gemm(
    const float* __restrict__ Apk, const float* __restrict__ Bpk,
    const float* __restrict__ bias, const float* __restrict__ resid,
    float* __restrict__ C, int M, int N, int K, int act, int pack_out,
    int round_out)
{
    extern __shared__ float sm[];
    const uint32_t sb = smem_u32(sm);

    const int tid  = threadIdx.x;
    const int wid  = tid >> 5;
    const int lane = tid & 31;
    const int wm = wid & 1;
    const int wn = wid >> 1;
    const int bm = blockIdx.y << 7;
    const int bn = blockIdx.x << 7;
    const int lr = lane >> 2;
    const int lc = lane & 3;

    const int nk = K >> 5;
    const char* abase = (const char*)Apk + (size_t)blockIdx.y * nk * 16384;
    const char* bbase = (const char*)Bpk + (size_t)blockIdx.x * nk * 16384;

    float acc[4][8][4];
    #pragma unroll
    for (int at = 0; at < 4; at++)
        #pragma unroll
        for (int nt = 0; nt < 8; nt++)
            #pragma unroll
            for (int j = 0; j < 4; j++) acc[at][nt][j] = 0.f;

    #define ISSUE(t) do { \
        if ((t) < nk) { \
            const char* _a = abase + (size_t)(t) * 16384 + tid * 16; \
            const char* _b = bbase + (size_t)(t) * 16384 + tid * 16; \
            const uint32_t _d = sb + ((t) % GSTG) * (STG_FLOATS * 4) + tid * 16; \
            _Pragma("unroll") \
            for (int _i = 0; _i < 8; _i++) { \
                CP_ASYNC16(_d + _i * 2048,         _a + _i * 2048); \
                CP_ASYNC16(_d + 16384 + _i * 2048, _b + _i * 2048); \
            } \
        } \
        CP_COMMIT(); \
    } while (0)

    ISSUE(0);
    ISSUE(1);

    for (int t = 0; t < nk; t++) {
        ISSUE(t + 2);
        CP_WAIT2();
        __syncthreads();

        const float* Ab = sm + (t % GSTG) * STG_FLOATS;
        const float* Bb = Ab + 4096;
        #pragma unroll
        for (int kk = 0; kk < 4; kk++) {
            uint4 a[4];
            #pragma unroll
            for (int at = 0; at < 4; at++)
                a[at] = *reinterpret_cast<const uint4*>(
                    Ab + ((kk * 4 + wm * 2 + (at >> 1)) * 2 + (at & 1)) * 128 + lane * 4);
            const float* bq = Bb + (kk * 2 + wn) * 512 + lane * 2;
            #pragma unroll
            for (int nt = 0; nt < 8; nt++) {
                const uint2 bv = *reinterpret_cast<const uint2*>(bq + nt * 64);
                #pragma unroll
                for (int at = 0; at < 4; at++)
                    mma_tf32(acc[at][nt], a[at].x, a[at].y, a[at].z, a[at].w,
                             bv.x, bv.y);
            }
        }
        __syncthreads();
    }

    // epilogue
    #pragma unroll
    for (int at = 0; at < 4; at++) {
        const int r0 = bm + wm * 64 + (at >> 1) * 32 + (at & 1) * 16 + lr;
        const int r1 = r0 + 8;
        #pragma unroll
        for (int nt = 0; nt < 8; nt++) {
            const int col = bn + wn * 64 + nt * 8 + lc * 2;
            const float bb0 = __ldg(&bias[col]);
            const float bb1 = __ldg(&bias[col + 1]);
            float v0 = acc[at][nt][0] + bb0;
            float v1 = acc[at][nt][1] + bb1;
            float v2 = acc[at][nt][2] + bb0;
            float v3 = acc[at][nt][3] + bb1;
            if (act) {
                v0 = gelu_f(v0); v1 = gelu_f(v1);
                v2 = gelu_f(v2); v3 = gelu_f(v3);
            }
            if (pack_out) {
                const float u0 = __shfl_xor_sync(0xffffffffu, v0, 2);
                const float u1 = __shfl_xor_sync(0xffffffffu, v1, 2);
                const float u2 = __shfl_xor_sync(0xffffffffu, v2, 2);
                const float u3 = __shfl_xor_sync(0xffffffffu, v3, 2);
                if (lc < 2) {
                    *reinterpret_cast<float4*>(&C[paddrA(r0, col, N)]) =
                        make_float4(tf32r(v0), tf32r(v2), tf32r(u0), tf32r(u2));
                } else {
                    const int colo = col - 3;
                    *reinterpret_cast<float4*>(&C[paddrA(r0, colo, N)]) =
                        make_float4(tf32r(u1), tf32r(u3), tf32r(v1), tf32r(v3));
                }
            } else {
                const size_t o0 = (size_t)r0 * N + col;
                const size_t o1 = (size_t)r1 * N + col;
                if (resid) {
                    const float2 q0 = *reinterpret_cast<const float2*>(&resid[o0]);
                    const float2 q1 = *reinterpret_cast<const float2*>(&resid[o1]);
                    v0 += q0.x; v1 += q0.y; v2 += q1.x; v3 += q1.y;
                }
                if (round_out) {
                    v0 = tf32r(v0); v1 = tf32r(v1); v2 = tf32r(v2); v3 = tf32r(v3);
                }
                *reinterpret_cast<float2*>(&C[o0]) = make_float2(v0, v1);
                *reinterpret_cast<float2*>(&C[o1]) = make_float2(v2, v3);
            }
        }
    }
}

// ---------------------------------------------------------------------------
// Flash attention on mma.sync tf32, causal. Output: full-granule packed A.
// Race-fixed: trailing __syncthreads each iteration so no warp issues
// cp.async into a buffer another warp is still reading.
// ---------------------------------------------------------------------------
#define AST_K 68
#define AST_V 72
#define ATT_QOFF 0
#define ATT_KOFF(b) (4352 + (b) * 4352)
#define ATT_VOFF(b) (13056 + (b) * 4608)
#define ATT_SMEM (22272 * 4)

__global__ __launch_bounds__(128, 2) void attn_mma(
    const float* __restrict__ qkv, float* __restrict__ out)
{
    extern __shared__ float sm[];
    const uint32_t sb = smem_u32(sm);
    const int tid = threadIdx.x;
    const int w = tid >> 5, lane = tid & 31;
    const int lr = lane >> 2, lc = lane & 3;
    const int qt = blockIdx.x, bh = blockIdx.y;
    const int b = bh >> 4, h = bh & 15;
    const int q0 = qt * 64;
    const float* basep = qkv + (size_t)b * 2048 * 3072 + (size_t)h * 64;

    #pragma unroll
    for (int i = 0; i < 8; i++) {
        const int idx = tid + i * 128, row = idx >> 4, ch = idx & 15;
        CP_ASYNC16(sb + (uint32_t)(ATT_QOFF + row * AST_K + ch * 4) * 4,
                   basep + (size_t)(q0 + row) * 3072 + ch * 4);
    }
    CP_COMMIT();

    #define ISSUE_KV(kt_, bb) do { \
        const float* _k = basep + (size_t)((kt_) * 64) * 3072 + 1024; \
        _Pragma("unroll") \
        for (int _i = 0; _i < 8; _i++) { \
            const int _idx = tid + _i * 128, _r = _idx >> 4, _c = _idx & 15; \
            CP_ASYNC16(sb + (uint32_t)(ATT_KOFF(bb) + _r * AST_K + _c * 4) * 4, \
                       _k + (size_t)_r * 3072 + _c * 4); \
            CP_ASYNC16(sb + (uint32_t)(ATT_VOFF(bb) + _r * AST_V + _c * 4) * 4, \
                       _k + 1024 + (size_t)_r * 3072 + _c * 4); \
        } \
        CP_COMMIT(); \
    } while (0)

    ISSUE_KV(0, 0);

    CP_WAIT1();
    __syncthreads();

    float qa[8][4];
    {
        const float* Qs = sm + ATT_QOFF;
        const int r0 = w * 16 + lr;
        #pragma unroll
        for (int kk = 0; kk < 8; kk++) {
            qa[kk][0] = 0.125f * Qs[r0 * AST_K + kk * 8 + lc];
            qa[kk][1] = 0.125f * Qs[(r0 + 8) * AST_K + kk * 8 + lc];
            qa[kk][2] = 0.125f * Qs[r0 * AST_K + kk * 8 + lc + 4];
            qa[kk][3] = 0.125f * Qs[(r0 + 8) * AST_K + kk * 8 + lc + 4];
        }
    }
    __syncthreads();

    float* Pw = sm + ATT_QOFF + w * 1024;

    float m0 = -1e30f, m1 = -1e30f, l0 = 0.f, l1 = 0.f;
    float o[4][2][4];
    #pragma unroll
    for (int mt = 0; mt < 4; mt++)
        #pragma unroll
        for (int nt = 0; nt < 2; nt++)
            #pragma unroll
            for (int j = 0; j < 4; j++) o[mt][nt][j] = 0.f;

    for (int kt = 0; kt <= qt; kt++) {
        const int buf = kt & 1;
        if (kt < qt) { ISSUE_KV(kt + 1, buf ^ 1); CP_WAIT1(); }
        else         { CP_WAIT0(); }
        __syncthreads();

        const float* Ks = sm + ATT_KOFF(buf);
        const float* Vs = sm + ATT_VOFF(buf);

        float s[8][4];
        #pragma unroll
        for (int nt = 0; nt < 8; nt++)
            #pragma unroll
            for (int j = 0; j < 4; j++) s[nt][j] = 0.f;

        #pragma unroll
        for (int kk = 0; kk < 8; kk++) {
            const uint32_t a0 = __float_as_uint(qa[kk][0]);
            const uint32_t a1 = __float_as_uint(qa[kk][1]);
            const uint32_t a2 = __float_as_uint(qa[kk][2]);
            const uint32_t a3 = __float_as_uint(qa[kk][3]);
            #pragma unroll
            for (int nt = 0; nt < 8; nt++) {
                const uint32_t b0 = __float_as_uint(Ks[(nt * 8 + lr) * AST_K + kk * 8 + lc]);
                const uint32_t b1 = __float_as_uint(Ks[(nt * 8 + lr) * AST_K + kk * 8 + lc + 4]);
                mma_tf32(s[nt], a0, a1, a2, a3, b0, b1);
            }
        }

        if (kt == qt) {
            const int r0l = w * 16 + lr;
            #pragma unroll
            for (int nt = 0; nt < 8; nt++) {
                const int c = nt * 8 + 2 * lc;
                if (c     > r0l)     s[nt][0] = -1e30f;
                if (c + 1 > r0l)     s[nt][1] = -1e30f;
                if (c     > r0l + 8) s[nt][2] = -1e30f;
                if (c + 1 > r0l + 8) s[nt][3] = -1e30f;
            }
        }

        float mx0 = -1e30f, mx1 = -1e30f;
        #pragma unroll
        for (int nt = 0; nt < 8; nt++) {
            mx0 = fmaxf(mx0, fmaxf(s[nt][0], s[nt][1]));
            mx1 = fmaxf(mx1, fmaxf(s[nt][2], s[nt][3]));
        }
        mx0 = fmaxf(mx0, __shfl_xor_sync(0xffffffffu, mx0, 1));
        mx0 = fmaxf(mx0, __shfl_xor_sync(0xffffffffu, mx0, 2));
        mx1 = fmaxf(mx1, __shfl_xor_sync(0xffffffffu, mx1, 1));
        mx1 = fmaxf(mx1, __shfl_xor_sync(0xffffffffu, mx1, 2));

        const float mn0 = fmaxf(m0, mx0), mn1 = fmaxf(m1, mx1);
        const float al0 = __expf(m0 - mn0), al1 = __expf(m1 - mn1);
        m0 = mn0; m1 = mn1;

        float sum0 = 0.f, sum1 = 0.f;
        #pragma unroll
        for (int nt = 0; nt < 8; nt++) {
            s[nt][0] = __expf(s[nt][0] - mn0); sum0 += s[nt][0];
            s[nt][1] = __expf(s[nt][1] - mn0); sum0 += s[nt][1];
            s[nt][2] = __expf(s[nt][2] - mn1); sum1 += s[nt][2];
            s[nt][3] = __expf(s[nt][3] - mn1); sum1 += s[nt][3];
        }
        sum0 += __shfl_xor_sync(0xffffffffu, sum0, 1);
        sum0 += __shfl_xor_sync(0xffffffffu, sum0, 2);
        sum1 += __shfl_xor_sync(0xffffffffu, sum1, 1);
        sum1 += __shfl_xor_sync(0xffffffffu, sum1, 2);
        l0 = l0 * al0 + sum0;
        l1 = l1 * al1 + sum1;

        const float zA0  = __shfl_sync(0xffffffffu, al0, 8 * lc);
        const float zA0b = __shfl_sync(0xffffffffu, al0, 8 * lc + 4);
        const float zA1  = __shfl_sync(0xffffffffu, al1, 8 * lc);
        const float zA1b = __shfl_sync(0xffffffffu, al1, 8 * lc + 4);
        #pragma unroll
        for (int mt = 0; mt < 4; mt++) {
            o[mt][0][0] *= zA0;  o[mt][0][1] *= zA0b;
            o[mt][0][2] *= zA0;  o[mt][0][3] *= zA0b;
            o[mt][1][0] *= zA1;  o[mt][1][1] *= zA1b;
            o[mt][1][2] *= zA1;  o[mt][1][3] *= zA1b;
        }

        __syncwarp();
        {
            const int c0c = 2 * lc, c1c = 2 * lc + 1;
            const int ln0 = lr * 4 + (c0c & 3), rg0 = (c0c & 4) >> 2;
            const int ln1 = lr * 4 + (c1c & 3), rg1 = (c1c & 4) >> 2;
            #pragma unroll
            for (int nt = 0; nt < 8; nt++) {
                Pw[(nt * 2 + 0) * 64 + ln0 * 2 + rg0] = tf32r(s[nt][0]);
                Pw[(nt * 2 + 0) * 64 + ln1 * 2 + rg1] = tf32r(s[nt][1]);
                Pw[(nt * 2 + 1) * 64 + ln0 * 2 + rg0] = tf32r(s[nt][2]);
                Pw[(nt * 2 + 1) * 64 + ln1 * 2 + rg1] = tf32r(s[nt][3]);
            }
        }
        __syncwarp();

        #pragma unroll
        for (int kk2 = 0; kk2 < 8; kk2++) {
            const uint2 bp0 = *reinterpret_cast<const uint2*>(Pw + (kk2 * 2 + 0) * 64 + lane * 2);
            const uint2 bp1 = *reinterpret_cast<const uint2*>(Pw + (kk2 * 2 + 1) * 64 + lane * 2);
            #pragma unroll
            for (int mt = 0; mt < 4; mt++) {
                const uint32_t a0 = __float_as_uint(Vs[(kk2 * 8 + lc) * AST_V + mt * 16 + lr]);
                const uint32_t a1 = __float_as_uint(Vs[(kk2 * 8 + lc) * AST_V + mt * 16 + lr + 8]);
                const uint32_t a2 = __float_as_uint(Vs[(kk2 * 8 + lc + 4) * AST_V + mt * 16 + lr]);
                const uint32_t a3 = __float_as_uint(Vs[(kk2 * 8 + lc + 4) * AST_V + mt * 16 + lr + 8]);
                mma_tf32(o[mt][0], a0, a1, a2, a3, bp0.x, bp0.y);
                mma_tf32(o[mt][1], a0, a1, a2, a3, bp1.x, bp1.y);
            }
        }

        // RACE FIX: all warps must be done reading Ks/Vs (this buffer pair)
        // before the next iteration's ISSUE_KV overwrites the other buffer
        // while some warp still lags in this one.
        __syncthreads();
    }

    // finalize: full-granule packed stores (lane^16 exchange pairs d <-> d+4)
    const float i0 = 1.0f / l0, i1 = 1.0f / l1;
    const float zI0  = __shfl_sync(0xffffffffu, i0, 8 * lc);
    const float zI0b = __shfl_sync(0xffffffffu, i0, 8 * lc + 4);
    const float zI1  = __shfl_sync(0xffffffffu, i1, 8 * lc);
    const float zI1b = __shfl_sync(0xffffffffu, i1, 8 * lc + 4);
    const int qr0 = b * 2048 + q0 + w * 16 + 2 * lc;

    #pragma unroll
    for (int mt = 0; mt < 4; mt++) {
        float f[2][4];
        f[0][0] = o[mt][0][0] * zI0;  f[0][1] = o[mt][0][1] * zI0b;
        f[0][2] = o[mt][0][2] * zI0;  f[0][3] = o[mt][0][3] * zI0b;
        f[1][0] = o[mt][1][0] * zI1;  f[1][1] = o[mt][1][1] * zI1b;
        f[1][2] = o[mt][1][2] * zI1;  f[1][3] = o[mt][1][3] * zI1b;

        float e[2][4];
        #pragma unroll
        for (int n2 = 0; n2 < 2; n2++)
            #pragma unroll
            for (int j = 0; j < 4; j++)
                e[n2][j] = __shfl_xor_sync(0xffffffffu, f[n2][j], 16);

        if (lr < 4) {
            const int k0 = h * 64 + mt * 16 + lr;
            *reinterpret_cast<float4*>(&out[paddrA(qr0, k0, CDIM)]) =
                make_float4(tf32r(f[0][0]), tf32r(f[1][0]), tf32r(e[0][0]), tf32r(e[1][0]));
            *reinterpret_cast<float4*>(&out[paddrA(qr0 + 1, k0, CDIM)]) =
                make_float4(tf32r(f[0][1]), tf32r(f[1][1]), tf32r(e[0][1]), tf32r(e[1][1]));
        } else {
            const int kb = h * 64 + mt * 16 + lr + 4;
            *reinterpret_cast<float4*>(&out[paddrA(qr0, kb, CDIM)]) =
                make_float4(tf32r(e[0][2]), tf32r(e[1][2]), tf32r(f[0][2]), tf32r(f[1][2]));
            *reinterpret_cast<float4*>(&out[paddrA(qr0 + 1, kb, CDIM)]) =
                make_float4(tf32r(e[0][3]), tf32r(e[1][3]), tf32r(f[0][3]), tf32r(f[1][3]));
        }
    }
}

// ---------------------------------------------------------------------------
// Launch
// ---------------------------------------------------------------------------
extern "C" void kernel_launch(void* const* d_in, const int* in_sizes, int n_in,
                              void* d_out, int out_size)
{
    const float* x        = (const float*)d_in[0];
    const float* c_attn_w = (const float*)d_in[1];
    const float* c_attn_b = (const float*)d_in[2];
    const float* c_proj_w = (const float*)d_in[3];
    const float* c_proj_b = (const float*)d_in[4];
    const float* fc_w     = (const float*)d_in[5];
    const float* fc_b     = (const float*)d_in[6];
    const float* proj_w   = (const float*)d_in[7];
    const float* proj_b   = (const float*)d_in[8];
    const float* ln1_g    = (const float*)d_in[9];
    const float* ln1_b    = (const float*)d_in[10];
    const float* ln2_g    = (const float*)d_in[11];
    const float* ln2_b    = (const float*)d_in[12];

    float *ln1, *qkv, *attn, *x1, *ln2, *hbuf, *w1p, *w2p, *w3p, *w4p;
    cudaGetSymbolAddress((void**)&ln1,  g_ln1);
    cudaGetSymbolAddress((void**)&qkv,  g_qkv);
    cudaGetSymbolAddress((void**)&attn, g_attn);
    cudaGetSymbolAddress((void**)&x1,   g_x1);
    cudaGetSymbolAddress((void**)&ln2,  g_ln2);
    cudaGetSymbolAddress((void**)&hbuf, g_hbuf);
    cudaGetSymbolAddress((void**)&w1p,  g_w1p);
    cudaGetSymbolAddress((void**)&w2p,  g_w2p);
    cudaGetSymbolAddress((void**)&w3p,  g_w3p);
    cudaGetSymbolAddress((void**)&w4p,  g_w4p);

    cudaFuncSetAttribute(mma_gemm, cudaFuncAttributeMaxDynamicSharedMemorySize, GEMM_SMEM);
    cudaFuncSetAttribute(attn_mma, cudaFuncAttributeMaxDynamicSharedMemorySize, ATT_SMEM);

    float* outp = (float*)d_out;

    // weight prep (all 4 in one launch, full-sector stores)
    wprep4_kernel<<<6144, 256>>>(c_attn_w, c_proj_w, fc_w, proj_w,
                                 w1p, w2p, w3p, w4p);

    // 1. ln1 = LN(x) (packed A, granule stores)
    ln_kernel<<<4096, 256>>>(x, ln1_g, ln1_b, ln1);
    // 2. qkv = ln1 @ c_attn_w + b  (natural, tf32-rounded for attention)
    mma_gemm<<<dim3(24, 64), 128, GEMM_SMEM>>>(
        ln1, w1p, c_attn_b, nullptr, qkv, MROWS, 3072, 1024, 0, 0, 1);
    // 3. attention (mma.sync) -> packed A (granule stores)
    attn_mma<<<dim3(32, 64), 128, ATT_SMEM>>>(qkv, attn);
    // 4. x1 = attn @ c_proj_w + b + x
    mma_gemm<<<dim3(8, 64), 128, GEMM_SMEM>>>(
        attn, w2p, c_proj_b, x, x1, MROWS, 1024, 1024, 0, 0, 0);
    // 5. ln2 = LN(x1) (packed A)
    ln_kernel<<<4096, 256>>>(x1, ln2_g, ln2_b, ln2);
    // 6. h = gelu(ln2 @ fc_w + b) (packed out, granule stores)
    mma_gemm<<<dim3(32, 64), 128, GEMM_SMEM>>>(
        ln2, w3p, fc_b, nullptr, hbuf, MROWS, 4096, 1024, 1, 1, 0);
    // 7. out = h @ proj_w + b + x1
    mma_gemm<<<dim3(8, 64), 128, GEMM_SMEM>>>(
        hbuf, w4p, proj_b, x1, outp, MROWS, 1024, 4096, 0, 0, 0);
}

// round 10
// speedup vs baseline: 4.2045x; 1.0102x over previous
#include <cuda_runtime.h>
#include <math.h>
#include <stdint.h>

// ---------------------------------------------------------------------------
// B=4, T=2048, C=1024, H=16, HS=64. M = 8192.
// GEMMs + attention on mma.sync.m16n8k8 tf32, fragment-packed operands.
// R10: attention warp q-tile widened to 32 rows (CTA q-tile 128) for 2x
// K/V fragment reuse; causal full-tile skip per warp.
// ---------------------------------------------------------------------------
#define MROWS 8192
#define CDIM  1024

__device__ float g_ln1 [8192u * 1024];   // packed A
__device__ float g_qkv [8192u * 3072];   // natural, tf32-rounded
__device__ float g_attn[8192u * 1024];   // packed A
__device__ float g_x1  [8192u * 1024];   // natural
__device__ float g_ln2 [8192u * 1024];   // packed A
__device__ float g_hbuf[8192u * 4096];   // packed A
__device__ float g_w1p [1024u * 3072];   // packed B
__device__ float g_w2p [1024u * 1024];
__device__ float g_w3p [1024u * 4096];
__device__ float g_w4p [4096u * 1024];

// ---------------- helpers ----------------
__device__ __forceinline__ float tf32r(float x) {
    uint32_t u;
    asm("cvt.rna.tf32.f32 %0, %1;" : "=r"(u) : "f"(x));
    return __uint_as_float(u);
}
__device__ __forceinline__ uint32_t smem_u32(const void* p) {
    uint32_t a;
    asm("{ .reg .u64 t; cvta.to.shared.u64 t, %1; cvt.u32.u64 %0, t; }"
        : "=r"(a) : "l"(p));
    return a;
}
#define CP_ASYNC16(dst, src) \
    asm volatile("cp.async.cg.shared.global [%0], [%1], 16;" :: "r"(dst), "l"(src))
#define CP_COMMIT() asm volatile("cp.async.commit_group;" ::: "memory")
#define CP_WAIT0()  asm volatile("cp.async.wait_group 0;"  ::: "memory")
#define CP_WAIT1()  asm volatile("cp.async.wait_group 1;"  ::: "memory")
#define CP_WAIT2()  asm volatile("cp.async.wait_group 2;"  ::: "memory")

__device__ __forceinline__ void mma_tf32(float c[4], uint32_t a0, uint32_t a1,
                                         uint32_t a2, uint32_t a3,
                                         uint32_t b0, uint32_t b1) {
    asm volatile(
        "mma.sync.aligned.m16n8k8.row.col.f32.tf32.tf32.f32 "
        "{%0,%1,%2,%3}, {%4,%5,%6,%7}, {%8,%9}, {%0,%1,%2,%3};"
        : "+f"(c[0]), "+f"(c[1]), "+f"(c[2]), "+f"(c[3])
        : "r"(a0), "r"(a1), "r"(a2), "r"(a3), "r"(b0), "r"(b1));
}

__device__ __forceinline__ float gelu_f(float x) {
    float x3 = x * x * x;
    return 0.5f * x * (1.0f + tanhf(0.7978845608028654f * (x + 0.044715f * x3)));
}

// Packed-A address (float index) for element (m,k) of an [M,K] A operand.
__device__ __forceinline__ size_t paddrA(int m, int k, int K) {
    const int mb = m >> 7, rm = m & 127;
    const int wm = rm >> 5, mt = (rm >> 4) & 1, lr = rm & 7, ah = (rm >> 3) & 1;
    const int kt = k >> 5, kk = (k >> 3) & 3, lc = k & 3, kh = (k >> 2) & 1;
    const int lane = lr * 4 + lc;
    const int reg  = ah + 2 * kh;
    return ((size_t)mb * (K >> 5) + kt) * 4096 +
           ((((kk * 4 + wm) * 2 + mt) * 32 + lane) * 4 + reg);
}
// Packed-B address (float index) for element (n,k) of W[K,N] viewed as [N,K].
__device__ __forceinline__ size_t paddrB(int n, int k, int K) {
    const int nb = n >> 7, rn = n & 127;
    const int wn = (rn >> 6) & 1, nt = (rn >> 3) & 7, n8 = rn & 7;
    const int kt = k >> 5, kk = (k >> 3) & 3, kh = (k >> 2) & 1;
    const int lane = n8 * 4 + (k & 3);
    return ((size_t)nb * (K >> 5) + kt) * 4096 +
           ((((kk * 2 + wn) * 8 + nt) * 32 + lane) * 2 + kh);
}

// ---------------------------------------------------------------------------
// Weight prep, all 4 weights in one launch.
// ---------------------------------------------------------------------------
__global__ __launch_bounds__(256) void wprep4_kernel(
    const float* __restrict__ w1, const float* __restrict__ w2,
    const float* __restrict__ w3, const float* __restrict__ w4,
    float* __restrict__ o1, float* __restrict__ o2,
    float* __restrict__ o3, float* __restrict__ o4)
{
    const int bid = blockIdx.x;
    const float* W; float* O; int K, N, base;
    if (bid < 1536)      { W = w1; O = o1; K = 1024; N = 3072; base = 0; }
    else if (bid < 2048) { W = w2; O = o2; K = 1024; N = 1024; base = 1536; }
    else if (bid < 4096) { W = w3; O = o3; K = 1024; N = 4096; base = 2048; }
    else                 { W = w4; O = o4; K = 4096; N = 1024; base = 4096; }

    const int idx = (bid - base) * 256 + threadIdx.x;
    const int n  = idx % N;
    const int kb = (idx / N) * 8;

    float v[8];
    #pragma unroll
    for (int i = 0; i < 8; i++)
        v[i] = tf32r(__ldg(&W[(size_t)(kb + i) * N + n]));

    float4* p = reinterpret_cast<float4*>(&O[paddrB(n, kb, K)]);
    p[0] = make_float4(v[0], v[4], v[1], v[5]);
    p[1] = make_float4(v[2], v[6], v[3], v[7]);
}

// ---------------------------------------------------------------------------
// LayerNorm, row-pair (m, m+8) per block -> full float4 granule stores.
// ---------------------------------------------------------------------------
__global__ __launch_bounds__(256) void ln_kernel(
    const float* __restrict__ x, const float* __restrict__ g,
    const float* __restrict__ b, float* __restrict__ o)
{
    const int p  = blockIdx.x;
    const int m0 = (p >> 3) * 16 + (p & 7);
    const int m1 = m0 + 8;
    const int tid = threadIdx.x;
    const int k0 = ((tid >> 2) << 3) + (tid & 3);
    const int k1 = k0 + 512;

    const float* x0 = x + (size_t)m0 * CDIM;
    const float* x1 = x + (size_t)m1 * CDIM;
    const float a00 = x0[k0], a01 = x0[k0 + 4], a02 = x0[k1], a03 = x0[k1 + 4];
    const float a10 = x1[k0], a11 = x1[k0 + 4], a12 = x1[k1], a13 = x1[k1 + 4];

    float s0 = a00 + a01 + a02 + a03;
    float q0 = a00 * a00 + a01 * a01 + a02 * a02 + a03 * a03;
    float s1 = a10 + a11 + a12 + a13;
    float q1 = a10 * a10 + a11 * a11 + a12 * a12 + a13 * a13;

    #pragma unroll
    for (int off = 16; off > 0; off >>= 1) {
        s0 += __shfl_xor_sync(0xffffffffu, s0, off);
        q0 += __shfl_xor_sync(0xffffffffu, q0, off);
        s1 += __shfl_xor_sync(0xffffffffu, s1, off);
        q1 += __shfl_xor_sync(0xffffffffu, q1, off);
    }
    __shared__ float red[4][8];
    const int wid = tid >> 5;
    if ((tid & 31) == 0) {
        red[0][wid] = s0; red[1][wid] = q0; red[2][wid] = s1; red[3][wid] = q1;
    }
    __syncthreads();
    float ts0 = 0.f, tq0 = 0.f, ts1 = 0.f, tq1 = 0.f;
    #pragma unroll
    for (int w = 0; w < 8; w++) {
        ts0 += red[0][w]; tq0 += red[1][w]; ts1 += red[2][w]; tq1 += red[3][w];
    }

    const float mu0 = ts0 * (1.0f / CDIM);
    const float mu1 = ts1 * (1.0f / CDIM);
    const float r0 = rsqrtf(tq0 * (1.0f / CDIM) - mu0 * mu0 + 1e-5f);
    const float r1 = rsqrtf(tq1 * (1.0f / CDIM) - mu1 * mu1 + 1e-5f);

    #pragma unroll
    for (int gi = 0; gi < 2; gi++) {
        const int k = gi ? k1 : k0;
        const float ga = __ldg(&g[k]), gb = __ldg(&g[k + 4]);
        const float ba = __ldg(&b[k]), bb = __ldg(&b[k + 4]);
        const float xa0 = gi ? a02 : a00, xa1 = gi ? a03 : a01;
        const float xb0 = gi ? a12 : a10, xb1 = gi ? a13 : a11;
        *reinterpret_cast<float4*>(&o[paddrA(m0, k, CDIM)]) = make_float4(
            tf32r((xa0 - mu0) * r0 * ga + ba),
            tf32r((xb0 - mu1) * r1 * ga + ba),
            tf32r((xa1 - mu0) * r0 * gb + bb),
            tf32r((xb1 - mu1) * r1 * gb + bb));
    }
}

// ---------------------------------------------------------------------------
// tf32 mma.sync GEMM, fragment-packed operands (unchanged from R9).
// ---------------------------------------------------------------------------
#define GSTG 3
#define STG_FLOATS 8192
#define GEMM_SMEM (GSTG * STG_FLOATS * 4)

__global__ __launch_bounds__(128, 2) void mma_gemm(
    const float* __restrict__ Apk, const float* __restrict__ Bpk,
    const float* __restrict__ bias, const float* __restrict__ resid,
    float* __restrict__ C, int M, int N, int K, int act, int pack_out,
    int round_out)
{
    extern __shared__ float sm[];
    const uint32_t sb = smem_u32(sm);

    const int tid  = threadIdx.x;
    const int wid  = tid >> 5;
    const int lane = tid & 31;
    const int wm = wid & 1;
    const int wn = wid >> 1;
    const int bm = blockIdx.y << 7;
    const int bn = blockIdx.x << 7;
    const int lr = lane >> 2;
    const int lc = lane & 3;

    const int nk = K >> 5;
    const char* abase = (const char*)Apk + (size_t)blockIdx.y * nk * 16384;
    const char* bbase = (const char*)Bpk + (size_t)blockIdx.x * nk * 16384;

    float acc[4][8][4];
    #pragma unroll
    for (int at = 0; at < 4; at++)
        #pragma unroll
        for (int nt = 0; nt < 8; nt++)
            #pragma unroll
            for (int j = 0; j < 4; j++) acc[at][nt][j] = 0.f;

    #define ISSUE(t) do { \
        if ((t) < nk) { \
            const char* _a = abase + (size_t)(t) * 16384 + tid * 16; \
            const char* _b = bbase + (size_t)(t) * 16384 + tid * 16; \
            const uint32_t _d = sb + ((t) % GSTG) * (STG_FLOATS * 4) + tid * 16; \
            _Pragma("unroll") \
            for (int _i = 0; _i < 8; _i++) { \
                CP_ASYNC16(_d + _i * 2048,         _a + _i * 2048); \
                CP_ASYNC16(_d + 16384 + _i * 2048, _b + _i * 2048); \
            } \
        } \
        CP_COMMIT(); \
    } while (0)

    ISSUE(0);
    ISSUE(1);

    for (int t = 0; t < nk; t++) {
        ISSUE(t + 2);
        CP_WAIT2();
        __syncthreads();

        const float* Ab = sm + (t % GSTG) * STG_FLOATS;
        const float* Bb = Ab + 4096;
        #pragma unroll
        for (int kk = 0; kk < 4; kk++) {
            uint4 a[4];
            #pragma unroll
            for (int at = 0; at < 4; at++)
                a[at] = *reinterpret_cast<const uint4*>(
                    Ab + ((kk * 4 + wm * 2 + (at >> 1)) * 2 + (at & 1)) * 128 + lane * 4);
            const float* bq = Bb + (kk * 2 + wn) * 512 + lane * 2;
            #pragma unroll
            for (int nt = 0; nt < 8; nt++) {
                const uint2 bv = *reinterpret_cast<const uint2*>(bq + nt * 64);
                #pragma unroll
                for (int at = 0; at < 4; at++)
                    mma_tf32(acc[at][nt], a[at].x, a[at].y, a[at].z, a[at].w,
                             bv.x, bv.y);
            }
        }
        __syncthreads();
    }

    #pragma unroll
    for (int at = 0; at < 4; at++) {
        const int r0 = bm + wm * 64 + (at >> 1) * 32 + (at & 1) * 16 + lr;
        const int r1 = r0 + 8;
        #pragma unroll
        for (int nt = 0; nt < 8; nt++) {
            const int col = bn + wn * 64 + nt * 8 + lc * 2;
            const float bb0 = __ldg(&bias[col]);
            const float bb1 = __ldg(&bias[col + 1]);
            float v0 = acc[at][nt][0] + bb0;
            float v1 = acc[at][nt][1] + bb1;
            float v2 = acc[at][nt][2] + bb0;
            float v3 = acc[at][nt][3] + bb1;
            if (act) {
                v0 = gelu_f(v0); v1 = gelu_f(v1);
                v2 = gelu_f(v2); v3 = gelu_f(v3);
            }
            if (pack_out) {
                const float u0 = __shfl_xor_sync(0xffffffffu, v0, 2);
                const float u1 = __shfl_xor_sync(0xffffffffu, v1, 2);
                const float u2 = __shfl_xor_sync(0xffffffffu, v2, 2);
                const float u3 = __shfl_xor_sync(0xffffffffu, v3, 2);
                if (lc < 2) {
                    *reinterpret_cast<float4*>(&C[paddrA(r0, col, N)]) =
                        make_float4(tf32r(v0), tf32r(v2), tf32r(u0), tf32r(u2));
                } else {
                    const int colo = col - 3;
                    *reinterpret_cast<float4*>(&C[paddrA(r0, colo, N)]) =
                        make_float4(tf32r(u1), tf32r(u3), tf32r(v1), tf32r(v3));
                }
            } else {
                const size_t o0 = (size_t)r0 * N + col;
                const size_t o1 = (size_t)r1 * N + col;
                if (resid) {
                    const float2 q0 = *reinterpret_cast<const float2*>(&resid[o0]);
                    const float2 q1 = *reinterpret_cast<const float2*>(&resid[o1]);
                    v0 += q0.x; v1 += q0.y; v2 += q1.x; v3 += q1.y;
                }
                if (round_out) {
                    v0 = tf32r(v0); v1 = tf32r(v1); v2 = tf32r(v2); v3 = tf32r(v3);
                }
                *reinterpret_cast<float2*>(&C[o0]) = make_float2(v0, v1);
                *reinterpret_cast<float2*>(&C[o1]) = make_float2(v2, v3);
            }
        }
    }
}

// ---------------------------------------------------------------------------
// Flash attention on mma.sync tf32, causal.
// CTA q-tile 128 (4 warps x 32 q rows). Warp tile 32q x 64k:
// K/V fragments reused across 2 m-tiles / 4 q-subtiles.
// Fully-masked warp-iterations are skipped.
// ---------------------------------------------------------------------------
#define AST_K 68
#define AST_V 72
#define ATT_QOFF 0                         // 128*68 = 8704 floats; P region after Q read
#define ATT_KOFF(b) (8704 + (b) * 4352)
#define ATT_VOFF(b) (17408 + (b) * 4608)
#define ATT_SMEM (26624 * 4)               // 106496 bytes

__global__ __launch_bounds__(128, 2) void attn_mma(
    const float* __restrict__ qkv, float* __restrict__ out)
{
    extern __shared__ float sm[];
    const uint32_t sb = smem_u32(sm);
    const int tid = threadIdx.x;
    const int w = tid >> 5, lane = tid & 31;
    const int lr = lane >> 2, lc = lane & 3;
    const int qt = blockIdx.x, bh = blockIdx.y;
    const int b = bh >> 4, h = bh & 15;
    const int q0 = qt * 128;
    const float* basep = qkv + (size_t)b * 2048 * 3072 + (size_t)h * 64;

    // Q tile: 128 rows x 64 d  (group 0)
    #pragma unroll
    for (int i = 0; i < 16; i++) {
        const int idx = tid + i * 128, row = idx >> 4, ch = idx & 15;
        CP_ASYNC16(sb + (uint32_t)(ATT_QOFF + row * AST_K + ch * 4) * 4,
                   basep + (size_t)(q0 + row) * 3072 + ch * 4);
    }
    CP_COMMIT();

    #define ISSUE_KV(kt_, bb) do { \
        const float* _k = basep + (size_t)((kt_) * 64) * 3072 + 1024; \
        _Pragma("unroll") \
        for (int _i = 0; _i < 8; _i++) { \
            const int _idx = tid + _i * 128, _r = _idx >> 4, _c = _idx & 15; \
            CP_ASYNC16(sb + (uint32_t)(ATT_KOFF(bb) + _r * AST_K + _c * 4) * 4, \
                       _k + (size_t)_r * 3072 + _c * 4); \
            CP_ASYNC16(sb + (uint32_t)(ATT_VOFF(bb) + _r * AST_V + _c * 4) * 4, \
                       _k + 1024 + (size_t)_r * 3072 + _c * 4); \
        } \
        CP_COMMIT(); \
    } while (0)

    ISSUE_KV(0, 0);

    CP_WAIT1();          // Q ready
    __syncthreads();

    // Q fragments for 32 rows (2 m-tiles), scale folded
    float qa[2][8][4];
    {
        const float* Qs = sm + ATT_QOFF;
        #pragma unroll
        for (int mt2 = 0; mt2 < 2; mt2++) {
            const int r0 = w * 32 + mt2 * 16 + lr;
            #pragma unroll
            for (int kk = 0; kk < 8; kk++) {
                qa[mt2][kk][0] = 0.125f * Qs[r0 * AST_K + kk * 8 + lc];
                qa[mt2][kk][1] = 0.125f * Qs[(r0 + 8) * AST_K + kk * 8 + lc];
                qa[mt2][kk][2] = 0.125f * Qs[r0 * AST_K + kk * 8 + lc + 4];
                qa[mt2][kk][3] = 0.125f * Qs[(r0 + 8) * AST_K + kk * 8 + lc + 4];
            }
        }
    }
    __syncthreads();     // Q region becomes P region

    float* Pw = sm + ATT_QOFF + w * 2048;   // per-warp P^T region (2048 floats)

    float m[2][2], l[2][2];
    #pragma unroll
    for (int i = 0; i < 2; i++)
        #pragma unroll
        for (int j2 = 0; j2 < 2; j2++) { m[i][j2] = -1e30f; l[i][j2] = 0.f; }

    float o[4][4][4];    // [d-tile][q-subtile][reg]
    #pragma unroll
    for (int mt = 0; mt < 4; mt++)
        #pragma unroll
        for (int qn = 0; qn < 4; qn++)
            #pragma unroll
            for (int j = 0; j < 4; j++) o[mt][qn][j] = 0.f;

    const int ktmax = 2 * qt + 1;
    for (int kt = 0; kt <= ktmax; kt++) {
        const int buf = kt & 1;
        if (kt < ktmax) { ISSUE_KV(kt + 1, buf ^ 1); CP_WAIT1(); }
        else            { CP_WAIT0(); }
        __syncthreads();

        // full-tile causal skip: all keys beyond all of this warp's rows
        if (64 * kt <= q0 + w * 32 + 31) {
            const float* Ks = sm + ATT_KOFF(buf);
            const float* Vs = sm + ATT_VOFF(buf);

            // ---- S = Q K^T  (2 m-tiles share each K fragment) ----
            float s[2][8][4];
            #pragma unroll
            for (int mt2 = 0; mt2 < 2; mt2++)
                #pragma unroll
                for (int nt = 0; nt < 8; nt++)
                    #pragma unroll
                    for (int j = 0; j < 4; j++) s[mt2][nt][j] = 0.f;

            #pragma unroll
            for (int kk = 0; kk < 8; kk++) {
                #pragma unroll
                for (int nt = 0; nt < 8; nt++) {
                    const uint32_t b0 = __float_as_uint(Ks[(nt * 8 + lr) * AST_K + kk * 8 + lc]);
                    const uint32_t b1 = __float_as_uint(Ks[(nt * 8 + lr) * AST_K + kk * 8 + lc + 4]);
                    mma_tf32(s[0][nt],
                             __float_as_uint(qa[0][kk][0]), __float_as_uint(qa[0][kk][1]),
                             __float_as_uint(qa[0][kk][2]), __float_as_uint(qa[0][kk][3]),
                             b0, b1);
                    mma_tf32(s[1][nt],
                             __float_as_uint(qa[1][kk][0]), __float_as_uint(qa[1][kk][1]),
                             __float_as_uint(qa[1][kk][2]), __float_as_uint(qa[1][kk][3]),
                             b0, b1);
                }
            }

            // ---- causal mask (per m-tile, only near diagonal) ----
            #pragma unroll
            for (int mt2 = 0; mt2 < 2; mt2++) {
                const int rbase = q0 + w * 32 + mt2 * 16;
                if (64 * kt + 63 > rbase) {
                    #pragma unroll
                    for (int nt = 0; nt < 8; nt++) {
                        const int c = 64 * kt + nt * 8 + 2 * lc;
                        if (c     > rbase + lr)     s[mt2][nt][0] = -1e30f;
                        if (c + 1 > rbase + lr)     s[mt2][nt][1] = -1e30f;
                        if (c     > rbase + lr + 8) s[mt2][nt][2] = -1e30f;
                        if (c + 1 > rbase + lr + 8) s[mt2][nt][3] = -1e30f;
                    }
                }
            }

            // ---- online softmax per m-tile ----
            float al[2][2];
            #pragma unroll
            for (int mt2 = 0; mt2 < 2; mt2++) {
                float mx0 = -1e30f, mx1 = -1e30f;
                #pragma unroll
                for (int nt = 0; nt < 8; nt++) {
                    mx0 = fmaxf(mx0, fmaxf(s[mt2][nt][0], s[mt2][nt][1]));
                    mx1 = fmaxf(mx1, fmaxf(s[mt2][nt][2], s[mt2][nt][3]));
                }
                mx0 = fmaxf(mx0, __shfl_xor_sync(0xffffffffu, mx0, 1));
                mx0 = fmaxf(mx0, __shfl_xor_sync(0xffffffffu, mx0, 2));
                mx1 = fmaxf(mx1, __shfl_xor_sync(0xffffffffu, mx1, 1));
                mx1 = fmaxf(mx1, __shfl_xor_sync(0xffffffffu, mx1, 2));

                const float mn0 = fmaxf(m[mt2][0], mx0);
                const float mn1 = fmaxf(m[mt2][1], mx1);
                al[mt2][0] = __expf(m[mt2][0] - mn0);
                al[mt2][1] = __expf(m[mt2][1] - mn1);
                m[mt2][0] = mn0; m[mt2][1] = mn1;

                float sum0 = 0.f, sum1 = 0.f;
                #pragma unroll
                for (int nt = 0; nt < 8; nt++) {
                    s[mt2][nt][0] = __expf(s[mt2][nt][0] - mn0); sum0 += s[mt2][nt][0];
                    s[mt2][nt][1] = __expf(s[mt2][nt][1] - mn0); sum0 += s[mt2][nt][1];
                    s[mt2][nt][2] = __expf(s[mt2][nt][2] - mn1); sum1 += s[mt2][nt][2];
                    s[mt2][nt][3] = __expf(s[mt2][nt][3] - mn1); sum1 += s[mt2][nt][3];
                }
                sum0 += __shfl_xor_sync(0xffffffffu, sum0, 1);
                sum0 += __shfl_xor_sync(0xffffffffu, sum0, 2);
                sum1 += __shfl_xor_sync(0xffffffffu, sum1, 1);
                sum1 += __shfl_xor_sync(0xffffffffu, sum1, 2);
                l[mt2][0] = l[mt2][0] * al[mt2][0] + sum0;
                l[mt2][1] = l[mt2][1] * al[mt2][1] + sum1;
            }

            // ---- rescale O^T (cols are q-rows; broadcast alpha per q-subtile) ----
            #pragma unroll
            for (int qn = 0; qn < 4; qn++) {
                const float zA  = __shfl_sync(0xffffffffu, al[qn >> 1][qn & 1], 8 * lc);
                const float zAb = __shfl_sync(0xffffffffu, al[qn >> 1][qn & 1], 8 * lc + 4);
                #pragma unroll
                for (int mt = 0; mt < 4; mt++) {
                    o[mt][qn][0] *= zA;  o[mt][qn][1] *= zAb;
                    o[mt][qn][2] *= zA;  o[mt][qn][3] *= zAb;
                }
            }

            // ---- store P^T (packed B granules) ----
            __syncwarp();
            {
                const int c0c = 2 * lc, c1c = 2 * lc + 1;
                const int ln0 = lr * 4 + (c0c & 3), rg0 = (c0c & 4) >> 2;
                const int ln1 = lr * 4 + (c1c & 3), rg1 = (c1c & 4) >> 2;
                #pragma unroll
                for (int mt2 = 0; mt2 < 2; mt2++) {
                    #pragma unroll
                    for (int nt = 0; nt < 8; nt++) {
                        const int q0n = mt2 * 2;
                        Pw[(nt * 4 + q0n + 0) * 64 + ln0 * 2 + rg0] = tf32r(s[mt2][nt][0]);
                        Pw[(nt * 4 + q0n + 0) * 64 + ln1 * 2 + rg1] = tf32r(s[mt2][nt][1]);
                        Pw[(nt * 4 + q0n + 1) * 64 + ln0 * 2 + rg0] = tf32r(s[mt2][nt][2]);
                        Pw[(nt * 4 + q0n + 1) * 64 + ln1 * 2 + rg1] = tf32r(s[mt2][nt][3]);
                    }
                }
            }
            __syncwarp();

            // ---- O^T += V^T P^T  (V fragment reused across 4 q-subtiles) ----
            #pragma unroll
            for (int kk2 = 0; kk2 < 8; kk2++) {
                uint2 bp[4];
                #pragma unroll
                for (int qn = 0; qn < 4; qn++)
                    bp[qn] = *reinterpret_cast<const uint2*>(
                        Pw + (kk2 * 4 + qn) * 64 + lane * 2);
                #pragma unroll
                for (int mt = 0; mt < 4; mt++) {
                    const uint32_t a0 = __float_as_uint(Vs[(kk2 * 8 + lc) * AST_V + mt * 16 + lr]);
                    const uint32_t a1 = __float_as_uint(Vs[(kk2 * 8 + lc) * AST_V + mt * 16 + lr + 8]);
                    const uint32_t a2 = __float_as_uint(Vs[(kk2 * 8 + lc + 4) * AST_V + mt * 16 + lr]);
                    const uint32_t a3 = __float_as_uint(Vs[(kk2 * 8 + lc + 4) * AST_V + mt * 16 + lr + 8]);
                    #pragma unroll
                    for (int qn = 0; qn < 4; qn++)
                        mma_tf32(o[mt][qn], a0, a1, a2, a3, bp[qn].x, bp[qn].y);
                }
            }
        }

        // all warps done with this buffer pair before next ISSUE_KV overwrite
        __syncthreads();
    }

    // ---- finalize: full-granule packed stores ----
    float zI[4], zIb[4];
    #pragma unroll
    for (int qn = 0; qn < 4; qn++) {
        const float inv = 1.0f / l[qn >> 1][qn & 1];
        zI[qn]  = __shfl_sync(0xffffffffu, inv, 8 * lc);
        zIb[qn] = __shfl_sync(0xffffffffu, inv, 8 * lc + 4);
    }

    #pragma unroll
    for (int mt = 0; mt < 4; mt++) {
        #pragma unroll
        for (int p = 0; p < 2; p++) {       // q-subtile pairs (2p, 2p+1)
            float f[2][4];
            #pragma unroll
            for (int h2 = 0; h2 < 2; h2++) {
                const int qn = 2 * p + h2;
                f[h2][0] = o[mt][qn][0] * zI[qn];
                f[h2][1] = o[mt][qn][1] * zIb[qn];
                f[h2][2] = o[mt][qn][2] * zI[qn];
                f[h2][3] = o[mt][qn][3] * zIb[qn];
            }
            float e[2][4];
            #pragma unroll
            for (int h2 = 0; h2 < 2; h2++)
                #pragma unroll
                for (int j = 0; j < 4; j++)
                    e[h2][j] = __shfl_xor_sync(0xffffffffu, f[h2][j], 16);

            const int qr0 = b * 2048 + q0 + w * 32 + p * 16 + 2 * lc;
            if (lr < 4) {
                const int k0 = h * 64 + mt * 16 + lr;
                *reinterpret_cast<float4*>(&out[paddrA(qr0, k0, CDIM)]) =
                    make_float4(tf32r(f[0][0]), tf32r(f[1][0]), tf32r(e[0][0]), tf32r(e[1][0]));
                *reinterpret_cast<float4*>(&out[paddrA(qr0 + 1, k0, CDIM)]) =
                    make_float4(tf32r(f[0][1]), tf32r(f[1][1]), tf32r(e[0][1]), tf32r(e[1][1]));
            } else {
                const int kb = h * 64 + mt * 16 + lr + 4;
                *reinterpret_cast<float4*>(&out[paddrA(qr0, kb, CDIM)]) =
                    make_float4(tf32r(e[0][2]), tf32r(e[1][2]), tf32r(f[0][2]), tf32r(f[1][2]));
                *reinterpret_cast<float4*>(&out[paddrA(qr0 + 1, kb, CDIM)]) =
                    make_float4(tf32r(e[0][3]), tf32r(e[1][3]), tf32r(f[0][3]), tf32r(f[1][3]));
            }
        }
    }
}

// ---------------------------------------------------------------------------
// Launch
// ---------------------------------------------------------------------------
extern "C" void kernel_launch(void* const* d_in, const int* in_sizes, int n_in,
                              void* d_out, int out_size)
{
    const float* x        = (const float*)d_in[0];
    const float* c_attn_w = (const float*)d_in[1];
    const float* c_attn_b = (const float*)d_in[2];
    const float* c_proj_w = (const float*)d_in[3];
    const float* c_proj_b = (const float*)d_in[4];
    const float* fc_w     = (const float*)d_in[5];
    const float* fc_b     = (const float*)d_in[6];
    const float* proj_w   = (const float*)d_in[7];
    const float* proj_b   = (const float*)d_in[8];
    const float* ln1_g    = (const float*)d_in[9];
    const float* ln1_b    = (const float*)d_in[10];
    const float* ln2_g    = (const float*)d_in[11];
    const float* ln2_b    = (const float*)d_in[12];

    float *ln1, *qkv, *attn, *x1, *ln2, *hbuf, *w1p, *w2p, *w3p, *w4p;
    cudaGetSymbolAddress((void**)&ln1,  g_ln1);
    cudaGetSymbolAddress((void**)&qkv,  g_qkv);
    cudaGetSymbolAddress((void**)&attn, g_attn);
    cudaGetSymbolAddress((void**)&x1,   g_x1);
    cudaGetSymbolAddress((void**)&ln2,  g_ln2);
    cudaGetSymbolAddress((void**)&hbuf, g_hbuf);
    cudaGetSymbolAddress((void**)&w1p,  g_w1p);
    cudaGetSymbolAddress((void**)&w2p,  g_w2p);
    cudaGetSymbolAddress((void**)&w3p,  g_w3p);
    cudaGetSymbolAddress((void**)&w4p,  g_w4p);

    cudaFuncSetAttribute(mma_gemm, cudaFuncAttributeMaxDynamicSharedMemorySize, GEMM_SMEM);
    cudaFuncSetAttribute(attn_mma, cudaFuncAttributeMaxDynamicSharedMemorySize, ATT_SMEM);

    float* outp = (float*)d_out;

    wprep4_kernel<<<6144, 256>>>(c_attn_w, c_proj_w, fc_w, proj_w,
                                 w1p, w2p, w3p, w4p);

    // 1. ln1 = LN(x) (packed A)
    ln_kernel<<<4096, 256>>>(x, ln1_g, ln1_b, ln1);
    // 2. qkv = ln1 @ c_attn_w + b  (natural, tf32-rounded for attention)
    mma_gemm<<<dim3(24, 64), 128, GEMM_SMEM>>>(
        ln1, w1p, c_attn_b, nullptr, qkv, MROWS, 3072, 1024, 0, 0, 1);
    // 3. attention (q-tile 128) -> packed A
    attn_mma<<<dim3(16, 64), 128, ATT_SMEM>>>(qkv, attn);
    // 4. x1 = attn @ c_proj_w + b + x
    mma_gemm<<<dim3(8, 64), 128, GEMM_SMEM>>>(
        attn, w2p, c_proj_b, x, x1, MROWS, 1024, 1024, 0, 0, 0);
    // 5. ln2 = LN(x1) (packed A)
    ln_kernel<<<4096, 256>>>(x1, ln2_g, ln2_b, ln2);
    // 6. h = gelu(ln2 @ fc_w + b) (packed out)
    mma_gemm<<<dim3(32, 64), 128, GEMM_SMEM>>>(
        ln2, w3p, fc_b, nullptr, hbuf, MROWS, 4096, 1024, 1, 1, 0);
    // 7. out = h @ proj_w + b + x1
    mma_gemm<<<dim3(8, 64), 128, GEMM_SMEM>>>(
        hbuf, w4p, proj_b, x1, outp, MROWS, 1024, 4096, 0, 0, 0);
}

// round 11
// speedup vs baseline: 4.2180x; 1.0032x over previous
#include <cuda_runtime.h>
#include <math.h>
#include <stdint.h>

// ---------------------------------------------------------------------------
// B=4, T=2048, C=1024, H=16, HS=64. M = 8192.
// GEMMs + attention on mma.sync.m16n8k8 tf32, fragment-packed operands.
// R11: prep (weights + LN1) merged into one launch; attention heavy-CTA-first.
// ---------------------------------------------------------------------------
#define MROWS 8192
#define CDIM  1024

__device__ float g_ln1 [8192u * 1024];   // packed A
__device__ float g_qkv [8192u * 3072];   // natural, tf32-rounded
__device__ float g_attn[8192u * 1024];   // packed A
__device__ float g_x1  [8192u * 1024];   // natural
__device__ float g_ln2 [8192u * 1024];   // packed A
__device__ float g_hbuf[8192u * 4096];   // packed A
__device__ float g_w1p [1024u * 3072];   // packed B
__device__ float g_w2p [1024u * 1024];
__device__ float g_w3p [1024u * 4096];
__device__ float g_w4p [4096u * 1024];

// ---------------- helpers ----------------
__device__ __forceinline__ float tf32r(float x) {
    uint32_t u;
    asm("cvt.rna.tf32.f32 %0, %1;" : "=r"(u) : "f"(x));
    return __uint_as_float(u);
}
__device__ __forceinline__ uint32_t smem_u32(const void* p) {
    uint32_t a;
    asm("{ .reg .u64 t; cvta.to.shared.u64 t, %1; cvt.u32.u64 %0, t; }"
        : "=r"(a) : "l"(p));
    return a;
}
#define CP_ASYNC16(dst, src) \
    asm volatile("cp.async.cg.shared.global [%0], [%1], 16;" :: "r"(dst), "l"(src))
#define CP_COMMIT() asm volatile("cp.async.commit_group;" ::: "memory")
#define CP_WAIT0()  asm volatile("cp.async.wait_group 0;"  ::: "memory")
#define CP_WAIT1()  asm volatile("cp.async.wait_group 1;"  ::: "memory")
#define CP_WAIT2()  asm volatile("cp.async.wait_group 2;"  ::: "memory")

__device__ __forceinline__ void mma_tf32(float c[4], uint32_t a0, uint32_t a1,
                                         uint32_t a2, uint32_t a3,
                                         uint32_t b0, uint32_t b1) {
    asm volatile(
        "mma.sync.aligned.m16n8k8.row.col.f32.tf32.tf32.f32 "
        "{%0,%1,%2,%3}, {%4,%5,%6,%7}, {%8,%9}, {%0,%1,%2,%3};"
        : "+f"(c[0]), "+f"(c[1]), "+f"(c[2]), "+f"(c[3])
        : "r"(a0), "r"(a1), "r"(a2), "r"(a3), "r"(b0), "r"(b1));
}

__device__ __forceinline__ float gelu_f(float x) {
    float x3 = x * x * x;
    return 0.5f * x * (1.0f + tanhf(0.7978845608028654f * (x + 0.044715f * x3)));
}

// Packed-A address (float index) for element (m,k) of an [M,K] A operand.
__device__ __forceinline__ size_t paddrA(int m, int k, int K) {
    const int mb = m >> 7, rm = m & 127;
    const int wm = rm >> 5, mt = (rm >> 4) & 1, lr = rm & 7, ah = (rm >> 3) & 1;
    const int kt = k >> 5, kk = (k >> 3) & 3, lc = k & 3, kh = (k >> 2) & 1;
    const int lane = lr * 4 + lc;
    const int reg  = ah + 2 * kh;
    return ((size_t)mb * (K >> 5) + kt) * 4096 +
           ((((kk * 4 + wm) * 2 + mt) * 32 + lane) * 4 + reg);
}
// Packed-B address (float index) for element (n,k) of W[K,N] viewed as [N,K].
__device__ __forceinline__ size_t paddrB(int n, int k, int K) {
    const int nb = n >> 7, rn = n & 127;
    const int wn = (rn >> 6) & 1, nt = (rn >> 3) & 7, n8 = rn & 7;
    const int kt = k >> 5, kk = (k >> 3) & 3, kh = (k >> 2) & 1;
    const int lane = n8 * 4 + (k & 3);
    return ((size_t)nb * (K >> 5) + kt) * 4096 +
           ((((kk * 2 + wn) * 8 + nt) * 32 + lane) * 2 + kh);
}

// ---------------------------------------------------------------------------
// LN body (shared by prep_kernel and ln_kernel)
// ---------------------------------------------------------------------------
__device__ __forceinline__ void ln_body(
    const float* __restrict__ x, const float* __restrict__ g,
    const float* __restrict__ b, float* __restrict__ o, int p, int tid)
{
    const int m0 = (p >> 3) * 16 + (p & 7);
    const int m1 = m0 + 8;
    const int k0 = ((tid >> 2) << 3) + (tid & 3);
    const int k1 = k0 + 512;

    const float* x0 = x + (size_t)m0 * CDIM;
    const float* x1 = x + (size_t)m1 * CDIM;
    const float a00 = x0[k0], a01 = x0[k0 + 4], a02 = x0[k1], a03 = x0[k1 + 4];
    const float a10 = x1[k0], a11 = x1[k0 + 4], a12 = x1[k1], a13 = x1[k1 + 4];

    float s0 = a00 + a01 + a02 + a03;
    float q0 = a00 * a00 + a01 * a01 + a02 * a02 + a03 * a03;
    float s1 = a10 + a11 + a12 + a13;
    float q1 = a10 * a10 + a11 * a11 + a12 * a12 + a13 * a13;

    #pragma unroll
    for (int off = 16; off > 0; off >>= 1) {
        s0 += __shfl_xor_sync(0xffffffffu, s0, off);
        q0 += __shfl_xor_sync(0xffffffffu, q0, off);
        s1 += __shfl_xor_sync(0xffffffffu, s1, off);
        q1 += __shfl_xor_sync(0xffffffffu, q1, off);
    }
    __shared__ float red[4][8];
    const int wid = tid >> 5;
    if ((tid & 31) == 0) {
        red[0][wid] = s0; red[1][wid] = q0; red[2][wid] = s1; red[3][wid] = q1;
    }
    __syncthreads();
    float ts0 = 0.f, tq0 = 0.f, ts1 = 0.f, tq1 = 0.f;
    #pragma unroll
    for (int w = 0; w < 8; w++) {
        ts0 += red[0][w]; tq0 += red[1][w]; ts1 += red[2][w]; tq1 += red[3][w];
    }

    const float mu0 = ts0 * (1.0f / CDIM);
    const float mu1 = ts1 * (1.0f / CDIM);
    const float r0 = rsqrtf(tq0 * (1.0f / CDIM) - mu0 * mu0 + 1e-5f);
    const float r1 = rsqrtf(tq1 * (1.0f / CDIM) - mu1 * mu1 + 1e-5f);

    #pragma unroll
    for (int gi = 0; gi < 2; gi++) {
        const int k = gi ? k1 : k0;
        const float ga = __ldg(&g[k]), gb = __ldg(&g[k + 4]);
        const float ba = __ldg(&b[k]), bb = __ldg(&b[k + 4]);
        const float xa0 = gi ? a02 : a00, xa1 = gi ? a03 : a01;
        const float xb0 = gi ? a12 : a10, xb1 = gi ? a13 : a11;
        *reinterpret_cast<float4*>(&o[paddrA(m0, k, CDIM)]) = make_float4(
            tf32r((xa0 - mu0) * r0 * ga + ba),
            tf32r((xb0 - mu1) * r1 * ga + ba),
            tf32r((xa1 - mu0) * r0 * gb + bb),
            tf32r((xb1 - mu1) * r1 * gb + bb));
    }
}

__device__ __forceinline__ void wprep_body(
    const float* __restrict__ W, float* __restrict__ O,
    int K, int N, int idx)
{
    const int n  = idx % N;
    const int kb = (idx / N) * 8;
    float v[8];
    #pragma unroll
    for (int i = 0; i < 8; i++)
        v[i] = tf32r(__ldg(&W[(size_t)(kb + i) * N + n]));
    float4* p = reinterpret_cast<float4*>(&O[paddrB(n, kb, K)]);
    p[0] = make_float4(v[0], v[4], v[1], v[5]);
    p[1] = make_float4(v[2], v[6], v[3], v[7]);
}

// ---------------------------------------------------------------------------
// prep_kernel: weights pack (blocks 0..6143) + LN1 (blocks 6144..10239)
// ---------------------------------------------------------------------------
__global__ __launch_bounds__(256) void prep_kernel(
    const float* __restrict__ w1, const float* __restrict__ w2,
    const float* __restrict__ w3, const float* __restrict__ w4,
    float* __restrict__ o1, float* __restrict__ o2,
    float* __restrict__ o3, float* __restrict__ o4,
    const float* __restrict__ x, const float* __restrict__ ln1_g,
    const float* __restrict__ ln1_b, float* __restrict__ ln1_o)
{
    const int bid = blockIdx.x;
    const int tid = threadIdx.x;
    if (bid < 1536)
        wprep_body(w1, o1, 1024, 3072, bid * 256 + tid);
    else if (bid < 2048)
        wprep_body(w2, o2, 1024, 1024, (bid - 1536) * 256 + tid);
    else if (bid < 4096)
        wprep_body(w3, o3, 1024, 4096, (bid - 2048) * 256 + tid);
    else if (bid < 6144)
        wprep_body(w4, o4, 4096, 1024, (bid - 4096) * 256 + tid);
    else
        ln_body(x, ln1_g, ln1_b, ln1_o, bid - 6144, tid);
}

// ---------------------------------------------------------------------------
// LayerNorm standalone (for LN2)
// ---------------------------------------------------------------------------
__global__ __launch_bounds__(256) void ln_kernel(
    const float* __restrict__ x, const float* __restrict__ g,
    const float* __restrict__ b, float* __restrict__ o)
{
    ln_body(x, g, b, o, blockIdx.x, threadIdx.x);
}

// ---------------------------------------------------------------------------
// tf32 mma.sync GEMM, fragment-packed operands (unchanged from R10).
// ---------------------------------------------------------------------------
#define GSTG 3
#define STG_FLOATS 8192
#define GEMM_SMEM (GSTG * STG_FLOATS * 4)

__global__ __launch_bounds__(128, 2) void mma_gemm(
    const float* __restrict__ Apk, const float* __restrict__ Bpk,
    const float* __restrict__ bias, const float* __restrict__ resid,
    float* __restrict__ C, int M, int N, int K, int act, int pack_out,
    int round_out)
{
    extern __shared__ float sm[];
    const uint32_t sb = smem_u32(sm);

    const int tid  = threadIdx.x;
    const int wid  = tid >> 5;
    const int lane = tid & 31;
    const int wm = wid & 1;
    const int wn = wid >> 1;
    const int bm = blockIdx.y << 7;
    const int bn = blockIdx.x << 7;
    const int lr = lane >> 2;
    const int lc = lane & 3;

    const int nk = K >> 5;
    const char* abase = (const char*)Apk + (size_t)blockIdx.y * nk * 16384;
    const char* bbase = (const char*)Bpk + (size_t)blockIdx.x * nk * 16384;

    float acc[4][8][4];
    #pragma unroll
    for (int at = 0; at < 4; at++)
        #pragma unroll
        for (int nt = 0; nt < 8; nt++)
            #pragma unroll
            for (int j = 0; j < 4; j++) acc[at][nt][j] = 0.f;

    #define ISSUE(t) do { \
        if ((t) < nk) { \
            const char* _a = abase + (size_t)(t) * 16384 + tid * 16; \
            const char* _b = bbase + (size_t)(t) * 16384 + tid * 16; \
            const uint32_t _d = sb + ((t) % GSTG) * (STG_FLOATS * 4) + tid * 16; \
            _Pragma("unroll") \
            for (int _i = 0; _i < 8; _i++) { \
                CP_ASYNC16(_d + _i * 2048,         _a + _i * 2048); \
                CP_ASYNC16(_d + 16384 + _i * 2048, _b + _i * 2048); \
            } \
        } \
        CP_COMMIT(); \
    } while (0)

    ISSUE(0);
    ISSUE(1);

    for (int t = 0; t < nk; t++) {
        ISSUE(t + 2);
        CP_WAIT2();
        __syncthreads();

        const float* Ab = sm + (t % GSTG) * STG_FLOATS;
        const float* Bb = Ab + 4096;
        #pragma unroll
        for (int kk = 0; kk < 4; kk++) {
            uint4 a[4];
            #pragma unroll
            for (int at = 0; at < 4; at++)
                a[at] = *reinterpret_cast<const uint4*>(
                    Ab + ((kk * 4 + wm * 2 + (at >> 1)) * 2 + (at & 1)) * 128 + lane * 4);
            const float* bq = Bb + (kk * 2 + wn) * 512 + lane * 2;
            #pragma unroll
            for (int nt = 0; nt < 8; nt++) {
                const uint2 bv = *reinterpret_cast<const uint2*>(bq + nt * 64);
                #pragma unroll
                for (int at = 0; at < 4; at++)
                    mma_tf32(acc[at][nt], a[at].x, a[at].y, a[at].z, a[at].w,
                             bv.x, bv.y);
            }
        }
        __syncthreads();
    }

    #pragma unroll
    for (int at = 0; at < 4; at++) {
        const int r0 = bm + wm * 64 + (at >> 1) * 32 + (at & 1) * 16 + lr;
        const int r1 = r0 + 8;
        #pragma unroll
        for (int nt = 0; nt < 8; nt++) {
            const int col = bn + wn * 64 + nt * 8 + lc * 2;
            const float bb0 = __ldg(&bias[col]);
            const float bb1 = __ldg(&bias[col + 1]);
            float v0 = acc[at][nt][0] + bb0;
            float v1 = acc[at][nt][1] + bb1;
            float v2 = acc[at][nt][2] + bb0;
            float v3 = acc[at][nt][3] + bb1;
            if (act) {
                v0 = gelu_f(v0); v1 = gelu_f(v1);
                v2 = gelu_f(v2); v3 = gelu_f(v3);
            }
            if (pack_out) {
                const float u0 = __shfl_xor_sync(0xffffffffu, v0, 2);
                const float u1 = __shfl_xor_sync(0xffffffffu, v1, 2);
                const float u2 = __shfl_xor_sync(0xffffffffu, v2, 2);
                const float u3 = __shfl_xor_sync(0xffffffffu, v3, 2);
                if (lc < 2) {
                    *reinterpret_cast<float4*>(&C[paddrA(r0, col, N)]) =
                        make_float4(tf32r(v0), tf32r(v2), tf32r(u0), tf32r(u2));
                } else {
                    const int colo = col - 3;
                    *reinterpret_cast<float4*>(&C[paddrA(r0, colo, N)]) =
                        make_float4(tf32r(u1), tf32r(u3), tf32r(v1), tf32r(v3));
                }
            } else {
                const size_t o0 = (size_t)r0 * N + col;
                const size_t o1 = (size_t)r1 * N + col;
                if (resid) {
                    const float2 q0 = *reinterpret_cast<const float2*>(&resid[o0]);
                    const float2 q1 = *reinterpret_cast<const float2*>(&resid[o1]);
                    v0 += q0.x; v1 += q0.y; v2 += q1.x; v3 += q1.y;
                }
                if (round_out) {
                    v0 = tf32r(v0); v1 = tf32r(v1); v2 = tf32r(v2); v3 = tf32r(v3);
                }
                *reinterpret_cast<float2*>(&C[o0]) = make_float2(v0, v1);
                *reinterpret_cast<float2*>(&C[o1]) = make_float2(v2, v3);
            }
        }
    }
}

// ---------------------------------------------------------------------------
// Flash attention on mma.sync tf32, causal. CTA q-tile 128 (4 warps x 32 q).
// Heavy-CTA-first scheduling: qt = 15 - blockIdx.x.
// ---------------------------------------------------------------------------
#define AST_K 68
#define AST_V 72
#define ATT_QOFF 0
#define ATT_KOFF(b) (8704 + (b) * 4352)
#define ATT_VOFF(b) (17408 + (b) * 4608)
#define ATT_SMEM (26624 * 4)

__global__ __launch_bounds__(128, 2) void attn_mma(
    const float* __restrict__ qkv, float* __restrict__ out)
{
    extern __shared__ float sm[];
    const uint32_t sb = smem_u32(sm);
    const int tid = threadIdx.x;
    const int w = tid >> 5, lane = tid & 31;
    const int lr = lane >> 2, lc = lane & 3;
    const int qt = (int)gridDim.x - 1 - (int)blockIdx.x;   // heavy CTAs first
    const int bh = blockIdx.y;
    const int b = bh >> 4, h = bh & 15;
    const int q0 = qt * 128;
    const float* basep = qkv + (size_t)b * 2048 * 3072 + (size_t)h * 64;

    #pragma unroll
    for (int i = 0; i < 16; i++) {
        const int idx = tid + i * 128, row = idx >> 4, ch = idx & 15;
        CP_ASYNC16(sb + (uint32_t)(ATT_QOFF + row * AST_K + ch * 4) * 4,
                   basep + (size_t)(q0 + row) * 3072 + ch * 4);
    }
    CP_COMMIT();

    #define ISSUE_KV(kt_, bb) do { \
        const float* _k = basep + (size_t)((kt_) * 64) * 3072 + 1024; \
        _Pragma("unroll") \
        for (int _i = 0; _i < 8; _i++) { \
            const int _idx = tid + _i * 128, _r = _idx >> 4, _c = _idx & 15; \
            CP_ASYNC16(sb + (uint32_t)(ATT_KOFF(bb) + _r * AST_K + _c * 4) * 4, \
                       _k + (size_t)_r * 3072 + _c * 4); \
            CP_ASYNC16(sb + (uint32_t)(ATT_VOFF(bb) + _r * AST_V + _c * 4) * 4, \
                       _k + 1024 + (size_t)_r * 3072 + _c * 4); \
        } \
        CP_COMMIT(); \
    } while (0)

    ISSUE_KV(0, 0);

    CP_WAIT1();
    __syncthreads();

    float qa[2][8][4];
    {
        const float* Qs = sm + ATT_QOFF;
        #pragma unroll
        for (int mt2 = 0; mt2 < 2; mt2++) {
            const int r0 = w * 32 + mt2 * 16 + lr;
            #pragma unroll
            for (int kk = 0; kk < 8; kk++) {
                qa[mt2][kk][0] = 0.125f * Qs[r0 * AST_K + kk * 8 + lc];
                qa[mt2][kk][1] = 0.125f * Qs[(r0 + 8) * AST_K + kk * 8 + lc];
                qa[mt2][kk][2] = 0.125f * Qs[r0 * AST_K + kk * 8 + lc + 4];
                qa[mt2][kk][3] = 0.125f * Qs[(r0 + 8) * AST_K + kk * 8 + lc + 4];
            }
        }
    }
    __syncthreads();

    float* Pw = sm + ATT_QOFF + w * 2048;

    float m[2][2], l[2][2];
    #pragma unroll
    for (int i = 0; i < 2; i++)
        #pragma unroll
        for (int j2 = 0; j2 < 2; j2++) { m[i][j2] = -1e30f; l[i][j2] = 0.f; }

    float o[4][4][4];
    #pragma unroll
    for (int mt = 0; mt < 4; mt++)
        #pragma unroll
        for (int qn = 0; qn < 4; qn++)
            #pragma unroll
            for (int j = 0; j < 4; j++) o[mt][qn][j] = 0.f;

    const int ktmax = 2 * qt + 1;
    for (int kt = 0; kt <= ktmax; kt++) {
        const int buf = kt & 1;
        if (kt < ktmax) { ISSUE_KV(kt + 1, buf ^ 1); CP_WAIT1(); }
        else            { CP_WAIT0(); }
        __syncthreads();

        if (64 * kt <= q0 + w * 32 + 31) {
            const float* Ks = sm + ATT_KOFF(buf);
            const float* Vs = sm + ATT_VOFF(buf);

            float s[2][8][4];
            #pragma unroll
            for (int mt2 = 0; mt2 < 2; mt2++)
                #pragma unroll
                for (int nt = 0; nt < 8; nt++)
                    #pragma unroll
                    for (int j = 0; j < 4; j++) s[mt2][nt][j] = 0.f;

            #pragma unroll
            for (int kk = 0; kk < 8; kk++) {
                #pragma unroll
                for (int nt = 0; nt < 8; nt++) {
                    const uint32_t b0 = __float_as_uint(Ks[(nt * 8 + lr) * AST_K + kk * 8 + lc]);
                    const uint32_t b1 = __float_as_uint(Ks[(nt * 8 + lr) * AST_K + kk * 8 + lc + 4]);
                    mma_tf32(s[0][nt],
                             __float_as_uint(qa[0][kk][0]), __float_as_uint(qa[0][kk][1]),
                             __float_as_uint(qa[0][kk][2]), __float_as_uint(qa[0][kk][3]),
                             b0, b1);
                    mma_tf32(s[1][nt],
                             __float_as_uint(qa[1][kk][0]), __float_as_uint(qa[1][kk][1]),
                             __float_as_uint(qa[1][kk][2]), __float_as_uint(qa[1][kk][3]),
                             b0, b1);
                }
            }

            #pragma unroll
            for (int mt2 = 0; mt2 < 2; mt2++) {
                const int rbase = q0 + w * 32 + mt2 * 16;
                if (64 * kt + 63 > rbase) {
                    #pragma unroll
                    for (int nt = 0; nt < 8; nt++) {
                        const int c = 64 * kt + nt * 8 + 2 * lc;
                        if (c     > rbase + lr)     s[mt2][nt][0] = -1e30f;
                        if (c + 1 > rbase + lr)     s[mt2][nt][1] = -1e30f;
                        if (c     > rbase + lr + 8) s[mt2][nt][2] = -1e30f;
                        if (c + 1 > rbase + lr + 8) s[mt2][nt][3] = -1e30f;
                    }
                }
            }

            float al[2][2];
            #pragma unroll
            for (int mt2 = 0; mt2 < 2; mt2++) {
                float mx0 = -1e30f, mx1 = -1e30f;
                #pragma unroll
                for (int nt = 0; nt < 8; nt++) {
                    mx0 = fmaxf(mx0, fmaxf(s[mt2][nt][0], s[mt2][nt][1]));
                    mx1 = fmaxf(mx1, fmaxf(s[mt2][nt][2], s[mt2][nt][3]));
                }
                mx0 = fmaxf(mx0, __shfl_xor_sync(0xffffffffu, mx0, 1));
                mx0 = fmaxf(mx0, __shfl_xor_sync(0xffffffffu, mx0, 2));
                mx1 = fmaxf(mx1, __shfl_xor_sync(0xffffffffu, mx1, 1));
                mx1 = fmaxf(mx1, __shfl_xor_sync(0xffffffffu, mx1, 2));

                const float mn0 = fmaxf(m[mt2][0], mx0);
                const float mn1 = fmaxf(m[mt2][1], mx1);
                al[mt2][0] = __expf(m[mt2][0] - mn0);
                al[mt2][1] = __expf(m[mt2][1] - mn1);
                m[mt2][0] = mn0; m[mt2][1] = mn1;

                float sum0 = 0.f, sum1 = 0.f;
                #pragma unroll
                for (int nt = 0; nt < 8; nt++) {
                    s[mt2][nt][0] = __expf(s[mt2][nt][0] - mn0); sum0 += s[mt2][nt][0];
                    s[mt2][nt][1] = __expf(s[mt2][nt][1] - mn0); sum0 += s[mt2][nt][1];
                    s[mt2][nt][2] = __expf(s[mt2][nt][2] - mn1); sum1 += s[mt2][nt][2];
                    s[mt2][nt][3] = __expf(s[mt2][nt][3] - mn1); sum1 += s[mt2][nt][3];
                }
                sum0 += __shfl_xor_sync(0xffffffffu, sum0, 1);
                sum0 += __shfl_xor_sync(0xffffffffu, sum0, 2);
                sum1 += __shfl_xor_sync(0xffffffffu, sum1, 1);
                sum1 += __shfl_xor_sync(0xffffffffu, sum1, 2);
                l[mt2][0] = l[mt2][0] * al[mt2][0] + sum0;
                l[mt2][1] = l[mt2][1] * al[mt2][1] + sum1;
            }

            #pragma unroll
            for (int qn = 0; qn < 4; qn++) {
                const float zA  = __shfl_sync(0xffffffffu, al[qn >> 1][qn & 1], 8 * lc);
                const float zAb = __shfl_sync(0xffffffffu, al[qn >> 1][qn & 1], 8 * lc + 4);
                #pragma unroll
                for (int mt = 0; mt < 4; mt++) {
                    o[mt][qn][0] *= zA;  o[mt][qn][1] *= zAb;
                    o[mt][qn][2] *= zA;  o[mt][qn][3] *= zAb;
                }
            }

            __syncwarp();
            {
                const int c0c = 2 * lc, c1c = 2 * lc + 1;
                const int ln0 = lr * 4 + (c0c & 3), rg0 = (c0c & 4) >> 2;
                const int ln1 = lr * 4 + (c1c & 3), rg1 = (c1c & 4) >> 2;
                #pragma unroll
                for (int mt2 = 0; mt2 < 2; mt2++) {
                    #pragma unroll
                    for (int nt = 0; nt < 8; nt++) {
                        const int q0n = mt2 * 2;
                        Pw[(nt * 4 + q0n + 0) * 64 + ln0 * 2 + rg0] = tf32r(s[mt2][nt][0]);
                        Pw[(nt * 4 + q0n + 0) * 64 + ln1 * 2 + rg1] = tf32r(s[mt2][nt][1]);
                        Pw[(nt * 4 + q0n + 1) * 64 + ln0 * 2 + rg0] = tf32r(s[mt2][nt][2]);
                        Pw[(nt * 4 + q0n + 1) * 64 + ln1 * 2 + rg1] = tf32r(s[mt2][nt][3]);
                    }
                }
            }
            __syncwarp();

            #pragma unroll
            for (int kk2 = 0; kk2 < 8; kk2++) {
                uint2 bp[4];
                #pragma unroll
                for (int qn = 0; qn < 4; qn++)
                    bp[qn] = *reinterpret_cast<const uint2*>(
                        Pw + (kk2 * 4 + qn) * 64 + lane * 2);
                #pragma unroll
                for (int mt = 0; mt < 4; mt++) {
                    const uint32_t a0 = __float_as_uint(Vs[(kk2 * 8 + lc) * AST_V + mt * 16 + lr]);
                    const uint32_t a1 = __float_as_uint(Vs[(kk2 * 8 + lc) * AST_V + mt * 16 + lr + 8]);
                    const uint32_t a2 = __float_as_uint(Vs[(kk2 * 8 + lc + 4) * AST_V + mt * 16 + lr]);
                    const uint32_t a3 = __float_as_uint(Vs[(kk2 * 8 + lc + 4) * AST_V + mt * 16 + lr + 8]);
                    #pragma unroll
                    for (int qn = 0; qn < 4; qn++)
                        mma_tf32(o[mt][qn], a0, a1, a2, a3, bp[qn].x, bp[qn].y);
                }
            }
        }

        __syncthreads();
    }

    float zI[4], zIb[4];
    #pragma unroll
    for (int qn = 0; qn < 4; qn++) {
        const float inv = 1.0f / l[qn >> 1][qn & 1];
        zI[qn]  = __shfl_sync(0xffffffffu, inv, 8 * lc);
        zIb[qn] = __shfl_sync(0xffffffffu, inv, 8 * lc + 4);
    }

    #pragma unroll
    for (int mt = 0; mt < 4; mt++) {
        #pragma unroll
        for (int p = 0; p < 2; p++) {
            float f[2][4];
            #pragma unroll
            for (int h2 = 0; h2 < 2; h2++) {
                const int qn = 2 * p + h2;
                f[h2][0] = o[mt][qn][0] * zI[qn];
                f[h2][1] = o[mt][qn][1] * zIb[qn];
                f[h2][2] = o[mt][qn][2] * zI[qn];
                f[h2][3] = o[mt][qn][3] * zIb[qn];
            }
            float e[2][4];
            #pragma unroll
            for (int h2 = 0; h2 < 2; h2++)
                #pragma unroll
                for (int j = 0; j < 4; j++)
                    e[h2][j] = __shfl_xor_sync(0xffffffffu, f[h2][j], 16);

            const int qr0 = b * 2048 + q0 + w * 32 + p * 16 + 2 * lc;
            if (lr < 4) {
                const int k0 = h * 64 + mt * 16 + lr;
                *reinterpret_cast<float4*>(&out[paddrA(qr0, k0, CDIM)]) =
                    make_float4(tf32r(f[0][0]), tf32r(f[1][0]), tf32r(e[0][0]), tf32r(e[1][0]));
                *reinterpret_cast<float4*>(&out[paddrA(qr0 + 1, k0, CDIM)]) =
                    make_float4(tf32r(f[0][1]), tf32r(f[1][1]), tf32r(e[0][1]), tf32r(e[1][1]));
            } else {
                const int kb = h * 64 + mt * 16 + lr + 4;
                *reinterpret_cast<float4*>(&out[paddrA(qr0, kb, CDIM)]) =
                    make_float4(tf32r(e[0][2]), tf32r(e[1][2]), tf32r(f[0][2]), tf32r(f[1][2]));
                *reinterpret_cast<float4*>(&out[paddrA(qr0 + 1, kb, CDIM)]) =
                    make_float4(tf32r(e[0][3]), tf32r(e[1][3]), tf32r(f[0][3]), tf32r(f[1][3]));
            }
        }
    }
}

// ---------------------------------------------------------------------------
// Launch
// ---------------------------------------------------------------------------
extern "C" void kernel_launch(void* const* d_in, const int* in_sizes, int n_in,
                              void* d_out, int out_size)
{
    const float* x        = (const float*)d_in[0];
    const float* c_attn_w = (const float*)d_in[1];
    const float* c_attn_b = (const float*)d_in[2];
    const float* c_proj_w = (const float*)d_in[3];
    const float* c_proj_b = (const float*)d_in[4];
    const float* fc_w     = (const float*)d_in[5];
    const float* fc_b     = (const float*)d_in[6];
    const float* proj_w   = (const float*)d_in[7];
    const float* proj_b   = (const float*)d_in[8];
    const float* ln1_g    = (const float*)d_in[9];
    const float* ln1_b    = (const float*)d_in[10];
    const float* ln2_g    = (const float*)d_in[11];
    const float* ln2_b    = (const float*)d_in[12];

    float *ln1, *qkv, *attn, *x1, *ln2, *hbuf, *w1p, *w2p, *w3p, *w4p;
    cudaGetSymbolAddress((void**)&ln1,  g_ln1);
    cudaGetSymbolAddress((void**)&qkv,  g_qkv);
    cudaGetSymbolAddress((void**)&attn, g_attn);
    cudaGetSymbolAddress((void**)&x1,   g_x1);
    cudaGetSymbolAddress((void**)&ln2,  g_ln2);
    cudaGetSymbolAddress((void**)&hbuf, g_hbuf);
    cudaGetSymbolAddress((void**)&w1p,  g_w1p);
    cudaGetSymbolAddress((void**)&w2p,  g_w2p);
    cudaGetSymbolAddress((void**)&w3p,  g_w3p);
    cudaGetSymbolAddress((void**)&w4p,  g_w4p);

    cudaFuncSetAttribute(mma_gemm, cudaFuncAttributeMaxDynamicSharedMemorySize, GEMM_SMEM);
    cudaFuncSetAttribute(attn_mma, cudaFuncAttributeMaxDynamicSharedMemorySize, ATT_SMEM);

    float* outp = (float*)d_out;

    // 0. prep: weight packing + LN1 in one launch (independent, overlap)
    prep_kernel<<<10240, 256>>>(c_attn_w, c_proj_w, fc_w, proj_w,
                                w1p, w2p, w3p, w4p,
                                x, ln1_g, ln1_b, ln1);

    // 2. qkv = ln1 @ c_attn_w + b  (natural, tf32-rounded for attention)
    mma_gemm<<<dim3(24, 64), 128, GEMM_SMEM>>>(
        ln1, w1p, c_attn_b, nullptr, qkv, MROWS, 3072, 1024, 0, 0, 1);
    // 3. attention (q-tile 128, heavy CTAs first) -> packed A
    attn_mma<<<dim3(16, 64), 128, ATT_SMEM>>>(qkv, attn);
    // 4. x1 = attn @ c_proj_w + b + x
    mma_gemm<<<dim3(8, 64), 128, GEMM_SMEM>>>(
        attn, w2p, c_proj_b, x, x1, MROWS, 1024, 1024, 0, 0, 0);
    // 5. ln2 = LN(x1) (packed A)
    ln_kernel<<<4096, 256>>>(x1, ln2_g, ln2_b, ln2);
    // 6. h = gelu(ln2 @ fc_w + b) (packed out)
    mma_gemm<<<dim3(32, 64), 128, GEMM_SMEM>>>(
        ln2, w3p, fc_b, nullptr, hbuf, MROWS, 4096, 1024, 1, 1, 0);
    // 7. out = h @ proj_w + b + x1
    mma_gemm<<<dim3(8, 64), 128, GEMM_SMEM>>>(
        hbuf, w4p, proj_b, x1, outp, MROWS, 1024, 4096, 0, 0, 0);
}